// round 11
// baseline (speedup 1.0000x reference)
#include <cuda_runtime.h>
#include <cuda_bf16.h>
#include <math.h>
#include <stdint.h>

// ---------------- problem constants ----------------
#define T_LEN 1024
#define NSLOT 8
#define DS 1024
#define DR 512
#define HEADS 8
#define DHS 128
#define DHR 64
#define TOPK 4
#define ROWS_R (T_LEN * NSLOT)   // 8192
#define SCALE_S 0.08838834764831845f  // 1/sqrt(128)
#define SCALE_R 0.125f                // 1/sqrt(64)
#define EPS 1e-6f

// fused layouts
#define N_SN 2048        // q(1024) | kr(512) | vr(512), K=1024
#define N_RN 2560        // k(1024) | v(1024) | qr(512), K=512

// ---------------- scratch (static device memory; no allocation) -------------
__device__ __nv_bfloat16 g_sn_h[T_LEN * DS], g_sn_l[T_LEN * DS];
__device__ __nv_bfloat16 g_rn_h[ROWS_R * DR], g_rn_l[ROWS_R * DR];
__device__ __nv_bfloat16 g_as_h[T_LEN * DS], g_as_l[T_LEN * DS];
__device__ __nv_bfloat16 g_ar_h[ROWS_R * DR], g_ar_l[ROWS_R * DR];
__device__ __nv_bfloat16 g_wsn_h[N_SN * DS], g_wsn_l[N_SN * DS];
__device__ __nv_bfloat16 g_wrn_h[N_RN * DR], g_wrn_l[N_RN * DR];
__device__ __nv_bfloat16 g_wso_h[DS * DS], g_wso_l[DS * DS];
__device__ __nv_bfloat16 g_wro_h[DR * DR], g_wro_l[DR * DR];
__device__ float g_csn[T_LEN * N_SN];     // q | kr | vr
__device__ float g_crn[ROWS_R * N_RN];    // k | v | qr
__device__ float g_rsp[T_LEN * DS];
__device__ uint32_t g_kh[T_LEN * 256], g_kl[T_LEN * 256];
__device__ uint32_t g_vth[HEADS * DHR * (T_LEN / 2)];
__device__ uint32_t g_vtl[HEADS * DHR * (T_LEN / 2)];

// ---------------- PTX helpers ----------------
__device__ __forceinline__ uint32_t smem_u32(const void* p) {
    uint32_t a;
    asm("{ .reg .u64 t; cvta.to.shared.u64 t, %1; cvt.u32.u64 %0, t; }"
        : "=r"(a) : "l"(p));
    return a;
}
__device__ __forceinline__ void cp16(uint32_t dst, const void* src) {
    asm volatile("cp.async.cg.shared.global [%0], [%1], 16;"
                 :: "r"(dst), "l"(src) : "memory");
}
__device__ __forceinline__ void ldm_x4(uint32_t* r, uint32_t addr) {
    asm volatile("ldmatrix.sync.aligned.m8n8.x4.shared.b16 {%0,%1,%2,%3}, [%4];"
                 : "=r"(r[0]), "=r"(r[1]), "=r"(r[2]), "=r"(r[3]) : "r"(addr));
}
__device__ __forceinline__ void mma_bf16(
    float* c, const uint32_t* a, uint32_t b0, uint32_t b1)
{
    asm volatile(
        "mma.sync.aligned.m16n8k16.row.col.f32.bf16.bf16.f32 "
        "{%0,%1,%2,%3}, {%4,%5,%6,%7}, {%8,%9}, {%0,%1,%2,%3};"
        : "+f"(c[0]), "+f"(c[1]), "+f"(c[2]), "+f"(c[3])
        : "r"(a[0]), "r"(a[1]), "r"(a[2]), "r"(a[3]), "r"(b0), "r"(b1));
}
__device__ __forceinline__ void split2(float x, float y,
                                       uint32_t& hi, uint32_t& lo)
{
    __nv_bfloat162 h = __floats2bfloat162_rn(x, y);
    float xr = x - __bfloat162float(h.x);
    float yr = y - __bfloat162float(h.y);
    __nv_bfloat162 l = __floats2bfloat162_rn(xr, yr);
    hi = *(uint32_t*)&h;
    lo = *(uint32_t*)&l;
}

// ---------------- merged prep: 8 weight transposes + 2 rmsnorms -------------
__global__ __launch_bounds__(256) void prep_kernel(
    const float* __restrict__ Wsq, const float* __restrict__ Wsk,
    const float* __restrict__ Wsv, const float* __restrict__ Wso,
    const float* __restrict__ Wrq, const float* __restrict__ Wrk,
    const float* __restrict__ Wrv, const float* __restrict__ Wro,
    __nv_bfloat16* __restrict__ wsnh, __nv_bfloat16* __restrict__ wsnl,
    __nv_bfloat16* __restrict__ wrnh, __nv_bfloat16* __restrict__ wrnl,
    __nv_bfloat16* __restrict__ wsoh, __nv_bfloat16* __restrict__ wsol,
    __nv_bfloat16* __restrict__ wroh, __nv_bfloat16* __restrict__ wrol,
    const float* __restrict__ s, const float* __restrict__ nsw,
    __nv_bfloat16* __restrict__ snh, __nv_bfloat16* __restrict__ snl,
    const float* __restrict__ r, const float* __restrict__ nrw,
    __nv_bfloat16* __restrict__ rnh, __nv_bfloat16* __restrict__ rnl)
{
    int b = blockIdx.x;
    if (b < 4608) {
        const float* W;
        __nv_bfloat16 *th, *tl;
        int K, N;
        if (b < 1024)      { W = Wsq; th = wsnh; tl = wsnl; K = 1024; N = 1024; }
        else if (b < 1536) { b -= 1024; W = Wrk; th = wsnh + 1024 * 1024;
                             tl = wsnl + 1024 * 1024; K = 1024; N = 512; }
        else if (b < 2048) { b -= 1536; W = Wrv; th = wsnh + 1536 * 1024;
                             tl = wsnl + 1536 * 1024; K = 1024; N = 512; }
        else if (b < 2560) { b -= 2048; W = Wsk; th = wrnh; tl = wrnl;
                             K = 512; N = 1024; }
        else if (b < 3072) { b -= 2560; W = Wsv; th = wrnh + 1024 * 512;
                             tl = wrnl + 1024 * 512; K = 512; N = 1024; }
        else if (b < 3328) { b -= 3072; W = Wrq; th = wrnh + 2048 * 512;
                             tl = wrnl + 2048 * 512; K = 512; N = 512; }
        else if (b < 4352) { b -= 3328; W = Wso; th = wsoh; tl = wsol;
                             K = 1024; N = 1024; }
        else               { b -= 4352; W = Wro; th = wroh; tl = wrol;
                             K = 512; N = 512; }

        int ntx = N >> 5;
        int bx = (b % ntx) * 32;
        int by = (b / ntx) * 32;

        __shared__ float t[32][33];
        int tx = threadIdx.x & 31, ty = threadIdx.x >> 5;
        #pragma unroll
        for (int i = 0; i < 4; i++)
            t[ty + i * 8][tx] = W[(size_t)(by + ty + i * 8) * N + bx + tx];
        __syncthreads();
        #pragma unroll
        for (int i = 0; i < 4; i++) {
            int n = bx + ty + i * 8;
            int k = by + tx;
            float v = t[tx][ty + i * 8];
            __nv_bfloat16 h = __float2bfloat16(v);
            th[(size_t)n * K + k] = h;
            tl[(size_t)n * K + k] = __float2bfloat16(v - __bfloat162float(h));
        }
        return;
    }
    const float *x, *w;
    __nv_bfloat16 *oh, *ol;
    int C, row;
    if (b < 4608 + T_LEN) {
        row = b - 4608; x = s; w = nsw; oh = snh; ol = snl; C = DS;
    } else {
        row = b - 4608 - T_LEN; x = r; w = nrw; oh = rnh; ol = rnl; C = DR;
    }
    const float* xr = x + (size_t)row * C;
    float acc = 0.f;
    for (int j = threadIdx.x; j < C; j += 256) {
        float v = xr[j];
        acc += v * v;
    }
    __shared__ float red[8];
    int lane = threadIdx.x & 31, warp = threadIdx.x >> 5;
    #pragma unroll
    for (int off = 16; off; off >>= 1) acc += __shfl_xor_sync(0xffffffffu, acc, off);
    if (lane == 0) red[warp] = acc;
    __syncthreads();
    __shared__ float scale;
    if (threadIdx.x == 0) {
        float tot = 0.f;
        #pragma unroll
        for (int i = 0; i < 8; i++) tot += red[i];
        scale = rsqrtf(tot / (float)C + EPS);
    }
    __syncthreads();
    float sc = scale;
    uint32_t* ph = (uint32_t*)(oh + (size_t)row * C);
    uint32_t* pl = (uint32_t*)(ol + (size_t)row * C);
    for (int j2 = threadIdx.x; j2 < C / 2; j2 += 256) {
        float v0 = xr[2 * j2] * sc * w[2 * j2];
        float v1 = xr[2 * j2 + 1] * sc * w[2 * j2 + 1];
        uint32_t h, l;
        split2(v0, v1, h, l);
        ph[j2] = h;
        pl[j2] = l;
    }
}

// ---------------- bf16-split mma GEMM body (64x128 tile) --------------------
struct GArg {
    const __nv_bfloat16 *Ah, *Al, *Bh, *Bl;
    float* C;
    int M, N, K, ldc;
    const float *add1, *add2, *rowscale;
};

__device__ __forceinline__ void gemm_body(
    const GArg g, int bx, int by,
    uint32_t bAh, uint32_t bAl, uint32_t bBh, uint32_t bBl)
{
    int tid = threadIdx.x;
    int lane = tid & 31, wid = tid >> 5;
    int wm = wid & 1, wn = wid >> 1;
    int bm = by * 64, bn = bx * 128;
    int gid = lane >> 2, tig = lane & 3;
    int K = g.K;

    float acc[2][4][4];
    #pragma unroll
    for (int i = 0; i < 2; i++)
        #pragma unroll
        for (int j = 0; j < 4; j++)
            #pragma unroll
            for (int l = 0; l < 4; l++) acc[i][j][l] = 0.f;

    uint32_t aoff0, aoff1, boff0, boff1;
    {
        int lrow = lane & 7;
        int rA = wm * 32 + lrow + (lane & 8);
        int cA = (lane & 16) >> 2;
        aoff0 = (uint32_t)(rA * 8 + cA) * 4;
        aoff1 = (uint32_t)((rA + 16) * 8 + cA) * 4;
        int rB = wn * 32 + lrow + ((lane & 16) >> 1);
        int cB = (lane & 8) >> 1;
        boff0 = (uint32_t)(rB * 8 + cB) * 4;
        boff1 = (uint32_t)((rB + 16) * 8 + cB) * 4;
    }

    int row = tid >> 1;
    int gg = tid & 1;
    const __nv_bfloat16 *Ah = g.Ah, *Al = g.Al, *Bh = g.Bh, *Bl = g.Bl;
    auto issue = [&](int st, int k0) {
        uint32_t bdoff = (uint32_t)(st * 128 * 8 + row * 8 + gg * 4) * 4;
        size_t bsrc = (size_t)(bn + row) * K + k0 + gg * 8;
        cp16(bBh + bdoff, Bh + bsrc);
        cp16(bBl + bdoff, Bl + bsrc);
        if (tid < 128) {
            uint32_t adoff = (uint32_t)(st * 64 * 8 + row * 8 + gg * 4) * 4;
            size_t asrc = (size_t)(bm + row) * K + k0 + gg * 8;
            cp16(bAh + adoff, Ah + asrc);
            cp16(bAl + adoff, Al + asrc);
        }
        asm volatile("cp.async.commit_group;" ::: "memory");
    };

    int nch = K >> 4;
    issue(0, 0);
    if (nch > 1) issue(1, 16);

    for (int c = 0; c < nch; c++) {
        if (c + 1 < nch) {
            asm volatile("cp.async.wait_group 1;" ::: "memory");
        } else {
            asm volatile("cp.async.wait_group 0;" ::: "memory");
        }
        __syncthreads();
        if (c + 2 < nch) issue((c + 2) % 3, (c + 2) * 16);

        uint32_t aoffst = (uint32_t)((c % 3) * 64 * 8 * 4);
        uint32_t boffst = (uint32_t)((c % 3) * 128 * 8 * 4);

        uint32_t ah[2][4], al[2][4];
        ldm_x4(ah[0], bAh + aoffst + aoff0);
        ldm_x4(ah[1], bAh + aoffst + aoff1);
        ldm_x4(al[0], bAl + aoffst + aoff0);
        ldm_x4(al[1], bAl + aoffst + aoff1);

        #pragma unroll
        for (int p = 0; p < 2; p++) {
            uint32_t bh[4], bl[4];
            ldm_x4(bh, bBh + boffst + (p ? boff1 : boff0));
            ldm_x4(bl, bBl + boffst + (p ? boff1 : boff0));
            #pragma unroll
            for (int q = 0; q < 2; q++) {
                int nt = p * 2 + q;
                uint32_t b0h = bh[2 * q], b1h = bh[2 * q + 1];
                uint32_t b0l = bl[2 * q], b1l = bl[2 * q + 1];
                mma_bf16(acc[0][nt], ah[0], b0h, b1h);
                mma_bf16(acc[0][nt], ah[0], b0l, b1l);
                mma_bf16(acc[0][nt], al[0], b0h, b1h);
                mma_bf16(acc[1][nt], ah[1], b0h, b1h);
                mma_bf16(acc[1][nt], ah[1], b0l, b1l);
                mma_bf16(acc[1][nt], al[1], b0h, b1h);
            }
        }
    }

    #pragma unroll
    for (int mt = 0; mt < 2; mt++) {
        int r0 = bm + wm * 32 + mt * 16 + gid;
        float rs0 = (g.rowscale != nullptr) ? g.rowscale[r0] : 0.f;
        float rs8 = (g.rowscale != nullptr) ? g.rowscale[r0 + 8] : 0.f;
        #pragma unroll
        for (int nt = 0; nt < 4; nt++) {
            int col = bn + wn * 32 + nt * 8 + 2 * tig;
            size_t o0 = (size_t)r0 * g.ldc + col;
            size_t o8 = (size_t)(r0 + 8) * g.ldc + col;
            float2 v0 = make_float2(acc[mt][nt][0], acc[mt][nt][1]);
            float2 v8 = make_float2(acc[mt][nt][2], acc[mt][nt][3]);
            if (g.add1) {
                float2 x = *(const float2*)(g.add1 + o0);
                v0.x += x.x; v0.y += x.y;
                x = *(const float2*)(g.add1 + o8);
                v8.x += x.x; v8.y += x.y;
            }
            if (g.add2) {
                float2 x = *(const float2*)(g.add2 + o0);
                v0.x += rs0 * x.x; v0.y += rs0 * x.y;
                x = *(const float2*)(g.add2 + o8);
                v8.x += rs8 * x.x; v8.y += rs8 * x.y;
            }
            *(float2*)(g.C + o0) = v0;
            *(float2*)(g.C + o8) = v8;
        }
    }
}

__global__ __launch_bounds__(256, 3) void gemm_pair(
    GArg g0, GArg g1, int nblk0, int gx0, int gx1)
{
    __shared__ __align__(16) uint32_t sAh[3][64 * 8], sAl[3][64 * 8];
    __shared__ __align__(16) uint32_t sBh[3][128 * 8], sBl[3][128 * 8];
    uint32_t bAh = smem_u32(sAh), bAl = smem_u32(sAl);
    uint32_t bBh = smem_u32(sBh), bBl = smem_u32(sBl);

    int b = blockIdx.x;
    if (b < nblk0)
        gemm_body(g0, b % gx0, b / gx0, bAh, bAl, bBh, bBl);
    else {
        b -= nblk0;
        gemm_body(g1, b % gx1, b / gx1, bAh, bAl, bBh, bBl);
    }
}

// ---------------- merged conv_kv + s-attention ----------------
__global__ __launch_bounds__(256) void conv_sattn_kernel(
    const float* __restrict__ csn,
    const float* __restrict__ crn,
    uint32_t* __restrict__ kh, uint32_t* __restrict__ kl,
    uint32_t* __restrict__ vh, uint32_t* __restrict__ vl,
    __nv_bfloat16* __restrict__ as_h, __nv_bfloat16* __restrict__ as_l,
    float* __restrict__ rsp)
{
    int b = blockIdx.x;
    if (b < T_LEN) {
        int t = b, j = threadIdx.x;
        float2 v = *(const float2*)(csn + (size_t)t * N_SN + 1024 + 2 * j);
        uint32_t h, l;
        split2(v.x, v.y, h, l);
        kh[(size_t)t * 256 + j] = h;
        kl[(size_t)t * 256 + j] = l;
        return;
    }
    if (b < T_LEN + 1024) {
        int idx = (b - T_LEN) * 256 + threadIdx.x;
        int pp = idx & 511;
        int d = (idx >> 9) & 63;
        int h = idx >> 15;
        float v0 = csn[(size_t)(2 * pp) * N_SN + 1536 + h * DHR + d];
        float v1 = csn[(size_t)(2 * pp + 1) * N_SN + 1536 + h * DHR + d];
        uint32_t hh, ll;
        split2(v0, v1, hh, ll);
        vh[idx] = hh;
        vl[idx] = ll;
        return;
    }
    int t = b - T_LEN - 1024;
    int tid = threadIdx.x;
    int warp = tid >> 5, lane = tid & 31;

    __shared__ float qs[DS];
    __shared__ float logits[HEADS][NSLOT];
    __shared__ float wattn[HEADS][NSLOT];
    __shared__ float wsp[NSLOT];

    for (int j = tid; j < DS; j += 256) qs[j] = csn[(size_t)t * N_SN + j];
    __syncthreads();

    {
        int h = warp;
        #pragma unroll
        for (int n = 0; n < NSLOT; n++) {
            const float* krow = crn + (size_t)(t * NSLOT + n) * N_RN + h * DHS;
            const float* qrow = qs + h * DHS;
            float p = 0.f;
            #pragma unroll
            for (int d = lane; d < DHS; d += 32) p += qrow[d] * krow[d];
            #pragma unroll
            for (int off = 16; off; off >>= 1) p += __shfl_xor_sync(0xffffffffu, p, off);
            if (lane == 0) logits[h][n] = p;
        }
    }
    __syncthreads();

    if (tid < HEADS) {
        int h = tid;
        float m = -INFINITY;
        #pragma unroll
        for (int n = 0; n < NSLOT; n++) m = fmaxf(m, logits[h][n] * SCALE_S);
        float sum = 0.f;
        #pragma unroll
        for (int n = 0; n < NSLOT; n++) {
            float e = __expf(logits[h][n] * SCALE_S - m);
            wattn[h][n] = e;
            sum += e;
        }
        float inv = 1.f / sum;
        #pragma unroll
        for (int n = 0; n < NSLOT; n++) wattn[h][n] *= inv;
    }
    if (tid == 8) {
        float sp[NSLOT];
        #pragma unroll
        for (int n = 0; n < NSLOT; n++) {
            float a = 0.f;
            #pragma unroll
            for (int h = 0; h < HEADS; h++) a += logits[h][n];
            sp[n] = a * SCALE_S;
        }
        bool sel[NSLOT];
        #pragma unroll
        for (int n = 0; n < NSLOT; n++) { sel[n] = false; wsp[n] = 0.f; }
        int idxs[TOPK];
        #pragma unroll
        for (int kk = 0; kk < TOPK; kk++) {
            int best = -1; float bv = -INFINITY;
            #pragma unroll
            for (int n = 0; n < NSLOT; n++)
                if (!sel[n] && sp[n] > bv) { bv = sp[n]; best = n; }
            sel[best] = true; idxs[kk] = best;
        }
        float m = -INFINITY;
        #pragma unroll
        for (int kk = 0; kk < TOPK; kk++) m = fmaxf(m, sp[idxs[kk]]);
        float sum = 0.f, e[TOPK];
        #pragma unroll
        for (int kk = 0; kk < TOPK; kk++) { e[kk] = __expf(sp[idxs[kk]] - m); sum += e[kk]; }
        float inv = 1.f / sum;
        #pragma unroll
        for (int kk = 0; kk < TOPK; kk++) wsp[idxs[kk]] = e[kk] * inv;
    }
    __syncthreads();

    uint32_t* ph = (uint32_t*)(as_h + (size_t)t * DS);
    uint32_t* pl = (uint32_t*)(as_l + (size_t)t * DS);
    for (int j2 = tid; j2 < DS / 2; j2 += 256) {
        int j = 2 * j2;
        int h = j >> 7;
        float a0 = 0.f, a1 = 0.f, b0 = 0.f, b1 = 0.f;
        #pragma unroll
        for (int n = 0; n < NSLOT; n++) {
            float2 vv = *(const float2*)(crn + (size_t)(t * NSLOT + n) * N_RN + 1024 + j);
            a0 += wattn[h][n] * vv.x;
            a1 += wattn[h][n] * vv.y;
            b0 += wsp[n] * vv.x;
            b1 += wsp[n] * vv.y;
        }
        uint32_t hh, ll;
        split2(a0, a1, hh, ll);
        ph[j2] = hh;
        pl[j2] = ll;
        *(float2*)(rsp + (size_t)t * DS + j) = make_float2(b0, b1);
    }
}

// ---------------- causal r-attention: MMA flash, 16-token tiles, -----------
// 256 threads / 8 warps share K/V tiles; 3-stage cp.async pipeline.
// Dynamic smem: 3 stages x (kh|kl|vh|vl) x 8KB = 96KB.
__global__ __launch_bounds__(256) void r_attn_mma(
    const float* __restrict__ qr, int qld,
    const uint32_t* __restrict__ kh_g, const uint32_t* __restrict__ kl_g,
    const uint32_t* __restrict__ vh_g, const uint32_t* __restrict__ vl_g,
    __nv_bfloat16* __restrict__ ar_h, __nv_bfloat16* __restrict__ ar_l)
{
    extern __shared__ __align__(16) uint32_t dsm[];
    uint32_t* skh = dsm;               // 3 x 2048
    uint32_t* skl = dsm + 3 * 2048;
    uint32_t* svh = dsm + 6 * 2048;
    uint32_t* svl = dsm + 9 * 2048;

    int tt = (int)(gridDim.x - 1 - blockIdx.x);  // long blocks first
    int h = blockIdx.y;
    int t0 = tt * 16;                  // 16 tokens per CTA
    int hb = h * DHR;

    int tid = threadIdx.x;
    int w = tid >> 5, lane = tid & 31;
    int gid = lane >> 2, tig = lane & 3;

    uint32_t bkh = smem_u32(skh), bkl = smem_u32(skl);
    uint32_t bvh = smem_u32(svh), bvl = smem_u32(svl);

    // warp w owns qr rows t0*8 + 16w .. +15 (tokens t0+2w, t0+2w+1)
    int r0 = t0 * 8 + 16 * w + gid;
    int r8 = r0 + 8;
    uint32_t qh[4][4], ql[4][4];
    #pragma unroll
    for (int kc = 0; kc < 4; kc++) {
        float2 x0 = *(const float2*)(qr + (size_t)r0 * qld + hb + kc * 16 + 2 * tig);
        float2 x1 = *(const float2*)(qr + (size_t)r8 * qld + hb + kc * 16 + 2 * tig);
        float2 x2 = *(const float2*)(qr + (size_t)r0 * qld + hb + kc * 16 + 2 * tig + 8);
        float2 x3 = *(const float2*)(qr + (size_t)r8 * qld + hb + kc * 16 + 2 * tig + 8);
        split2(x0.x * SCALE_R, x0.y * SCALE_R, qh[kc][0], ql[kc][0]);
        split2(x1.x * SCALE_R, x1.y * SCALE_R, qh[kc][1], ql[kc][1]);
        split2(x2.x * SCALE_R, x2.y * SCALE_R, qh[kc][2], ql[kc][2]);
        split2(x3.x * SCALE_R, x3.y * SCALE_R, qh[kc][3], ql[kc][3]);
    }
    int tok0 = t0 + ((16 * w + gid) >> 3);
    int tok8 = t0 + ((16 * w + gid + 8) >> 3);

    float m0 = -INFINITY, m1 = -INFINITY, l0 = 0.f, l1 = 0.f;
    float acco[8][4];
    #pragma unroll
    for (int i = 0; i < 8; i++)
        #pragma unroll
        for (int j = 0; j < 4; j++) acco[i][j] = 0.f;

    int ntiles = (t0 + 16 + 63) >> 6;

    auto issueT = [&](int st, int p0) {
        int pp0 = p0 >> 1;
        #pragma unroll
        for (int it = 0; it < 2; it++) {
            int idx = tid + it * 256;            // 0..511
            int p = idx >> 3, g = idx & 7;
            uint32_t doff = (uint32_t)(st * 8192) +
                            (uint32_t)(p * 32 + ((g ^ (p & 7)) << 2)) * 4;
            size_t ksrc = (size_t)(p0 + p) * 256 + h * 32 + g * 4;
            cp16(bkh + doff, kh_g + ksrc);
            cp16(bkl + doff, kl_g + ksrc);
            size_t vsrc = (size_t)h * 32768 + (size_t)p * 512 + pp0 + g * 4;
            cp16(bvh + doff, vh_g + vsrc);
            cp16(bvl + doff, vl_g + vsrc);
        }
        asm volatile("cp.async.commit_group;" ::: "memory");
    };

    issueT(0, 0);
    if (ntiles > 1) issueT(1, 64);

    for (int c = 0; c < ntiles; c++) {
        int p0 = c * 64;
        if (c + 1 < ntiles) {
            asm volatile("cp.async.wait_group 1;" ::: "memory");
        } else {
            asm volatile("cp.async.wait_group 0;" ::: "memory");
        }
        __syncthreads();
        if (c + 2 < ntiles) issueT((c + 2) % 3, (c + 2) * 64);

        uint32_t stoff = (uint32_t)((c % 3) * 2048);

        float s[8][4];
        #pragma unroll
        for (int i = 0; i < 8; i++)
            #pragma unroll
            for (int j = 0; j < 4; j++) s[i][j] = 0.f;

        #pragma unroll
        for (int nt = 0; nt < 8; nt++) {
            int n0 = nt * 8 + gid;
            int sw = n0 & 7;
            #pragma unroll
            for (int kc = 0; kc < 4; kc++) {
                uint32_t o0 = stoff + n0 * 32 + (((2 * kc) ^ sw) << 2) + tig;
                uint32_t o1 = stoff + n0 * 32 + (((2 * kc + 1) ^ sw) << 2) + tig;
                uint32_t bh0 = skh[o0], bh1 = skh[o1];
                uint32_t bl0 = skl[o0], bl1 = skl[o1];
                mma_bf16(s[nt], qh[kc], bh0, bh1);
                mma_bf16(s[nt], qh[kc], bl0, bl1);
                mma_bf16(s[nt], ql[kc], bh0, bh1);
            }
        }

        if (p0 + 64 > t0) {
            #pragma unroll
            for (int nt = 0; nt < 8; nt++) {
                int pg = p0 + nt * 8 + 2 * tig;
                if (pg > tok0)     s[nt][0] = -INFINITY;
                if (pg + 1 > tok0) s[nt][1] = -INFINITY;
                if (pg > tok8)     s[nt][2] = -INFINITY;
                if (pg + 1 > tok8) s[nt][3] = -INFINITY;
            }
        }

        float mx0 = -INFINITY, mx1 = -INFINITY;
        #pragma unroll
        for (int nt = 0; nt < 8; nt++) {
            mx0 = fmaxf(mx0, fmaxf(s[nt][0], s[nt][1]));
            mx1 = fmaxf(mx1, fmaxf(s[nt][2], s[nt][3]));
        }
        mx0 = fmaxf(mx0, __shfl_xor_sync(0xffffffffu, mx0, 1));
        mx0 = fmaxf(mx0, __shfl_xor_sync(0xffffffffu, mx0, 2));
        mx1 = fmaxf(mx1, __shfl_xor_sync(0xffffffffu, mx1, 1));
        mx1 = fmaxf(mx1, __shfl_xor_sync(0xffffffffu, mx1, 2));
        float nm0 = fmaxf(m0, mx0), nm1 = fmaxf(m1, mx1);
        float cr0 = __expf(m0 - nm0), cr1 = __expf(m1 - nm1);
        m0 = nm0; m1 = nm1;

        float rs0 = 0.f, rs1 = 0.f;
        #pragma unroll
        for (int nt = 0; nt < 8; nt++) {
            s[nt][0] = __expf(s[nt][0] - nm0);
            s[nt][1] = __expf(s[nt][1] - nm0);
            s[nt][2] = __expf(s[nt][2] - nm1);
            s[nt][3] = __expf(s[nt][3] - nm1);
            rs0 += s[nt][0] + s[nt][1];
            rs1 += s[nt][2] + s[nt][3];
        }
        rs0 += __shfl_xor_sync(0xffffffffu, rs0, 1);
        rs0 += __shfl_xor_sync(0xffffffffu, rs0, 2);
        rs1 += __shfl_xor_sync(0xffffffffu, rs1, 1);
        rs1 += __shfl_xor_sync(0xffffffffu, rs1, 2);
        l0 = l0 * cr0 + rs0;
        l1 = l1 * cr1 + rs1;

        #pragma unroll
        for (int ntd = 0; ntd < 8; ntd++) {
            acco[ntd][0] *= cr0; acco[ntd][1] *= cr0;
            acco[ntd][2] *= cr1; acco[ntd][3] *= cr1;
        }

        #pragma unroll
        for (int kc = 0; kc < 4; kc++) {
            uint32_t pah[4], pal[4];
            split2(s[2 * kc][0],     s[2 * kc][1],     pah[0], pal[0]);
            split2(s[2 * kc][2],     s[2 * kc][3],     pah[1], pal[1]);
            split2(s[2 * kc + 1][0], s[2 * kc + 1][1], pah[2], pal[2]);
            split2(s[2 * kc + 1][2], s[2 * kc + 1][3], pah[3], pal[3]);
            #pragma unroll
            for (int ntd = 0; ntd < 8; ntd++) {
                int d0 = ntd * 8 + gid;
                int sw = d0 & 7;
                uint32_t o0 = stoff + d0 * 32 + (((2 * kc) ^ sw) << 2) + tig;
                uint32_t o1 = stoff + d0 * 32 + (((2 * kc + 1) ^ sw) << 2) + tig;
                uint32_t bh0 = svh[o0], bh1 = svh[o1];
                uint32_t bl0 = svl[o0], bl1 = svl[o1];
                mma_bf16(acco[ntd], pah, bh0, bh1);
                mma_bf16(acco[ntd], pah, bl0, bl1);
                mma_bf16(acco[ntd], pal, bh0, bh1);
            }
        }
    }

    float i0 = 1.f / l0, i1 = 1.f / l1;
    #pragma unroll
    for (int ntd = 0; ntd < 8; ntd++) {
        int col = hb + ntd * 8 + 2 * tig;
        uint32_t hh, ll;
        split2(acco[ntd][0] * i0, acco[ntd][1] * i0, hh, ll);
        *(uint32_t*)(ar_h + (size_t)r0 * DR + col) = hh;
        *(uint32_t*)(ar_l + (size_t)r0 * DR + col) = ll;
        split2(acco[ntd][2] * i1, acco[ntd][3] * i1, hh, ll);
        *(uint32_t*)(ar_h + (size_t)r8 * DR + col) = hh;
        *(uint32_t*)(ar_l + (size_t)r8 * DR + col) = ll;
    }
}

// ---------------- host launch ----------------
extern "C" void kernel_launch(void* const* d_in, const int* in_sizes, int n_in,
                              void* d_out, int out_size)
{
    const float* s      = (const float*)d_in[0];
    const float* r      = (const float*)d_in[1];
    const float* gate_v = (const float*)d_in[2];
    const float* nsw    = (const float*)d_in[3];
    const float* nrw    = (const float*)d_in[4];
    const float* Wsq    = (const float*)d_in[5];
    const float* Wsk    = (const float*)d_in[6];
    const float* Wsv    = (const float*)d_in[7];
    const float* Wso    = (const float*)d_in[8];
    const float* Wrq    = (const float*)d_in[9];
    const float* Wrk    = (const float*)d_in[10];
    const float* Wrv    = (const float*)d_in[11];
    const float* Wro    = (const float*)d_in[12];

    float* out_s = (float*)d_out;
    float* out_r = (float*)d_out + T_LEN * DS;

    __nv_bfloat16 *snh, *snl, *rnh, *rnl, *ash, *asl, *arh, *arl;
    __nv_bfloat16 *wsnh, *wsnl, *wrnh, *wrnl, *wsoh, *wsol, *wroh, *wrol;
    float *csn, *crn, *rsp;
    uint32_t *kh, *kl, *vth, *vtl;
    cudaGetSymbolAddress((void**)&snh, g_sn_h);
    cudaGetSymbolAddress((void**)&snl, g_sn_l);
    cudaGetSymbolAddress((void**)&rnh, g_rn_h);
    cudaGetSymbolAddress((void**)&rnl, g_rn_l);
    cudaGetSymbolAddress((void**)&ash, g_as_h);
    cudaGetSymbolAddress((void**)&asl, g_as_l);
    cudaGetSymbolAddress((void**)&arh, g_ar_h);
    cudaGetSymbolAddress((void**)&arl, g_ar_l);
    cudaGetSymbolAddress((void**)&wsnh, g_wsn_h);
    cudaGetSymbolAddress((void**)&wsnl, g_wsn_l);
    cudaGetSymbolAddress((void**)&wrnh, g_wrn_h);
    cudaGetSymbolAddress((void**)&wrnl, g_wrn_l);
    cudaGetSymbolAddress((void**)&wsoh, g_wso_h);
    cudaGetSymbolAddress((void**)&wsol, g_wso_l);
    cudaGetSymbolAddress((void**)&wroh, g_wro_h);
    cudaGetSymbolAddress((void**)&wrol, g_wro_l);
    cudaGetSymbolAddress((void**)&csn, g_csn);
    cudaGetSymbolAddress((void**)&crn, g_crn);
    cudaGetSymbolAddress((void**)&rsp, g_rsp);
    cudaGetSymbolAddress((void**)&kh, g_kh);
    cudaGetSymbolAddress((void**)&kl, g_kl);
    cudaGetSymbolAddress((void**)&vth, g_vth);
    cudaGetSymbolAddress((void**)&vtl, g_vtl);

    // ---- 1. prep: weight transposes + rmsnorms ----
    prep_kernel<<<4608 + T_LEN + ROWS_R, 256>>>(
        Wsq, Wsk, Wsv, Wso, Wrq, Wrk, Wrv, Wro,
        wsnh, wsnl, wrnh, wrnl, wsoh, wsol, wroh, wrol,
        s, nsw, snh, snl, r, nrw, rnh, rnl);

    // ---- 2. merged projection GEMMs ----
    {
        GArg g0 = {snh, snl, wsnh, wsnl, csn, T_LEN, N_SN, DS, N_SN,
                   nullptr, nullptr, nullptr};
        GArg g1 = {rnh, rnl, wrnh, wrnl, crn, ROWS_R, N_RN, DR, N_RN,
                   nullptr, nullptr, nullptr};
        int gx0 = N_SN / 128, gy0 = T_LEN / 64;
        int gx1 = N_RN / 128, gy1 = ROWS_R / 64;
        gemm_pair<<<gx0 * gy0 + gx1 * gy1, 256>>>(g0, g1, gx0 * gy0, gx0, gx1);
    }

    // ---- 3. conv_kv + s-attention ----
    conv_sattn_kernel<<<T_LEN + 1024 + T_LEN, 256>>>(
        csn, crn, kh, kl, vth, vtl, ash, asl, rsp);

    // ---- 4. causal r attention (16-token tiles, pipelined) ----
    cudaFuncSetAttribute(r_attn_mma,
                         cudaFuncAttributeMaxDynamicSharedMemorySize, 98304);
    r_attn_mma<<<dim3(T_LEN / 16, HEADS), 256, 98304>>>(
        crn + 2048, N_RN, kh, kl, vth, vtl, arh, arl);

    // ---- 5. merged output GEMMs ----
    {
        GArg g0 = {ash, asl, wsoh, wsol, out_s, T_LEN, DS, DS, DS,
                   s, rsp, gate_v};
        GArg g1 = {arh, arl, wroh, wrol, out_r, ROWS_R, DR, DR, DR,
                   r, nullptr, nullptr};
        int gx0 = DS / 128, gy0 = T_LEN / 64;
        int gx1 = DR / 128, gy1 = ROWS_R / 64;
        gemm_pair<<<gx0 * gy0 + gx1 * gy1, 256>>>(g0, g1, gx0 * gy0, gx0, gx1);
    }
}

// round 12
// speedup vs baseline: 1.0246x; 1.0246x over previous
#include <cuda_runtime.h>
#include <cuda_bf16.h>
#include <math.h>
#include <stdint.h>

// ---------------- problem constants ----------------
#define T_LEN 1024
#define NSLOT 8
#define DS 1024
#define DR 512
#define HEADS 8
#define DHS 128
#define DHR 64
#define TOPK 4
#define ROWS_R (T_LEN * NSLOT)   // 8192
#define SCALE_S 0.08838834764831845f  // 1/sqrt(128)
#define SCALE_R 0.125f                // 1/sqrt(64)
#define EPS 1e-6f

// fused layouts
#define N_SN 2048        // q(1024) | kr(512) | vr(512), K=1024
#define N_RN 2560        // k(1024) | v(1024) | qr(512), K=512

// ---------------- scratch (static device memory; no allocation) -------------
__device__ __nv_bfloat16 g_sn_h[T_LEN * DS], g_sn_l[T_LEN * DS];
__device__ __nv_bfloat16 g_rn_h[ROWS_R * DR], g_rn_l[ROWS_R * DR];
__device__ __nv_bfloat16 g_as_h[T_LEN * DS], g_as_l[T_LEN * DS];
__device__ __nv_bfloat16 g_ar_h[ROWS_R * DR], g_ar_l[ROWS_R * DR];
__device__ __nv_bfloat16 g_wsn_h[N_SN * DS], g_wsn_l[N_SN * DS];
__device__ __nv_bfloat16 g_wrn_h[N_RN * DR], g_wrn_l[N_RN * DR];
__device__ __nv_bfloat16 g_wso_h[DS * DS], g_wso_l[DS * DS];
__device__ __nv_bfloat16 g_wro_h[DR * DR], g_wro_l[DR * DR];
__device__ float g_csn[T_LEN * N_SN];     // q | kr | vr
__device__ float g_crn[ROWS_R * N_RN];    // k | v | qr
__device__ float g_rsp[T_LEN * DS];
__device__ uint32_t g_kh[T_LEN * 256], g_kl[T_LEN * 256];
__device__ uint32_t g_vth[HEADS * DHR * (T_LEN / 2)];
__device__ uint32_t g_vtl[HEADS * DHR * (T_LEN / 2)];

// ---------------- PTX helpers ----------------
__device__ __forceinline__ uint32_t smem_u32(const void* p) {
    uint32_t a;
    asm("{ .reg .u64 t; cvta.to.shared.u64 t, %1; cvt.u32.u64 %0, t; }"
        : "=r"(a) : "l"(p));
    return a;
}
__device__ __forceinline__ void cp16(uint32_t dst, const void* src) {
    asm volatile("cp.async.cg.shared.global [%0], [%1], 16;"
                 :: "r"(dst), "l"(src) : "memory");
}
__device__ __forceinline__ void ldm_x4(uint32_t* r, uint32_t addr) {
    asm volatile("ldmatrix.sync.aligned.m8n8.x4.shared.b16 {%0,%1,%2,%3}, [%4];"
                 : "=r"(r[0]), "=r"(r[1]), "=r"(r[2]), "=r"(r[3]) : "r"(addr));
}
__device__ __forceinline__ void mma_bf16(
    float* c, const uint32_t* a, uint32_t b0, uint32_t b1)
{
    asm volatile(
        "mma.sync.aligned.m16n8k16.row.col.f32.bf16.bf16.f32 "
        "{%0,%1,%2,%3}, {%4,%5,%6,%7}, {%8,%9}, {%0,%1,%2,%3};"
        : "+f"(c[0]), "+f"(c[1]), "+f"(c[2]), "+f"(c[3])
        : "r"(a[0]), "r"(a[1]), "r"(a[2]), "r"(a[3]), "r"(b0), "r"(b1));
}
__device__ __forceinline__ void split2(float x, float y,
                                       uint32_t& hi, uint32_t& lo)
{
    __nv_bfloat162 h = __floats2bfloat162_rn(x, y);
    float xr = x - __bfloat162float(h.x);
    float yr = y - __bfloat162float(h.y);
    __nv_bfloat162 l = __floats2bfloat162_rn(xr, yr);
    hi = *(uint32_t*)&h;
    lo = *(uint32_t*)&l;
}

// ---------------- merged prep: 8 weight transposes + 2 rmsnorms -------------
__global__ __launch_bounds__(256) void prep_kernel(
    const float* __restrict__ Wsq, const float* __restrict__ Wsk,
    const float* __restrict__ Wsv, const float* __restrict__ Wso,
    const float* __restrict__ Wrq, const float* __restrict__ Wrk,
    const float* __restrict__ Wrv, const float* __restrict__ Wro,
    __nv_bfloat16* __restrict__ wsnh, __nv_bfloat16* __restrict__ wsnl,
    __nv_bfloat16* __restrict__ wrnh, __nv_bfloat16* __restrict__ wrnl,
    __nv_bfloat16* __restrict__ wsoh, __nv_bfloat16* __restrict__ wsol,
    __nv_bfloat16* __restrict__ wroh, __nv_bfloat16* __restrict__ wrol,
    const float* __restrict__ s, const float* __restrict__ nsw,
    __nv_bfloat16* __restrict__ snh, __nv_bfloat16* __restrict__ snl,
    const float* __restrict__ r, const float* __restrict__ nrw,
    __nv_bfloat16* __restrict__ rnh, __nv_bfloat16* __restrict__ rnl)
{
    int b = blockIdx.x;
    if (b < 4608) {
        const float* W;
        __nv_bfloat16 *th, *tl;
        int K, N;
        if (b < 1024)      { W = Wsq; th = wsnh; tl = wsnl; K = 1024; N = 1024; }
        else if (b < 1536) { b -= 1024; W = Wrk; th = wsnh + 1024 * 1024;
                             tl = wsnl + 1024 * 1024; K = 1024; N = 512; }
        else if (b < 2048) { b -= 1536; W = Wrv; th = wsnh + 1536 * 1024;
                             tl = wsnl + 1536 * 1024; K = 1024; N = 512; }
        else if (b < 2560) { b -= 2048; W = Wsk; th = wrnh; tl = wrnl;
                             K = 512; N = 1024; }
        else if (b < 3072) { b -= 2560; W = Wsv; th = wrnh + 1024 * 512;
                             tl = wrnl + 1024 * 512; K = 512; N = 1024; }
        else if (b < 3328) { b -= 3072; W = Wrq; th = wrnh + 2048 * 512;
                             tl = wrnl + 2048 * 512; K = 512; N = 512; }
        else if (b < 4352) { b -= 3328; W = Wso; th = wsoh; tl = wsol;
                             K = 1024; N = 1024; }
        else               { b -= 4352; W = Wro; th = wroh; tl = wrol;
                             K = 512; N = 512; }

        int ntx = N >> 5;
        int bx = (b % ntx) * 32;
        int by = (b / ntx) * 32;

        __shared__ float t[32][33];
        int tx = threadIdx.x & 31, ty = threadIdx.x >> 5;
        #pragma unroll
        for (int i = 0; i < 4; i++)
            t[ty + i * 8][tx] = W[(size_t)(by + ty + i * 8) * N + bx + tx];
        __syncthreads();
        #pragma unroll
        for (int i = 0; i < 4; i++) {
            int n = bx + ty + i * 8;
            int k = by + tx;
            float v = t[tx][ty + i * 8];
            __nv_bfloat16 h = __float2bfloat16(v);
            th[(size_t)n * K + k] = h;
            tl[(size_t)n * K + k] = __float2bfloat16(v - __bfloat162float(h));
        }
        return;
    }
    const float *x, *w;
    __nv_bfloat16 *oh, *ol;
    int C, row;
    if (b < 4608 + T_LEN) {
        row = b - 4608; x = s; w = nsw; oh = snh; ol = snl; C = DS;
    } else {
        row = b - 4608 - T_LEN; x = r; w = nrw; oh = rnh; ol = rnl; C = DR;
    }
    const float* xr = x + (size_t)row * C;
    float acc = 0.f;
    for (int j = threadIdx.x; j < C; j += 256) {
        float v = xr[j];
        acc += v * v;
    }
    __shared__ float red[8];
    int lane = threadIdx.x & 31, warp = threadIdx.x >> 5;
    #pragma unroll
    for (int off = 16; off; off >>= 1) acc += __shfl_xor_sync(0xffffffffu, acc, off);
    if (lane == 0) red[warp] = acc;
    __syncthreads();
    __shared__ float scale;
    if (threadIdx.x == 0) {
        float tot = 0.f;
        #pragma unroll
        for (int i = 0; i < 8; i++) tot += red[i];
        scale = rsqrtf(tot / (float)C + EPS);
    }
    __syncthreads();
    float sc = scale;
    uint32_t* ph = (uint32_t*)(oh + (size_t)row * C);
    uint32_t* pl = (uint32_t*)(ol + (size_t)row * C);
    for (int j2 = threadIdx.x; j2 < C / 2; j2 += 256) {
        float v0 = xr[2 * j2] * sc * w[2 * j2];
        float v1 = xr[2 * j2 + 1] * sc * w[2 * j2 + 1];
        uint32_t h, l;
        split2(v0, v1, h, l);
        ph[j2] = h;
        pl[j2] = l;
    }
}

// ---------------- bf16-split mma GEMM body (64x128 tile) --------------------
struct GArg {
    const __nv_bfloat16 *Ah, *Al, *Bh, *Bl;
    float* C;
    int M, N, K, ldc;
    const float *add1, *add2, *rowscale;
};

__device__ __forceinline__ void gemm_body(
    const GArg g, int bx, int by,
    uint32_t bAh, uint32_t bAl, uint32_t bBh, uint32_t bBl)
{
    int tid = threadIdx.x;
    int lane = tid & 31, wid = tid >> 5;
    int wm = wid & 1, wn = wid >> 1;
    int bm = by * 64, bn = bx * 128;
    int gid = lane >> 2, tig = lane & 3;
    int K = g.K;

    float acc[2][4][4];
    #pragma unroll
    for (int i = 0; i < 2; i++)
        #pragma unroll
        for (int j = 0; j < 4; j++)
            #pragma unroll
            for (int l = 0; l < 4; l++) acc[i][j][l] = 0.f;

    uint32_t aoff0, aoff1, boff0, boff1;
    {
        int lrow = lane & 7;
        int rA = wm * 32 + lrow + (lane & 8);
        int cA = (lane & 16) >> 2;
        aoff0 = (uint32_t)(rA * 8 + cA) * 4;
        aoff1 = (uint32_t)((rA + 16) * 8 + cA) * 4;
        int rB = wn * 32 + lrow + ((lane & 16) >> 1);
        int cB = (lane & 8) >> 1;
        boff0 = (uint32_t)(rB * 8 + cB) * 4;
        boff1 = (uint32_t)((rB + 16) * 8 + cB) * 4;
    }

    int row = tid >> 1;
    int gg = tid & 1;
    const __nv_bfloat16 *Ah = g.Ah, *Al = g.Al, *Bh = g.Bh, *Bl = g.Bl;
    auto issue = [&](int st, int k0) {
        uint32_t bdoff = (uint32_t)(st * 128 * 8 + row * 8 + gg * 4) * 4;
        size_t bsrc = (size_t)(bn + row) * K + k0 + gg * 8;
        cp16(bBh + bdoff, Bh + bsrc);
        cp16(bBl + bdoff, Bl + bsrc);
        if (tid < 128) {
            uint32_t adoff = (uint32_t)(st * 64 * 8 + row * 8 + gg * 4) * 4;
            size_t asrc = (size_t)(bm + row) * K + k0 + gg * 8;
            cp16(bAh + adoff, Ah + asrc);
            cp16(bAl + adoff, Al + asrc);
        }
        asm volatile("cp.async.commit_group;" ::: "memory");
    };

    int nch = K >> 4;
    issue(0, 0);
    if (nch > 1) issue(1, 16);

    for (int c = 0; c < nch; c++) {
        if (c + 1 < nch) {
            asm volatile("cp.async.wait_group 1;" ::: "memory");
        } else {
            asm volatile("cp.async.wait_group 0;" ::: "memory");
        }
        __syncthreads();
        if (c + 2 < nch) issue((c + 2) % 3, (c + 2) * 16);

        uint32_t aoffst = (uint32_t)((c % 3) * 64 * 8 * 4);
        uint32_t boffst = (uint32_t)((c % 3) * 128 * 8 * 4);

        uint32_t ah[2][4], al[2][4];
        ldm_x4(ah[0], bAh + aoffst + aoff0);
        ldm_x4(ah[1], bAh + aoffst + aoff1);
        ldm_x4(al[0], bAl + aoffst + aoff0);
        ldm_x4(al[1], bAl + aoffst + aoff1);

        #pragma unroll
        for (int p = 0; p < 2; p++) {
            uint32_t bh[4], bl[4];
            ldm_x4(bh, bBh + boffst + (p ? boff1 : boff0));
            ldm_x4(bl, bBl + boffst + (p ? boff1 : boff0));
            #pragma unroll
            for (int q = 0; q < 2; q++) {
                int nt = p * 2 + q;
                uint32_t b0h = bh[2 * q], b1h = bh[2 * q + 1];
                uint32_t b0l = bl[2 * q], b1l = bl[2 * q + 1];
                mma_bf16(acc[0][nt], ah[0], b0h, b1h);
                mma_bf16(acc[0][nt], ah[0], b0l, b1l);
                mma_bf16(acc[0][nt], al[0], b0h, b1h);
                mma_bf16(acc[1][nt], ah[1], b0h, b1h);
                mma_bf16(acc[1][nt], ah[1], b0l, b1l);
                mma_bf16(acc[1][nt], al[1], b0h, b1h);
            }
        }
    }

    #pragma unroll
    for (int mt = 0; mt < 2; mt++) {
        int r0 = bm + wm * 32 + mt * 16 + gid;
        float rs0 = (g.rowscale != nullptr) ? g.rowscale[r0] : 0.f;
        float rs8 = (g.rowscale != nullptr) ? g.rowscale[r0 + 8] : 0.f;
        #pragma unroll
        for (int nt = 0; nt < 4; nt++) {
            int col = bn + wn * 32 + nt * 8 + 2 * tig;
            size_t o0 = (size_t)r0 * g.ldc + col;
            size_t o8 = (size_t)(r0 + 8) * g.ldc + col;
            float2 v0 = make_float2(acc[mt][nt][0], acc[mt][nt][1]);
            float2 v8 = make_float2(acc[mt][nt][2], acc[mt][nt][3]);
            if (g.add1) {
                float2 x = *(const float2*)(g.add1 + o0);
                v0.x += x.x; v0.y += x.y;
                x = *(const float2*)(g.add1 + o8);
                v8.x += x.x; v8.y += x.y;
            }
            if (g.add2) {
                float2 x = *(const float2*)(g.add2 + o0);
                v0.x += rs0 * x.x; v0.y += rs0 * x.y;
                x = *(const float2*)(g.add2 + o8);
                v8.x += rs8 * x.x; v8.y += rs8 * x.y;
            }
            *(float2*)(g.C + o0) = v0;
            *(float2*)(g.C + o8) = v8;
        }
    }
}

__global__ __launch_bounds__(256, 3) void gemm_pair(
    GArg g0, GArg g1, int nblk0, int gx0, int gx1)
{
    __shared__ __align__(16) uint32_t sAh[3][64 * 8], sAl[3][64 * 8];
    __shared__ __align__(16) uint32_t sBh[3][128 * 8], sBl[3][128 * 8];
    uint32_t bAh = smem_u32(sAh), bAl = smem_u32(sAl);
    uint32_t bBh = smem_u32(sBh), bBl = smem_u32(sBl);

    int b = blockIdx.x;
    if (b < nblk0)
        gemm_body(g0, b % gx0, b / gx0, bAh, bAl, bBh, bBl);
    else {
        b -= nblk0;
        gemm_body(g1, b % gx1, b / gx1, bAh, bAl, bBh, bBl);
    }
}

// ---------------- merged conv_kv + s-attention ----------------
__global__ __launch_bounds__(256) void conv_sattn_kernel(
    const float* __restrict__ csn,
    const float* __restrict__ crn,
    uint32_t* __restrict__ kh, uint32_t* __restrict__ kl,
    uint32_t* __restrict__ vh, uint32_t* __restrict__ vl,
    __nv_bfloat16* __restrict__ as_h, __nv_bfloat16* __restrict__ as_l,
    float* __restrict__ rsp)
{
    int b = blockIdx.x;
    if (b < T_LEN) {
        int t = b, j = threadIdx.x;
        float2 v = *(const float2*)(csn + (size_t)t * N_SN + 1024 + 2 * j);
        uint32_t h, l;
        split2(v.x, v.y, h, l);
        kh[(size_t)t * 256 + j] = h;
        kl[(size_t)t * 256 + j] = l;
        return;
    }
    if (b < T_LEN + 1024) {
        int idx = (b - T_LEN) * 256 + threadIdx.x;
        int pp = idx & 511;
        int d = (idx >> 9) & 63;
        int h = idx >> 15;
        float v0 = csn[(size_t)(2 * pp) * N_SN + 1536 + h * DHR + d];
        float v1 = csn[(size_t)(2 * pp + 1) * N_SN + 1536 + h * DHR + d];
        uint32_t hh, ll;
        split2(v0, v1, hh, ll);
        vh[idx] = hh;
        vl[idx] = ll;
        return;
    }
    int t = b - T_LEN - 1024;
    int tid = threadIdx.x;
    int warp = tid >> 5, lane = tid & 31;

    __shared__ float qs[DS];
    __shared__ float logits[HEADS][NSLOT];
    __shared__ float wattn[HEADS][NSLOT];
    __shared__ float wsp[NSLOT];

    for (int j = tid; j < DS; j += 256) qs[j] = csn[(size_t)t * N_SN + j];
    __syncthreads();

    {
        int h = warp;
        #pragma unroll
        for (int n = 0; n < NSLOT; n++) {
            const float* krow = crn + (size_t)(t * NSLOT + n) * N_RN + h * DHS;
            const float* qrow = qs + h * DHS;
            float p = 0.f;
            #pragma unroll
            for (int d = lane; d < DHS; d += 32) p += qrow[d] * krow[d];
            #pragma unroll
            for (int off = 16; off; off >>= 1) p += __shfl_xor_sync(0xffffffffu, p, off);
            if (lane == 0) logits[h][n] = p;
        }
    }
    __syncthreads();

    if (tid < HEADS) {
        int h = tid;
        float m = -INFINITY;
        #pragma unroll
        for (int n = 0; n < NSLOT; n++) m = fmaxf(m, logits[h][n] * SCALE_S);
        float sum = 0.f;
        #pragma unroll
        for (int n = 0; n < NSLOT; n++) {
            float e = __expf(logits[h][n] * SCALE_S - m);
            wattn[h][n] = e;
            sum += e;
        }
        float inv = 1.f / sum;
        #pragma unroll
        for (int n = 0; n < NSLOT; n++) wattn[h][n] *= inv;
    }
    if (tid == 8) {
        float sp[NSLOT];
        #pragma unroll
        for (int n = 0; n < NSLOT; n++) {
            float a = 0.f;
            #pragma unroll
            for (int h = 0; h < HEADS; h++) a += logits[h][n];
            sp[n] = a * SCALE_S;
        }
        bool sel[NSLOT];
        #pragma unroll
        for (int n = 0; n < NSLOT; n++) { sel[n] = false; wsp[n] = 0.f; }
        int idxs[TOPK];
        #pragma unroll
        for (int kk = 0; kk < TOPK; kk++) {
            int best = -1; float bv = -INFINITY;
            #pragma unroll
            for (int n = 0; n < NSLOT; n++)
                if (!sel[n] && sp[n] > bv) { bv = sp[n]; best = n; }
            sel[best] = true; idxs[kk] = best;
        }
        float m = -INFINITY;
        #pragma unroll
        for (int kk = 0; kk < TOPK; kk++) m = fmaxf(m, sp[idxs[kk]]);
        float sum = 0.f, e[TOPK];
        #pragma unroll
        for (int kk = 0; kk < TOPK; kk++) { e[kk] = __expf(sp[idxs[kk]] - m); sum += e[kk]; }
        float inv = 1.f / sum;
        #pragma unroll
        for (int kk = 0; kk < TOPK; kk++) wsp[idxs[kk]] = e[kk] * inv;
    }
    __syncthreads();

    uint32_t* ph = (uint32_t*)(as_h + (size_t)t * DS);
    uint32_t* pl = (uint32_t*)(as_l + (size_t)t * DS);
    for (int j2 = tid; j2 < DS / 2; j2 += 256) {
        int j = 2 * j2;
        int h = j >> 7;
        float a0 = 0.f, a1 = 0.f, b0 = 0.f, b1 = 0.f;
        #pragma unroll
        for (int n = 0; n < NSLOT; n++) {
            float2 vv = *(const float2*)(crn + (size_t)(t * NSLOT + n) * N_RN + 1024 + j);
            a0 += wattn[h][n] * vv.x;
            a1 += wattn[h][n] * vv.y;
            b0 += wsp[n] * vv.x;
            b1 += wsp[n] * vv.y;
        }
        uint32_t hh, ll;
        split2(a0, a1, hh, ll);
        ph[j2] = hh;
        pl[j2] = ll;
        *(float2*)(rsp + (size_t)t * DS + j) = make_float2(b0, b1);
    }
}

// ---------------- causal r-attention: MMA flash, 8-token tiles, -------------
// 128 threads / 4 warps; 3-stage cp.async pipeline in 96KB dynamic smem.
// regs ~208 x 128 threads = 26.6K -> 2 CTAs/SM; smem 96KB -> 2 CTAs/SM.
__global__ __launch_bounds__(128) void r_attn_mma(
    const float* __restrict__ qr, int qld,
    const uint32_t* __restrict__ kh_g, const uint32_t* __restrict__ kl_g,
    const uint32_t* __restrict__ vh_g, const uint32_t* __restrict__ vl_g,
    __nv_bfloat16* __restrict__ ar_h, __nv_bfloat16* __restrict__ ar_l)
{
    extern __shared__ __align__(16) uint32_t dsm[];
    uint32_t* skh = dsm;               // 3 stages x 2048 u32
    uint32_t* skl = dsm + 3 * 2048;
    uint32_t* svh = dsm + 6 * 2048;
    uint32_t* svl = dsm + 9 * 2048;

    int tt = (int)(gridDim.x - 1 - blockIdx.x);  // long blocks first
    int h = blockIdx.y;
    int t0 = tt * 8;
    int hb = h * DHR;

    int tid = threadIdx.x;
    int w = tid >> 5, lane = tid & 31;
    int gid = lane >> 2, tig = lane & 3;

    uint32_t bkh = smem_u32(skh), bkl = smem_u32(skl);
    uint32_t bvh = smem_u32(svh), bvl = smem_u32(svl);

    int r0 = t0 * 8 + 16 * w + gid;
    int r8 = r0 + 8;
    uint32_t qh[4][4], ql[4][4];
    #pragma unroll
    for (int kc = 0; kc < 4; kc++) {
        float2 x0 = *(const float2*)(qr + (size_t)r0 * qld + hb + kc * 16 + 2 * tig);
        float2 x1 = *(const float2*)(qr + (size_t)r8 * qld + hb + kc * 16 + 2 * tig);
        float2 x2 = *(const float2*)(qr + (size_t)r0 * qld + hb + kc * 16 + 2 * tig + 8);
        float2 x3 = *(const float2*)(qr + (size_t)r8 * qld + hb + kc * 16 + 2 * tig + 8);
        split2(x0.x * SCALE_R, x0.y * SCALE_R, qh[kc][0], ql[kc][0]);
        split2(x1.x * SCALE_R, x1.y * SCALE_R, qh[kc][1], ql[kc][1]);
        split2(x2.x * SCALE_R, x2.y * SCALE_R, qh[kc][2], ql[kc][2]);
        split2(x3.x * SCALE_R, x3.y * SCALE_R, qh[kc][3], ql[kc][3]);
    }
    int tok0 = t0 + ((16 * w + gid) >> 3);
    int tok8 = t0 + ((16 * w + gid + 8) >> 3);

    float m0 = -INFINITY, m1 = -INFINITY, l0 = 0.f, l1 = 0.f;
    float acco[8][4];
    #pragma unroll
    for (int i = 0; i < 8; i++)
        #pragma unroll
        for (int j = 0; j < 4; j++) acco[i][j] = 0.f;

    int ntiles = ((t0 + 7) >> 6) + 1;

    auto issueT = [&](int st, int p0) {
        int pp0 = p0 >> 1;
        #pragma unroll
        for (int it = 0; it < 4; it++) {
            int idx = tid + it * 128;            // 0..511
            int p = idx >> 3, g = idx & 7;
            uint32_t doff = (uint32_t)(st * 8192) +
                            (uint32_t)(p * 32 + ((g ^ (p & 7)) << 2)) * 4;
            size_t ksrc = (size_t)(p0 + p) * 256 + h * 32 + g * 4;
            cp16(bkh + doff, kh_g + ksrc);
            cp16(bkl + doff, kl_g + ksrc);
            size_t vsrc = (size_t)h * 32768 + (size_t)p * 512 + pp0 + g * 4;
            cp16(bvh + doff, vh_g + vsrc);
            cp16(bvl + doff, vl_g + vsrc);
        }
        asm volatile("cp.async.commit_group;" ::: "memory");
    };

    issueT(0, 0);
    if (ntiles > 1) issueT(1, 64);

    for (int c = 0; c < ntiles; c++) {
        int p0 = c * 64;
        if (c + 1 < ntiles) {
            asm volatile("cp.async.wait_group 1;" ::: "memory");
        } else {
            asm volatile("cp.async.wait_group 0;" ::: "memory");
        }
        __syncthreads();
        if (c + 2 < ntiles) issueT((c + 2) % 3, (c + 2) * 64);

        uint32_t stoff = (uint32_t)((c % 3) * 2048);

        float s[8][4];
        #pragma unroll
        for (int i = 0; i < 8; i++)
            #pragma unroll
            for (int j = 0; j < 4; j++) s[i][j] = 0.f;

        #pragma unroll
        for (int nt = 0; nt < 8; nt++) {
            int n0 = nt * 8 + gid;
            int sw = n0 & 7;
            #pragma unroll
            for (int kc = 0; kc < 4; kc++) {
                uint32_t o0 = stoff + n0 * 32 + (((2 * kc) ^ sw) << 2) + tig;
                uint32_t o1 = stoff + n0 * 32 + (((2 * kc + 1) ^ sw) << 2) + tig;
                uint32_t bh0 = skh[o0], bh1 = skh[o1];
                uint32_t bl0 = skl[o0], bl1 = skl[o1];
                mma_bf16(s[nt], qh[kc], bh0, bh1);
                mma_bf16(s[nt], qh[kc], bl0, bl1);
                mma_bf16(s[nt], ql[kc], bh0, bh1);
            }
        }

        if (p0 + 64 > t0) {
            #pragma unroll
            for (int nt = 0; nt < 8; nt++) {
                int pg = p0 + nt * 8 + 2 * tig;
                if (pg > tok0)     s[nt][0] = -INFINITY;
                if (pg + 1 > tok0) s[nt][1] = -INFINITY;
                if (pg > tok8)     s[nt][2] = -INFINITY;
                if (pg + 1 > tok8) s[nt][3] = -INFINITY;
            }
        }

        float mx0 = -INFINITY, mx1 = -INFINITY;
        #pragma unroll
        for (int nt = 0; nt < 8; nt++) {
            mx0 = fmaxf(mx0, fmaxf(s[nt][0], s[nt][1]));
            mx1 = fmaxf(mx1, fmaxf(s[nt][2], s[nt][3]));
        }
        mx0 = fmaxf(mx0, __shfl_xor_sync(0xffffffffu, mx0, 1));
        mx0 = fmaxf(mx0, __shfl_xor_sync(0xffffffffu, mx0, 2));
        mx1 = fmaxf(mx1, __shfl_xor_sync(0xffffffffu, mx1, 1));
        mx1 = fmaxf(mx1, __shfl_xor_sync(0xffffffffu, mx1, 2));
        float nm0 = fmaxf(m0, mx0), nm1 = fmaxf(m1, mx1);
        float cr0 = __expf(m0 - nm0), cr1 = __expf(m1 - nm1);
        m0 = nm0; m1 = nm1;

        float rs0 = 0.f, rs1 = 0.f;
        #pragma unroll
        for (int nt = 0; nt < 8; nt++) {
            s[nt][0] = __expf(s[nt][0] - nm0);
            s[nt][1] = __expf(s[nt][1] - nm0);
            s[nt][2] = __expf(s[nt][2] - nm1);
            s[nt][3] = __expf(s[nt][3] - nm1);
            rs0 += s[nt][0] + s[nt][1];
            rs1 += s[nt][2] + s[nt][3];
        }
        rs0 += __shfl_xor_sync(0xffffffffu, rs0, 1);
        rs0 += __shfl_xor_sync(0xffffffffu, rs0, 2);
        rs1 += __shfl_xor_sync(0xffffffffu, rs1, 1);
        rs1 += __shfl_xor_sync(0xffffffffu, rs1, 2);
        l0 = l0 * cr0 + rs0;
        l1 = l1 * cr1 + rs1;

        #pragma unroll
        for (int ntd = 0; ntd < 8; ntd++) {
            acco[ntd][0] *= cr0; acco[ntd][1] *= cr0;
            acco[ntd][2] *= cr1; acco[ntd][3] *= cr1;
        }

        #pragma unroll
        for (int kc = 0; kc < 4; kc++) {
            uint32_t pah[4], pal[4];
            split2(s[2 * kc][0],     s[2 * kc][1],     pah[0], pal[0]);
            split2(s[2 * kc][2],     s[2 * kc][3],     pah[1], pal[1]);
            split2(s[2 * kc + 1][0], s[2 * kc + 1][1], pah[2], pal[2]);
            split2(s[2 * kc + 1][2], s[2 * kc + 1][3], pah[3], pal[3]);
            #pragma unroll
            for (int ntd = 0; ntd < 8; ntd++) {
                int d0 = ntd * 8 + gid;
                int sw = d0 & 7;
                uint32_t o0 = stoff + d0 * 32 + (((2 * kc) ^ sw) << 2) + tig;
                uint32_t o1 = stoff + d0 * 32 + (((2 * kc + 1) ^ sw) << 2) + tig;
                uint32_t bh0 = svh[o0], bh1 = svh[o1];
                uint32_t bl0 = svl[o0], bl1 = svl[o1];
                mma_bf16(acco[ntd], pah, bh0, bh1);
                mma_bf16(acco[ntd], pah, bl0, bl1);
                mma_bf16(acco[ntd], pal, bh0, bh1);
            }
        }
    }

    float i0 = 1.f / l0, i1 = 1.f / l1;
    #pragma unroll
    for (int ntd = 0; ntd < 8; ntd++) {
        int col = hb + ntd * 8 + 2 * tig;
        uint32_t hh, ll;
        split2(acco[ntd][0] * i0, acco[ntd][1] * i0, hh, ll);
        *(uint32_t*)(ar_h + (size_t)r0 * DR + col) = hh;
        *(uint32_t*)(ar_l + (size_t)r0 * DR + col) = ll;
        split2(acco[ntd][2] * i1, acco[ntd][3] * i1, hh, ll);
        *(uint32_t*)(ar_h + (size_t)r8 * DR + col) = hh;
        *(uint32_t*)(ar_l + (size_t)r8 * DR + col) = ll;
    }
}

// ---------------- host launch ----------------
extern "C" void kernel_launch(void* const* d_in, const int* in_sizes, int n_in,
                              void* d_out, int out_size)
{
    const float* s      = (const float*)d_in[0];
    const float* r      = (const float*)d_in[1];
    const float* gate_v = (const float*)d_in[2];
    const float* nsw    = (const float*)d_in[3];
    const float* nrw    = (const float*)d_in[4];
    const float* Wsq    = (const float*)d_in[5];
    const float* Wsk    = (const float*)d_in[6];
    const float* Wsv    = (const float*)d_in[7];
    const float* Wso    = (const float*)d_in[8];
    const float* Wrq    = (const float*)d_in[9];
    const float* Wrk    = (const float*)d_in[10];
    const float* Wrv    = (const float*)d_in[11];
    const float* Wro    = (const float*)d_in[12];

    float* out_s = (float*)d_out;
    float* out_r = (float*)d_out + T_LEN * DS;

    __nv_bfloat16 *snh, *snl, *rnh, *rnl, *ash, *asl, *arh, *arl;
    __nv_bfloat16 *wsnh, *wsnl, *wrnh, *wrnl, *wsoh, *wsol, *wroh, *wrol;
    float *csn, *crn, *rsp;
    uint32_t *kh, *kl, *vth, *vtl;
    cudaGetSymbolAddress((void**)&snh, g_sn_h);
    cudaGetSymbolAddress((void**)&snl, g_sn_l);
    cudaGetSymbolAddress((void**)&rnh, g_rn_h);
    cudaGetSymbolAddress((void**)&rnl, g_rn_l);
    cudaGetSymbolAddress((void**)&ash, g_as_h);
    cudaGetSymbolAddress((void**)&asl, g_as_l);
    cudaGetSymbolAddress((void**)&arh, g_ar_h);
    cudaGetSymbolAddress((void**)&arl, g_ar_l);
    cudaGetSymbolAddress((void**)&wsnh, g_wsn_h);
    cudaGetSymbolAddress((void**)&wsnl, g_wsn_l);
    cudaGetSymbolAddress((void**)&wrnh, g_wrn_h);
    cudaGetSymbolAddress((void**)&wrnl, g_wrn_l);
    cudaGetSymbolAddress((void**)&wsoh, g_wso_h);
    cudaGetSymbolAddress((void**)&wsol, g_wso_l);
    cudaGetSymbolAddress((void**)&wroh, g_wro_h);
    cudaGetSymbolAddress((void**)&wrol, g_wro_l);
    cudaGetSymbolAddress((void**)&csn, g_csn);
    cudaGetSymbolAddress((void**)&crn, g_crn);
    cudaGetSymbolAddress((void**)&rsp, g_rsp);
    cudaGetSymbolAddress((void**)&kh, g_kh);
    cudaGetSymbolAddress((void**)&kl, g_kl);
    cudaGetSymbolAddress((void**)&vth, g_vth);
    cudaGetSymbolAddress((void**)&vtl, g_vtl);

    // ---- 1. prep: weight transposes + rmsnorms ----
    prep_kernel<<<4608 + T_LEN + ROWS_R, 256>>>(
        Wsq, Wsk, Wsv, Wso, Wrq, Wrk, Wrv, Wro,
        wsnh, wsnl, wrnh, wrnl, wsoh, wsol, wroh, wrol,
        s, nsw, snh, snl, r, nrw, rnh, rnl);

    // ---- 2. merged projection GEMMs ----
    {
        GArg g0 = {snh, snl, wsnh, wsnl, csn, T_LEN, N_SN, DS, N_SN,
                   nullptr, nullptr, nullptr};
        GArg g1 = {rnh, rnl, wrnh, wrnl, crn, ROWS_R, N_RN, DR, N_RN,
                   nullptr, nullptr, nullptr};
        int gx0 = N_SN / 128, gy0 = T_LEN / 64;
        int gx1 = N_RN / 128, gy1 = ROWS_R / 64;
        gemm_pair<<<gx0 * gy0 + gx1 * gy1, 256>>>(g0, g1, gx0 * gy0, gx0, gx1);
    }

    // ---- 3. conv_kv + s-attention ----
    conv_sattn_kernel<<<T_LEN + 1024 + T_LEN, 256>>>(
        csn, crn, kh, kl, vth, vtl, ash, asl, rsp);

    // ---- 4. causal r attention (8-token tiles, 3-stage pipeline) ----
    cudaFuncSetAttribute(r_attn_mma,
                         cudaFuncAttributeMaxDynamicSharedMemorySize, 98304);
    r_attn_mma<<<dim3(T_LEN / 8, HEADS), 128, 98304>>>(
        crn + 2048, N_RN, kh, kl, vth, vtl, arh, arl);

    // ---- 5. merged output GEMMs ----
    {
        GArg g0 = {ash, asl, wsoh, wsol, out_s, T_LEN, DS, DS, DS,
                   s, rsp, gate_v};
        GArg g1 = {arh, arl, wroh, wrol, out_r, ROWS_R, DR, DR, DR,
                   r, nullptr, nullptr};
        int gx0 = DS / 128, gy0 = T_LEN / 64;
        int gx1 = DR / 128, gy1 = ROWS_R / 64;
        gemm_pair<<<gx0 * gy0 + gx1 * gy1, 256>>>(g0, g1, gx0 * gy0, gx0, gx1);
    }
}

// round 13
// speedup vs baseline: 1.0346x; 1.0098x over previous
#include <cuda_runtime.h>
#include <cuda_bf16.h>
#include <math.h>
#include <stdint.h>

// ---------------- problem constants ----------------
#define T_LEN 1024
#define NSLOT 8
#define DS 1024
#define DR 512
#define HEADS 8
#define DHS 128
#define DHR 64
#define TOPK 4
#define ROWS_R (T_LEN * NSLOT)   // 8192
#define SCALE_S 0.08838834764831845f  // 1/sqrt(128)
#define SCALE_R 0.125f                // 1/sqrt(64)
#define EPS 1e-6f

// fused layouts
#define N_SN 2048        // q(1024) | kr(512) | vr(512), K=1024
#define N_RN 2560        // k(1024) | v(1024) | qr(512), K=512

// ---------------- scratch (static device memory; no allocation) -------------
__device__ __nv_bfloat16 g_sn_h[T_LEN * DS], g_sn_l[T_LEN * DS];
__device__ __nv_bfloat16 g_rn_h[ROWS_R * DR], g_rn_l[ROWS_R * DR];
__device__ __nv_bfloat16 g_as_h[T_LEN * DS], g_as_l[T_LEN * DS];
__device__ __nv_bfloat16 g_ar_h[ROWS_R * DR], g_ar_l[ROWS_R * DR];
__device__ __nv_bfloat16 g_wsn_h[N_SN * DS], g_wsn_l[N_SN * DS];
__device__ __nv_bfloat16 g_wrn_h[N_RN * DR], g_wrn_l[N_RN * DR];
__device__ __nv_bfloat16 g_wso_h[DS * DS], g_wso_l[DS * DS];
__device__ __nv_bfloat16 g_wro_h[DR * DR], g_wro_l[DR * DR];
__device__ float g_csn[T_LEN * N_SN];     // q | kr | vr
__device__ float g_crn[ROWS_R * N_RN];    // k | v | qr
__device__ float g_rsp[T_LEN * DS];
__device__ uint32_t g_kh[T_LEN * 256], g_kl[T_LEN * 256];
__device__ uint32_t g_vth[HEADS * DHR * (T_LEN / 2)];
__device__ uint32_t g_vtl[HEADS * DHR * (T_LEN / 2)];

// ---------------- PTX helpers ----------------
__device__ __forceinline__ uint32_t smem_u32(const void* p) {
    uint32_t a;
    asm("{ .reg .u64 t; cvta.to.shared.u64 t, %1; cvt.u32.u64 %0, t; }"
        : "=r"(a) : "l"(p));
    return a;
}
__device__ __forceinline__ void cp16(uint32_t dst, const void* src) {
    asm volatile("cp.async.cg.shared.global [%0], [%1], 16;"
                 :: "r"(dst), "l"(src) : "memory");
}
__device__ __forceinline__ void ldm_x4(uint32_t* r, uint32_t addr) {
    asm volatile("ldmatrix.sync.aligned.m8n8.x4.shared.b16 {%0,%1,%2,%3}, [%4];"
                 : "=r"(r[0]), "=r"(r[1]), "=r"(r[2]), "=r"(r[3]) : "r"(addr));
}
__device__ __forceinline__ void mma_bf16(
    float* c, const uint32_t* a, uint32_t b0, uint32_t b1)
{
    asm volatile(
        "mma.sync.aligned.m16n8k16.row.col.f32.bf16.bf16.f32 "
        "{%0,%1,%2,%3}, {%4,%5,%6,%7}, {%8,%9}, {%0,%1,%2,%3};"
        : "+f"(c[0]), "+f"(c[1]), "+f"(c[2]), "+f"(c[3])
        : "r"(a[0]), "r"(a[1]), "r"(a[2]), "r"(a[3]), "r"(b0), "r"(b1));
}
__device__ __forceinline__ void split2(float x, float y,
                                       uint32_t& hi, uint32_t& lo)
{
    __nv_bfloat162 h = __floats2bfloat162_rn(x, y);
    float xr = x - __bfloat162float(h.x);
    float yr = y - __bfloat162float(h.y);
    __nv_bfloat162 l = __floats2bfloat162_rn(xr, yr);
    hi = *(uint32_t*)&h;
    lo = *(uint32_t*)&l;
}

// ---------------- merged prep: 8 weight transposes + 2 rmsnorms -------------
__global__ __launch_bounds__(256) void prep_kernel(
    const float* __restrict__ Wsq, const float* __restrict__ Wsk,
    const float* __restrict__ Wsv, const float* __restrict__ Wso,
    const float* __restrict__ Wrq, const float* __restrict__ Wrk,
    const float* __restrict__ Wrv, const float* __restrict__ Wro,
    __nv_bfloat16* __restrict__ wsnh, __nv_bfloat16* __restrict__ wsnl,
    __nv_bfloat16* __restrict__ wrnh, __nv_bfloat16* __restrict__ wrnl,
    __nv_bfloat16* __restrict__ wsoh, __nv_bfloat16* __restrict__ wsol,
    __nv_bfloat16* __restrict__ wroh, __nv_bfloat16* __restrict__ wrol,
    const float* __restrict__ s, const float* __restrict__ nsw,
    __nv_bfloat16* __restrict__ snh, __nv_bfloat16* __restrict__ snl,
    const float* __restrict__ r, const float* __restrict__ nrw,
    __nv_bfloat16* __restrict__ rnh, __nv_bfloat16* __restrict__ rnl)
{
    int b = blockIdx.x;
    if (b < 4608) {
        const float* W;
        __nv_bfloat16 *th, *tl;
        int K, N;
        if (b < 1024)      { W = Wsq; th = wsnh; tl = wsnl; K = 1024; N = 1024; }
        else if (b < 1536) { b -= 1024; W = Wrk; th = wsnh + 1024 * 1024;
                             tl = wsnl + 1024 * 1024; K = 1024; N = 512; }
        else if (b < 2048) { b -= 1536; W = Wrv; th = wsnh + 1536 * 1024;
                             tl = wsnl + 1536 * 1024; K = 1024; N = 512; }
        else if (b < 2560) { b -= 2048; W = Wsk; th = wrnh; tl = wrnl;
                             K = 512; N = 1024; }
        else if (b < 3072) { b -= 2560; W = Wsv; th = wrnh + 1024 * 512;
                             tl = wrnl + 1024 * 512; K = 512; N = 1024; }
        else if (b < 3328) { b -= 3072; W = Wrq; th = wrnh + 2048 * 512;
                             tl = wrnl + 2048 * 512; K = 512; N = 512; }
        else if (b < 4352) { b -= 3328; W = Wso; th = wsoh; tl = wsol;
                             K = 1024; N = 1024; }
        else               { b -= 4352; W = Wro; th = wroh; tl = wrol;
                             K = 512; N = 512; }

        int ntx = N >> 5;
        int bx = (b % ntx) * 32;
        int by = (b / ntx) * 32;

        __shared__ float t[32][33];
        int tx = threadIdx.x & 31, ty = threadIdx.x >> 5;
        #pragma unroll
        for (int i = 0; i < 4; i++)
            t[ty + i * 8][tx] = W[(size_t)(by + ty + i * 8) * N + bx + tx];
        __syncthreads();
        #pragma unroll
        for (int i = 0; i < 4; i++) {
            int n = bx + ty + i * 8;
            int k = by + tx;
            float v = t[tx][ty + i * 8];
            __nv_bfloat16 h = __float2bfloat16(v);
            th[(size_t)n * K + k] = h;
            tl[(size_t)n * K + k] = __float2bfloat16(v - __bfloat162float(h));
        }
        return;
    }
    const float *x, *w;
    __nv_bfloat16 *oh, *ol;
    int C, row;
    if (b < 4608 + T_LEN) {
        row = b - 4608; x = s; w = nsw; oh = snh; ol = snl; C = DS;
    } else {
        row = b - 4608 - T_LEN; x = r; w = nrw; oh = rnh; ol = rnl; C = DR;
    }
    const float* xr = x + (size_t)row * C;
    float acc = 0.f;
    for (int j = threadIdx.x; j < C; j += 256) {
        float v = xr[j];
        acc += v * v;
    }
    __shared__ float red[8];
    int lane = threadIdx.x & 31, warp = threadIdx.x >> 5;
    #pragma unroll
    for (int off = 16; off; off >>= 1) acc += __shfl_xor_sync(0xffffffffu, acc, off);
    if (lane == 0) red[warp] = acc;
    __syncthreads();
    __shared__ float scale;
    if (threadIdx.x == 0) {
        float tot = 0.f;
        #pragma unroll
        for (int i = 0; i < 8; i++) tot += red[i];
        scale = rsqrtf(tot / (float)C + EPS);
    }
    __syncthreads();
    float sc = scale;
    uint32_t* ph = (uint32_t*)(oh + (size_t)row * C);
    uint32_t* pl = (uint32_t*)(ol + (size_t)row * C);
    for (int j2 = threadIdx.x; j2 < C / 2; j2 += 256) {
        float v0 = xr[2 * j2] * sc * w[2 * j2];
        float v1 = xr[2 * j2 + 1] * sc * w[2 * j2 + 1];
        uint32_t h, l;
        split2(v0, v1, h, l);
        ph[j2] = h;
        pl[j2] = l;
    }
}

// ---------------- bf16-split mma GEMM body (64x128 tile) --------------------
struct GArg {
    const __nv_bfloat16 *Ah, *Al, *Bh, *Bl;
    float* C;
    int M, N, K, ldc;
    const float *add1, *add2, *rowscale;
};

__device__ __forceinline__ void gemm_body(
    const GArg g, int bx, int by,
    uint32_t bAh, uint32_t bAl, uint32_t bBh, uint32_t bBl)
{
    int tid = threadIdx.x;
    int lane = tid & 31, wid = tid >> 5;
    int wm = wid & 1, wn = wid >> 1;
    int bm = by * 64, bn = bx * 128;
    int gid = lane >> 2, tig = lane & 3;
    int K = g.K;

    float acc[2][4][4];
    #pragma unroll
    for (int i = 0; i < 2; i++)
        #pragma unroll
        for (int j = 0; j < 4; j++)
            #pragma unroll
            for (int l = 0; l < 4; l++) acc[i][j][l] = 0.f;

    uint32_t aoff0, aoff1, boff0, boff1;
    {
        int lrow = lane & 7;
        int rA = wm * 32 + lrow + (lane & 8);
        int cA = (lane & 16) >> 2;
        aoff0 = (uint32_t)(rA * 8 + cA) * 4;
        aoff1 = (uint32_t)((rA + 16) * 8 + cA) * 4;
        int rB = wn * 32 + lrow + ((lane & 16) >> 1);
        int cB = (lane & 8) >> 1;
        boff0 = (uint32_t)(rB * 8 + cB) * 4;
        boff1 = (uint32_t)((rB + 16) * 8 + cB) * 4;
    }

    int row = tid >> 1;
    int gg = tid & 1;
    const __nv_bfloat16 *Ah = g.Ah, *Al = g.Al, *Bh = g.Bh, *Bl = g.Bl;
    auto issue = [&](int st, int k0) {
        uint32_t bdoff = (uint32_t)(st * 128 * 8 + row * 8 + gg * 4) * 4;
        size_t bsrc = (size_t)(bn + row) * K + k0 + gg * 8;
        cp16(bBh + bdoff, Bh + bsrc);
        cp16(bBl + bdoff, Bl + bsrc);
        if (tid < 128) {
            uint32_t adoff = (uint32_t)(st * 64 * 8 + row * 8 + gg * 4) * 4;
            size_t asrc = (size_t)(bm + row) * K + k0 + gg * 8;
            cp16(bAh + adoff, Ah + asrc);
            cp16(bAl + adoff, Al + asrc);
        }
        asm volatile("cp.async.commit_group;" ::: "memory");
    };

    int nch = K >> 4;
    issue(0, 0);
    if (nch > 1) issue(1, 16);

    for (int c = 0; c < nch; c++) {
        if (c + 1 < nch) {
            asm volatile("cp.async.wait_group 1;" ::: "memory");
        } else {
            asm volatile("cp.async.wait_group 0;" ::: "memory");
        }
        __syncthreads();
        if (c + 2 < nch) issue((c + 2) % 3, (c + 2) * 16);

        uint32_t aoffst = (uint32_t)((c % 3) * 64 * 8 * 4);
        uint32_t boffst = (uint32_t)((c % 3) * 128 * 8 * 4);

        uint32_t ah[2][4], al[2][4];
        ldm_x4(ah[0], bAh + aoffst + aoff0);
        ldm_x4(ah[1], bAh + aoffst + aoff1);
        ldm_x4(al[0], bAl + aoffst + aoff0);
        ldm_x4(al[1], bAl + aoffst + aoff1);

        #pragma unroll
        for (int p = 0; p < 2; p++) {
            uint32_t bh[4], bl[4];
            ldm_x4(bh, bBh + boffst + (p ? boff1 : boff0));
            ldm_x4(bl, bBl + boffst + (p ? boff1 : boff0));
            #pragma unroll
            for (int q = 0; q < 2; q++) {
                int nt = p * 2 + q;
                uint32_t b0h = bh[2 * q], b1h = bh[2 * q + 1];
                uint32_t b0l = bl[2 * q], b1l = bl[2 * q + 1];
                mma_bf16(acc[0][nt], ah[0], b0h, b1h);
                mma_bf16(acc[0][nt], ah[0], b0l, b1l);
                mma_bf16(acc[0][nt], al[0], b0h, b1h);
                mma_bf16(acc[1][nt], ah[1], b0h, b1h);
                mma_bf16(acc[1][nt], ah[1], b0l, b1l);
                mma_bf16(acc[1][nt], al[1], b0h, b1h);
            }
        }
    }

    #pragma unroll
    for (int mt = 0; mt < 2; mt++) {
        int r0 = bm + wm * 32 + mt * 16 + gid;
        float rs0 = (g.rowscale != nullptr) ? g.rowscale[r0] : 0.f;
        float rs8 = (g.rowscale != nullptr) ? g.rowscale[r0 + 8] : 0.f;
        #pragma unroll
        for (int nt = 0; nt < 4; nt++) {
            int col = bn + wn * 32 + nt * 8 + 2 * tig;
            size_t o0 = (size_t)r0 * g.ldc + col;
            size_t o8 = (size_t)(r0 + 8) * g.ldc + col;
            float2 v0 = make_float2(acc[mt][nt][0], acc[mt][nt][1]);
            float2 v8 = make_float2(acc[mt][nt][2], acc[mt][nt][3]);
            if (g.add1) {
                float2 x = *(const float2*)(g.add1 + o0);
                v0.x += x.x; v0.y += x.y;
                x = *(const float2*)(g.add1 + o8);
                v8.x += x.x; v8.y += x.y;
            }
            if (g.add2) {
                float2 x = *(const float2*)(g.add2 + o0);
                v0.x += rs0 * x.x; v0.y += rs0 * x.y;
                x = *(const float2*)(g.add2 + o8);
                v8.x += rs8 * x.x; v8.y += rs8 * x.y;
            }
            *(float2*)(g.C + o0) = v0;
            *(float2*)(g.C + o8) = v8;
        }
    }
}

__global__ __launch_bounds__(256, 3) void gemm_pair(
    GArg g0, GArg g1, int nblk0, int gx0, int gx1)
{
    __shared__ __align__(16) uint32_t sAh[3][64 * 8], sAl[3][64 * 8];
    __shared__ __align__(16) uint32_t sBh[3][128 * 8], sBl[3][128 * 8];
    uint32_t bAh = smem_u32(sAh), bAl = smem_u32(sAl);
    uint32_t bBh = smem_u32(sBh), bBl = smem_u32(sBl);

    int b = blockIdx.x;
    if (b < nblk0)
        gemm_body(g0, b % gx0, b / gx0, bAh, bAl, bBh, bBl);
    else {
        b -= nblk0;
        gemm_body(g1, b % gx1, b / gx1, bAh, bAl, bBh, bBl);
    }
}

// ---------------- merged conv_kv + s-attention ----------------
__global__ __launch_bounds__(256) void conv_sattn_kernel(
    const float* __restrict__ csn,
    const float* __restrict__ crn,
    uint32_t* __restrict__ kh, uint32_t* __restrict__ kl,
    uint32_t* __restrict__ vh, uint32_t* __restrict__ vl,
    __nv_bfloat16* __restrict__ as_h, __nv_bfloat16* __restrict__ as_l,
    float* __restrict__ rsp)
{
    int b = blockIdx.x;
    if (b < T_LEN) {
        int t = b, j = threadIdx.x;
        float2 v = *(const float2*)(csn + (size_t)t * N_SN + 1024 + 2 * j);
        uint32_t h, l;
        split2(v.x, v.y, h, l);
        kh[(size_t)t * 256 + j] = h;
        kl[(size_t)t * 256 + j] = l;
        return;
    }
    if (b < T_LEN + 1024) {
        int idx = (b - T_LEN) * 256 + threadIdx.x;
        int pp = idx & 511;
        int d = (idx >> 9) & 63;
        int h = idx >> 15;
        float v0 = csn[(size_t)(2 * pp) * N_SN + 1536 + h * DHR + d];
        float v1 = csn[(size_t)(2 * pp + 1) * N_SN + 1536 + h * DHR + d];
        uint32_t hh, ll;
        split2(v0, v1, hh, ll);
        vh[idx] = hh;
        vl[idx] = ll;
        return;
    }
    int t = b - T_LEN - 1024;
    int tid = threadIdx.x;
    int warp = tid >> 5, lane = tid & 31;

    __shared__ float qs[DS];
    __shared__ float logits[HEADS][NSLOT];
    __shared__ float wattn[HEADS][NSLOT];
    __shared__ float wsp[NSLOT];

    for (int j = tid; j < DS; j += 256) qs[j] = csn[(size_t)t * N_SN + j];
    __syncthreads();

    {
        int h = warp;
        #pragma unroll
        for (int n = 0; n < NSLOT; n++) {
            const float* krow = crn + (size_t)(t * NSLOT + n) * N_RN + h * DHS;
            const float* qrow = qs + h * DHS;
            float p = 0.f;
            #pragma unroll
            for (int d = lane; d < DHS; d += 32) p += qrow[d] * krow[d];
            #pragma unroll
            for (int off = 16; off; off >>= 1) p += __shfl_xor_sync(0xffffffffu, p, off);
            if (lane == 0) logits[h][n] = p;
        }
    }
    __syncthreads();

    if (tid < HEADS) {
        int h = tid;
        float m = -INFINITY;
        #pragma unroll
        for (int n = 0; n < NSLOT; n++) m = fmaxf(m, logits[h][n] * SCALE_S);
        float sum = 0.f;
        #pragma unroll
        for (int n = 0; n < NSLOT; n++) {
            float e = __expf(logits[h][n] * SCALE_S - m);
            wattn[h][n] = e;
            sum += e;
        }
        float inv = 1.f / sum;
        #pragma unroll
        for (int n = 0; n < NSLOT; n++) wattn[h][n] *= inv;
    }
    if (tid == 8) {
        float sp[NSLOT];
        #pragma unroll
        for (int n = 0; n < NSLOT; n++) {
            float a = 0.f;
            #pragma unroll
            for (int h = 0; h < HEADS; h++) a += logits[h][n];
            sp[n] = a * SCALE_S;
        }
        bool sel[NSLOT];
        #pragma unroll
        for (int n = 0; n < NSLOT; n++) { sel[n] = false; wsp[n] = 0.f; }
        int idxs[TOPK];
        #pragma unroll
        for (int kk = 0; kk < TOPK; kk++) {
            int best = -1; float bv = -INFINITY;
            #pragma unroll
            for (int n = 0; n < NSLOT; n++)
                if (!sel[n] && sp[n] > bv) { bv = sp[n]; best = n; }
            sel[best] = true; idxs[kk] = best;
        }
        float m = -INFINITY;
        #pragma unroll
        for (int kk = 0; kk < TOPK; kk++) m = fmaxf(m, sp[idxs[kk]]);
        float sum = 0.f, e[TOPK];
        #pragma unroll
        for (int kk = 0; kk < TOPK; kk++) { e[kk] = __expf(sp[idxs[kk]] - m); sum += e[kk]; }
        float inv = 1.f / sum;
        #pragma unroll
        for (int kk = 0; kk < TOPK; kk++) wsp[idxs[kk]] = e[kk] * inv;
    }
    __syncthreads();

    uint32_t* ph = (uint32_t*)(as_h + (size_t)t * DS);
    uint32_t* pl = (uint32_t*)(as_l + (size_t)t * DS);
    for (int j2 = tid; j2 < DS / 2; j2 += 256) {
        int j = 2 * j2;
        int h = j >> 7;
        float a0 = 0.f, a1 = 0.f, b0 = 0.f, b1 = 0.f;
        #pragma unroll
        for (int n = 0; n < NSLOT; n++) {
            float2 vv = *(const float2*)(crn + (size_t)(t * NSLOT + n) * N_RN + 1024 + j);
            a0 += wattn[h][n] * vv.x;
            a1 += wattn[h][n] * vv.y;
            b0 += wsp[n] * vv.x;
            b1 += wsp[n] * vv.y;
        }
        uint32_t hh, ll;
        split2(a0, a1, hh, ll);
        ph[j2] = hh;
        pl[j2] = ll;
        *(float2*)(rsp + (size_t)t * DS + j) = make_float2(b0, b1);
    }
}

// ---------------- causal r-attention: MMA flash, ldmatrix fragments, --------
// 2-stage cp.async pipeline in 64KB dynamic smem -> 3 CTAs/SM.
__global__ __launch_bounds__(128, 3) void r_attn_mma(
    const float* __restrict__ qr, int qld,
    const uint32_t* __restrict__ kh_g, const uint32_t* __restrict__ kl_g,
    const uint32_t* __restrict__ vh_g, const uint32_t* __restrict__ vl_g,
    __nv_bfloat16* __restrict__ ar_h, __nv_bfloat16* __restrict__ ar_l)
{
    extern __shared__ __align__(16) uint32_t dsm[];
    // layout: [kh 2x2048][kl 2x2048][vh 2x2048][vl 2x2048] u32
    uint32_t bkh = smem_u32(dsm);
    uint32_t bkl = bkh + 16384;
    uint32_t bvh = bkh + 32768;
    uint32_t bvl = bkh + 49152;

    int tt = (int)(gridDim.x - 1 - blockIdx.x);  // long blocks first
    int h = blockIdx.y;
    int t0 = tt * 8;
    int hb = h * DHR;

    int tid = threadIdx.x;
    int w = tid >> 5, lane = tid & 31;
    int gid = lane >> 2, tig = lane & 3;

    // ---- Q fragments (scaled), split once ----
    int r0 = t0 * 8 + 16 * w + gid;
    int r8 = r0 + 8;
    uint32_t qh[4][4], ql[4][4];
    #pragma unroll
    for (int kc = 0; kc < 4; kc++) {
        float2 x0 = *(const float2*)(qr + (size_t)r0 * qld + hb + kc * 16 + 2 * tig);
        float2 x1 = *(const float2*)(qr + (size_t)r8 * qld + hb + kc * 16 + 2 * tig);
        float2 x2 = *(const float2*)(qr + (size_t)r0 * qld + hb + kc * 16 + 2 * tig + 8);
        float2 x3 = *(const float2*)(qr + (size_t)r8 * qld + hb + kc * 16 + 2 * tig + 8);
        split2(x0.x * SCALE_R, x0.y * SCALE_R, qh[kc][0], ql[kc][0]);
        split2(x1.x * SCALE_R, x1.y * SCALE_R, qh[kc][1], ql[kc][1]);
        split2(x2.x * SCALE_R, x2.y * SCALE_R, qh[kc][2], ql[kc][2]);
        split2(x3.x * SCALE_R, x3.y * SCALE_R, qh[kc][3], ql[kc][3]);
    }
    int tok0 = t0 + ((16 * w + gid) >> 3);
    int tok8 = t0 + ((16 * w + gid + 8) >> 3);

    // ---- ldmatrix per-lane row geometry (shared by K and V tiles) ----
    // matrix m = lane>>3: m0/m1 = rows nr..nr+7, granules (2kc, 2kc+1);
    // m2/m3 = rows nr+8..: via (lane&16)>>1. gsel = (lane&8)>>3.
    uint32_t rowoff[4];
    uint32_t swr[4];
    {
        int mrow = ((lane & 16) >> 1) + (lane & 7);   // 0..15
        int gsel = (lane & 8) >> 3;
        #pragma unroll
        for (int p = 0; p < 4; p++) {
            int nr = p * 16 + mrow;
            rowoff[p] = (uint32_t)(nr * 128);
            swr[p] = (uint32_t)(nr & 7);
            (void)gsel;
        }
    }
    int gsel = (lane & 8) >> 3;

    float m0 = -INFINITY, m1 = -INFINITY, l0 = 0.f, l1 = 0.f;
    float acco[8][4];
    #pragma unroll
    for (int i = 0; i < 8; i++)
        #pragma unroll
        for (int j = 0; j < 4; j++) acco[i][j] = 0.f;

    int ntiles = ((t0 + 7) >> 6) + 1;

    auto issueT = [&](int st, int p0) {
        int pp0 = p0 >> 1;
        #pragma unroll
        for (int it = 0; it < 4; it++) {
            int idx = tid + it * 128;            // 0..511
            int p = idx >> 3, g = idx & 7;
            uint32_t doff = (uint32_t)(st * 8192) +
                            (uint32_t)(p * 32 + ((g ^ (p & 7)) << 2)) * 4;
            size_t ksrc = (size_t)(p0 + p) * 256 + h * 32 + g * 4;
            cp16(bkh + doff, kh_g + ksrc);
            cp16(bkl + doff, kl_g + ksrc);
            size_t vsrc = (size_t)h * 32768 + (size_t)p * 512 + pp0 + g * 4;
            cp16(bvh + doff, vh_g + vsrc);
            cp16(bvl + doff, vl_g + vsrc);
        }
        asm volatile("cp.async.commit_group;" ::: "memory");
    };

    issueT(0, 0);

    for (int c = 0; c < ntiles; c++) {
        int p0 = c * 64;
        if (c + 1 < ntiles) {
            issueT((c + 1) & 1, (c + 1) * 64);   // stage (c+1)&1 last read at c-1
            asm volatile("cp.async.wait_group 1;" ::: "memory");
        } else {
            asm volatile("cp.async.wait_group 0;" ::: "memory");
        }
        __syncthreads();

        uint32_t stB = (uint32_t)((c & 1) * 8192);

        // ---- QK via ldmatrix ----
        float s[8][4];
        #pragma unroll
        for (int i = 0; i < 8; i++)
            #pragma unroll
            for (int j = 0; j < 4; j++) s[i][j] = 0.f;

        #pragma unroll
        for (int p = 0; p < 4; p++) {
            #pragma unroll
            for (int kc = 0; kc < 4; kc++) {
                uint32_t off = stB + rowoff[p] +
                               ((uint32_t)((2 * kc + gsel) ^ swr[p]) << 4);
                uint32_t bh[4], bl[4];
                ldm_x4(bh, bkh + off);
                ldm_x4(bl, bkl + off);
                #pragma unroll
                for (int q = 0; q < 2; q++) {
                    int nt = 2 * p + q;
                    mma_bf16(s[nt], qh[kc], bh[2 * q], bh[2 * q + 1]);
                    mma_bf16(s[nt], qh[kc], bl[2 * q], bl[2 * q + 1]);
                    mma_bf16(s[nt], ql[kc], bh[2 * q], bh[2 * q + 1]);
                }
            }
        }

        // ---- causal mask (diagonal region only) ----
        if (p0 + 64 > t0) {
            #pragma unroll
            for (int nt = 0; nt < 8; nt++) {
                int pg = p0 + nt * 8 + 2 * tig;
                if (pg > tok0)     s[nt][0] = -INFINITY;
                if (pg + 1 > tok0) s[nt][1] = -INFINITY;
                if (pg > tok8)     s[nt][2] = -INFINITY;
                if (pg + 1 > tok8) s[nt][3] = -INFINITY;
            }
        }

        // ---- online softmax ----
        float mx0 = -INFINITY, mx1 = -INFINITY;
        #pragma unroll
        for (int nt = 0; nt < 8; nt++) {
            mx0 = fmaxf(mx0, fmaxf(s[nt][0], s[nt][1]));
            mx1 = fmaxf(mx1, fmaxf(s[nt][2], s[nt][3]));
        }
        mx0 = fmaxf(mx0, __shfl_xor_sync(0xffffffffu, mx0, 1));
        mx0 = fmaxf(mx0, __shfl_xor_sync(0xffffffffu, mx0, 2));
        mx1 = fmaxf(mx1, __shfl_xor_sync(0xffffffffu, mx1, 1));
        mx1 = fmaxf(mx1, __shfl_xor_sync(0xffffffffu, mx1, 2));
        float nm0 = fmaxf(m0, mx0), nm1 = fmaxf(m1, mx1);
        float cr0 = __expf(m0 - nm0), cr1 = __expf(m1 - nm1);
        m0 = nm0; m1 = nm1;

        float rs0 = 0.f, rs1 = 0.f;
        #pragma unroll
        for (int nt = 0; nt < 8; nt++) {
            s[nt][0] = __expf(s[nt][0] - nm0);
            s[nt][1] = __expf(s[nt][1] - nm0);
            s[nt][2] = __expf(s[nt][2] - nm1);
            s[nt][3] = __expf(s[nt][3] - nm1);
            rs0 += s[nt][0] + s[nt][1];
            rs1 += s[nt][2] + s[nt][3];
        }
        rs0 += __shfl_xor_sync(0xffffffffu, rs0, 1);
        rs0 += __shfl_xor_sync(0xffffffffu, rs0, 2);
        rs1 += __shfl_xor_sync(0xffffffffu, rs1, 1);
        rs1 += __shfl_xor_sync(0xffffffffu, rs1, 2);
        l0 = l0 * cr0 + rs0;
        l1 = l1 * cr1 + rs1;

        #pragma unroll
        for (int ntd = 0; ntd < 8; ntd++) {
            acco[ntd][0] *= cr0; acco[ntd][1] *= cr0;
            acco[ntd][2] *= cr1; acco[ntd][3] *= cr1;
        }

        // ---- PV via ldmatrix ----
        #pragma unroll
        for (int kc = 0; kc < 4; kc++) {
            uint32_t pah[4], pal[4];
            split2(s[2 * kc][0],     s[2 * kc][1],     pah[0], pal[0]);
            split2(s[2 * kc][2],     s[2 * kc][3],     pah[1], pal[1]);
            split2(s[2 * kc + 1][0], s[2 * kc + 1][1], pah[2], pal[2]);
            split2(s[2 * kc + 1][2], s[2 * kc + 1][3], pah[3], pal[3]);
            #pragma unroll
            for (int p = 0; p < 4; p++) {
                uint32_t off = stB + rowoff[p] +
                               ((uint32_t)((2 * kc + gsel) ^ swr[p]) << 4);
                uint32_t bh[4], bl[4];
                ldm_x4(bh, bvh + off);
                ldm_x4(bl, bvl + off);
                #pragma unroll
                for (int q = 0; q < 2; q++) {
                    int ntd = 2 * p + q;
                    mma_bf16(acco[ntd], pah, bh[2 * q], bh[2 * q + 1]);
                    mma_bf16(acco[ntd], pah, bl[2 * q], bl[2 * q + 1]);
                    mma_bf16(acco[ntd], pal, bh[2 * q], bh[2 * q + 1]);
                }
            }
        }

        if (c + 1 < ntiles) __syncthreads();   // protect stage c&1 before reuse
    }

    float i0 = 1.f / l0, i1 = 1.f / l1;
    #pragma unroll
    for (int ntd = 0; ntd < 8; ntd++) {
        int col = hb + ntd * 8 + 2 * tig;
        uint32_t hh, ll;
        split2(acco[ntd][0] * i0, acco[ntd][1] * i0, hh, ll);
        *(uint32_t*)(ar_h + (size_t)r0 * DR + col) = hh;
        *(uint32_t*)(ar_l + (size_t)r0 * DR + col) = ll;
        split2(acco[ntd][2] * i1, acco[ntd][3] * i1, hh, ll);
        *(uint32_t*)(ar_h + (size_t)r8 * DR + col) = hh;
        *(uint32_t*)(ar_l + (size_t)r8 * DR + col) = ll;
    }
}

// ---------------- host launch ----------------
extern "C" void kernel_launch(void* const* d_in, const int* in_sizes, int n_in,
                              void* d_out, int out_size)
{
    const float* s      = (const float*)d_in[0];
    const float* r      = (const float*)d_in[1];
    const float* gate_v = (const float*)d_in[2];
    const float* nsw    = (const float*)d_in[3];
    const float* nrw    = (const float*)d_in[4];
    const float* Wsq    = (const float*)d_in[5];
    const float* Wsk    = (const float*)d_in[6];
    const float* Wsv    = (const float*)d_in[7];
    const float* Wso    = (const float*)d_in[8];
    const float* Wrq    = (const float*)d_in[9];
    const float* Wrk    = (const float*)d_in[10];
    const float* Wrv    = (const float*)d_in[11];
    const float* Wro    = (const float*)d_in[12];

    float* out_s = (float*)d_out;
    float* out_r = (float*)d_out + T_LEN * DS;

    __nv_bfloat16 *snh, *snl, *rnh, *rnl, *ash, *asl, *arh, *arl;
    __nv_bfloat16 *wsnh, *wsnl, *wrnh, *wrnl, *wsoh, *wsol, *wroh, *wrol;
    float *csn, *crn, *rsp;
    uint32_t *kh, *kl, *vth, *vtl;
    cudaGetSymbolAddress((void**)&snh, g_sn_h);
    cudaGetSymbolAddress((void**)&snl, g_sn_l);
    cudaGetSymbolAddress((void**)&rnh, g_rn_h);
    cudaGetSymbolAddress((void**)&rnl, g_rn_l);
    cudaGetSymbolAddress((void**)&ash, g_as_h);
    cudaGetSymbolAddress((void**)&asl, g_as_l);
    cudaGetSymbolAddress((void**)&arh, g_ar_h);
    cudaGetSymbolAddress((void**)&arl, g_ar_l);
    cudaGetSymbolAddress((void**)&wsnh, g_wsn_h);
    cudaGetSymbolAddress((void**)&wsnl, g_wsn_l);
    cudaGetSymbolAddress((void**)&wrnh, g_wrn_h);
    cudaGetSymbolAddress((void**)&wrnl, g_wrn_l);
    cudaGetSymbolAddress((void**)&wsoh, g_wso_h);
    cudaGetSymbolAddress((void**)&wsol, g_wso_l);
    cudaGetSymbolAddress((void**)&wroh, g_wro_h);
    cudaGetSymbolAddress((void**)&wrol, g_wro_l);
    cudaGetSymbolAddress((void**)&csn, g_csn);
    cudaGetSymbolAddress((void**)&crn, g_crn);
    cudaGetSymbolAddress((void**)&rsp, g_rsp);
    cudaGetSymbolAddress((void**)&kh, g_kh);
    cudaGetSymbolAddress((void**)&kl, g_kl);
    cudaGetSymbolAddress((void**)&vth, g_vth);
    cudaGetSymbolAddress((void**)&vtl, g_vtl);

    // ---- 1. prep: weight transposes + rmsnorms ----
    prep_kernel<<<4608 + T_LEN + ROWS_R, 256>>>(
        Wsq, Wsk, Wsv, Wso, Wrq, Wrk, Wrv, Wro,
        wsnh, wsnl, wrnh, wrnl, wsoh, wsol, wroh, wrol,
        s, nsw, snh, snl, r, nrw, rnh, rnl);

    // ---- 2. merged projection GEMMs ----
    {
        GArg g0 = {snh, snl, wsnh, wsnl, csn, T_LEN, N_SN, DS, N_SN,
                   nullptr, nullptr, nullptr};
        GArg g1 = {rnh, rnl, wrnh, wrnl, crn, ROWS_R, N_RN, DR, N_RN,
                   nullptr, nullptr, nullptr};
        int gx0 = N_SN / 128, gy0 = T_LEN / 64;
        int gx1 = N_RN / 128, gy1 = ROWS_R / 64;
        gemm_pair<<<gx0 * gy0 + gx1 * gy1, 256>>>(g0, g1, gx0 * gy0, gx0, gx1);
    }

    // ---- 3. conv_kv + s-attention ----
    conv_sattn_kernel<<<T_LEN + 1024 + T_LEN, 256>>>(
        csn, crn, kh, kl, vth, vtl, ash, asl, rsp);

    // ---- 4. causal r attention (ldmatrix, 2-stage, 3 CTAs/SM) ----
    cudaFuncSetAttribute(r_attn_mma,
                         cudaFuncAttributeMaxDynamicSharedMemorySize, 65536);
    r_attn_mma<<<dim3(T_LEN / 8, HEADS), 128, 65536>>>(
        crn + 2048, N_RN, kh, kl, vth, vtl, arh, arl);

    // ---- 5. merged output GEMMs ----
    {
        GArg g0 = {ash, asl, wsoh, wsol, out_s, T_LEN, DS, DS, DS,
                   s, rsp, gate_v};
        GArg g1 = {arh, arl, wroh, wrol, out_r, ROWS_R, DR, DR, DR,
                   r, nullptr, nullptr};
        int gx0 = DS / 128, gy0 = T_LEN / 64;
        int gx1 = DR / 128, gy1 = ROWS_R / 64;
        gemm_pair<<<gx0 * gy0 + gx1 * gy1, 256>>>(g0, g1, gx0 * gy0, gx0, gx1);
    }
}

// round 14
// speedup vs baseline: 1.0552x; 1.0199x over previous
#include <cuda_runtime.h>
#include <cuda_bf16.h>
#include <math.h>
#include <stdint.h>

// ---------------- problem constants ----------------
#define T_LEN 1024
#define NSLOT 8
#define DS 1024
#define DR 512
#define HEADS 8
#define DHS 128
#define DHR 64
#define TOPK 4
#define ROWS_R (T_LEN * NSLOT)   // 8192
#define SCALE_S 0.08838834764831845f  // 1/sqrt(128)
#define SCALE_R 0.125f                // 1/sqrt(64)
#define EPS 1e-6f

// fused layouts
#define N_SN 2048        // q(1024) | kr(512) | vr(512), K=1024
#define N_RN 2560        // k(1024) | v(1024) | qr(512), K=512

// ---------------- scratch (static device memory; no allocation) -------------
__device__ __nv_bfloat16 g_sn_h[T_LEN * DS], g_sn_l[T_LEN * DS];
__device__ __nv_bfloat16 g_rn_h[ROWS_R * DR], g_rn_l[ROWS_R * DR];
__device__ __nv_bfloat16 g_as_h[T_LEN * DS], g_as_l[T_LEN * DS];
__device__ __nv_bfloat16 g_ar_h[ROWS_R * DR], g_ar_l[ROWS_R * DR];
__device__ __nv_bfloat16 g_wsn_h[N_SN * DS], g_wsn_l[N_SN * DS];
__device__ __nv_bfloat16 g_wrn_h[N_RN * DR], g_wrn_l[N_RN * DR];
__device__ __nv_bfloat16 g_wso_h[DS * DS], g_wso_l[DS * DS];
__device__ __nv_bfloat16 g_wro_h[DR * DR], g_wro_l[DR * DR];
__device__ float g_csn[T_LEN * N_SN];     // q | kr | vr
__device__ float g_crn[ROWS_R * N_RN];    // k | v | qr
__device__ float g_rsp[T_LEN * DS];
__device__ uint32_t g_kh[T_LEN * 256], g_kl[T_LEN * 256];
__device__ uint32_t g_vth[HEADS * DHR * (T_LEN / 2)];
__device__ uint32_t g_vtl[HEADS * DHR * (T_LEN / 2)];

// ---------------- PTX helpers ----------------
__device__ __forceinline__ uint32_t smem_u32(const void* p) {
    uint32_t a;
    asm("{ .reg .u64 t; cvta.to.shared.u64 t, %1; cvt.u32.u64 %0, t; }"
        : "=r"(a) : "l"(p));
    return a;
}
__device__ __forceinline__ void cp16(uint32_t dst, const void* src) {
    asm volatile("cp.async.cg.shared.global [%0], [%1], 16;"
                 :: "r"(dst), "l"(src) : "memory");
}
__device__ __forceinline__ void ldm_x4(uint32_t* r, uint32_t addr) {
    asm volatile("ldmatrix.sync.aligned.m8n8.x4.shared.b16 {%0,%1,%2,%3}, [%4];"
                 : "=r"(r[0]), "=r"(r[1]), "=r"(r[2]), "=r"(r[3]) : "r"(addr));
}
__device__ __forceinline__ void mma_bf16(
    float* c, const uint32_t* a, uint32_t b0, uint32_t b1)
{
    asm volatile(
        "mma.sync.aligned.m16n8k16.row.col.f32.bf16.bf16.f32 "
        "{%0,%1,%2,%3}, {%4,%5,%6,%7}, {%8,%9}, {%0,%1,%2,%3};"
        : "+f"(c[0]), "+f"(c[1]), "+f"(c[2]), "+f"(c[3])
        : "r"(a[0]), "r"(a[1]), "r"(a[2]), "r"(a[3]), "r"(b0), "r"(b1));
}
__device__ __forceinline__ void split2(float x, float y,
                                       uint32_t& hi, uint32_t& lo)
{
    __nv_bfloat162 h = __floats2bfloat162_rn(x, y);
    float xr = x - __bfloat162float(h.x);
    float yr = y - __bfloat162float(h.y);
    __nv_bfloat162 l = __floats2bfloat162_rn(xr, yr);
    hi = *(uint32_t*)&h;
    lo = *(uint32_t*)&l;
}

// ---------------- merged prep: 8 weight transposes + 2 rmsnorms -------------
__global__ __launch_bounds__(256) void prep_kernel(
    const float* __restrict__ Wsq, const float* __restrict__ Wsk,
    const float* __restrict__ Wsv, const float* __restrict__ Wso,
    const float* __restrict__ Wrq, const float* __restrict__ Wrk,
    const float* __restrict__ Wrv, const float* __restrict__ Wro,
    __nv_bfloat16* __restrict__ wsnh, __nv_bfloat16* __restrict__ wsnl,
    __nv_bfloat16* __restrict__ wrnh, __nv_bfloat16* __restrict__ wrnl,
    __nv_bfloat16* __restrict__ wsoh, __nv_bfloat16* __restrict__ wsol,
    __nv_bfloat16* __restrict__ wroh, __nv_bfloat16* __restrict__ wrol,
    const float* __restrict__ s, const float* __restrict__ nsw,
    __nv_bfloat16* __restrict__ snh, __nv_bfloat16* __restrict__ snl,
    const float* __restrict__ r, const float* __restrict__ nrw,
    __nv_bfloat16* __restrict__ rnh, __nv_bfloat16* __restrict__ rnl)
{
    int b = blockIdx.x;
    if (b < 4608) {
        const float* W;
        __nv_bfloat16 *th, *tl;
        int K, N;
        if (b < 1024)      { W = Wsq; th = wsnh; tl = wsnl; K = 1024; N = 1024; }
        else if (b < 1536) { b -= 1024; W = Wrk; th = wsnh + 1024 * 1024;
                             tl = wsnl + 1024 * 1024; K = 1024; N = 512; }
        else if (b < 2048) { b -= 1536; W = Wrv; th = wsnh + 1536 * 1024;
                             tl = wsnl + 1536 * 1024; K = 1024; N = 512; }
        else if (b < 2560) { b -= 2048; W = Wsk; th = wrnh; tl = wrnl;
                             K = 512; N = 1024; }
        else if (b < 3072) { b -= 2560; W = Wsv; th = wrnh + 1024 * 512;
                             tl = wrnl + 1024 * 512; K = 512; N = 1024; }
        else if (b < 3328) { b -= 3072; W = Wrq; th = wrnh + 2048 * 512;
                             tl = wrnl + 2048 * 512; K = 512; N = 512; }
        else if (b < 4352) { b -= 3328; W = Wso; th = wsoh; tl = wsol;
                             K = 1024; N = 1024; }
        else               { b -= 4352; W = Wro; th = wroh; tl = wrol;
                             K = 512; N = 512; }

        int ntx = N >> 5;
        int bx = (b % ntx) * 32;
        int by = (b / ntx) * 32;

        __shared__ float t[32][33];
        int tx = threadIdx.x & 31, ty = threadIdx.x >> 5;
        #pragma unroll
        for (int i = 0; i < 4; i++)
            t[ty + i * 8][tx] = W[(size_t)(by + ty + i * 8) * N + bx + tx];
        __syncthreads();
        #pragma unroll
        for (int i = 0; i < 4; i++) {
            int n = bx + ty + i * 8;
            int k = by + tx;
            float v = t[tx][ty + i * 8];
            __nv_bfloat16 h = __float2bfloat16(v);
            th[(size_t)n * K + k] = h;
            tl[(size_t)n * K + k] = __float2bfloat16(v - __bfloat162float(h));
        }
        return;
    }
    const float *x, *w;
    __nv_bfloat16 *oh, *ol;
    int C, row;
    if (b < 4608 + T_LEN) {
        row = b - 4608; x = s; w = nsw; oh = snh; ol = snl; C = DS;
    } else {
        row = b - 4608 - T_LEN; x = r; w = nrw; oh = rnh; ol = rnl; C = DR;
    }
    const float* xr = x + (size_t)row * C;
    float acc = 0.f;
    for (int j = threadIdx.x; j < C; j += 256) {
        float v = xr[j];
        acc += v * v;
    }
    __shared__ float red[8];
    int lane = threadIdx.x & 31, warp = threadIdx.x >> 5;
    #pragma unroll
    for (int off = 16; off; off >>= 1) acc += __shfl_xor_sync(0xffffffffu, acc, off);
    if (lane == 0) red[warp] = acc;
    __syncthreads();
    __shared__ float scale;
    if (threadIdx.x == 0) {
        float tot = 0.f;
        #pragma unroll
        for (int i = 0; i < 8; i++) tot += red[i];
        scale = rsqrtf(tot / (float)C + EPS);
    }
    __syncthreads();
    float sc = scale;
    uint32_t* ph = (uint32_t*)(oh + (size_t)row * C);
    uint32_t* pl = (uint32_t*)(ol + (size_t)row * C);
    for (int j2 = threadIdx.x; j2 < C / 2; j2 += 256) {
        float v0 = xr[2 * j2] * sc * w[2 * j2];
        float v1 = xr[2 * j2 + 1] * sc * w[2 * j2 + 1];
        uint32_t h, l;
        split2(v0, v1, h, l);
        ph[j2] = h;
        pl[j2] = l;
    }
}

// ---------------- bf16-split mma GEMM body (64x128 tile) --------------------
struct GArg {
    const __nv_bfloat16 *Ah, *Al, *Bh, *Bl;
    float* C;
    int M, N, K, ldc;
    const float *add1, *add2, *rowscale;
};

__device__ __forceinline__ void gemm_body(
    const GArg g, int bx, int by,
    uint32_t bAh, uint32_t bAl, uint32_t bBh, uint32_t bBl)
{
    int tid = threadIdx.x;
    int lane = tid & 31, wid = tid >> 5;
    int wm = wid & 1, wn = wid >> 1;
    int bm = by * 64, bn = bx * 128;
    int gid = lane >> 2, tig = lane & 3;
    int K = g.K;

    float acc[2][4][4];
    #pragma unroll
    for (int i = 0; i < 2; i++)
        #pragma unroll
        for (int j = 0; j < 4; j++)
            #pragma unroll
            for (int l = 0; l < 4; l++) acc[i][j][l] = 0.f;

    uint32_t aoff0, aoff1, boff0, boff1;
    {
        int lrow = lane & 7;
        int rA = wm * 32 + lrow + (lane & 8);
        int cA = (lane & 16) >> 2;
        aoff0 = (uint32_t)(rA * 8 + cA) * 4;
        aoff1 = (uint32_t)((rA + 16) * 8 + cA) * 4;
        int rB = wn * 32 + lrow + ((lane & 16) >> 1);
        int cB = (lane & 8) >> 1;
        boff0 = (uint32_t)(rB * 8 + cB) * 4;
        boff1 = (uint32_t)((rB + 16) * 8 + cB) * 4;
    }

    int row = tid >> 1;
    int gg = tid & 1;
    const __nv_bfloat16 *Ah = g.Ah, *Al = g.Al, *Bh = g.Bh, *Bl = g.Bl;
    auto issue = [&](int st, int k0) {
        uint32_t bdoff = (uint32_t)(st * 128 * 8 + row * 8 + gg * 4) * 4;
        size_t bsrc = (size_t)(bn + row) * K + k0 + gg * 8;
        cp16(bBh + bdoff, Bh + bsrc);
        cp16(bBl + bdoff, Bl + bsrc);
        if (tid < 128) {
            uint32_t adoff = (uint32_t)(st * 64 * 8 + row * 8 + gg * 4) * 4;
            size_t asrc = (size_t)(bm + row) * K + k0 + gg * 8;
            cp16(bAh + adoff, Ah + asrc);
            cp16(bAl + adoff, Al + asrc);
        }
        asm volatile("cp.async.commit_group;" ::: "memory");
    };

    int nch = K >> 4;
    issue(0, 0);
    if (nch > 1) issue(1, 16);

    for (int c = 0; c < nch; c++) {
        if (c + 1 < nch) {
            asm volatile("cp.async.wait_group 1;" ::: "memory");
        } else {
            asm volatile("cp.async.wait_group 0;" ::: "memory");
        }
        __syncthreads();
        if (c + 2 < nch) issue((c + 2) % 3, (c + 2) * 16);

        uint32_t aoffst = (uint32_t)((c % 3) * 64 * 8 * 4);
        uint32_t boffst = (uint32_t)((c % 3) * 128 * 8 * 4);

        uint32_t ah[2][4], al[2][4];
        ldm_x4(ah[0], bAh + aoffst + aoff0);
        ldm_x4(ah[1], bAh + aoffst + aoff1);
        ldm_x4(al[0], bAl + aoffst + aoff0);
        ldm_x4(al[1], bAl + aoffst + aoff1);

        #pragma unroll
        for (int p = 0; p < 2; p++) {
            uint32_t bh[4], bl[4];
            ldm_x4(bh, bBh + boffst + (p ? boff1 : boff0));
            ldm_x4(bl, bBl + boffst + (p ? boff1 : boff0));
            #pragma unroll
            for (int q = 0; q < 2; q++) {
                int nt = p * 2 + q;
                uint32_t b0h = bh[2 * q], b1h = bh[2 * q + 1];
                uint32_t b0l = bl[2 * q], b1l = bl[2 * q + 1];
                mma_bf16(acc[0][nt], ah[0], b0h, b1h);
                mma_bf16(acc[0][nt], ah[0], b0l, b1l);
                mma_bf16(acc[0][nt], al[0], b0h, b1h);
                mma_bf16(acc[1][nt], ah[1], b0h, b1h);
                mma_bf16(acc[1][nt], ah[1], b0l, b1l);
                mma_bf16(acc[1][nt], al[1], b0h, b1h);
            }
        }
    }

    #pragma unroll
    for (int mt = 0; mt < 2; mt++) {
        int r0 = bm + wm * 32 + mt * 16 + gid;
        float rs0 = (g.rowscale != nullptr) ? g.rowscale[r0] : 0.f;
        float rs8 = (g.rowscale != nullptr) ? g.rowscale[r0 + 8] : 0.f;
        #pragma unroll
        for (int nt = 0; nt < 4; nt++) {
            int col = bn + wn * 32 + nt * 8 + 2 * tig;
            size_t o0 = (size_t)r0 * g.ldc + col;
            size_t o8 = (size_t)(r0 + 8) * g.ldc + col;
            float2 v0 = make_float2(acc[mt][nt][0], acc[mt][nt][1]);
            float2 v8 = make_float2(acc[mt][nt][2], acc[mt][nt][3]);
            if (g.add1) {
                float2 x = *(const float2*)(g.add1 + o0);
                v0.x += x.x; v0.y += x.y;
                x = *(const float2*)(g.add1 + o8);
                v8.x += x.x; v8.y += x.y;
            }
            if (g.add2) {
                float2 x = *(const float2*)(g.add2 + o0);
                v0.x += rs0 * x.x; v0.y += rs0 * x.y;
                x = *(const float2*)(g.add2 + o8);
                v8.x += rs8 * x.x; v8.y += rs8 * x.y;
            }
            *(float2*)(g.C + o0) = v0;
            *(float2*)(g.C + o8) = v8;
        }
    }
}

__global__ __launch_bounds__(256, 3) void gemm_pair(
    GArg g0, GArg g1, int nblk0, int gx0, int gx1)
{
    __shared__ __align__(16) uint32_t sAh[3][64 * 8], sAl[3][64 * 8];
    __shared__ __align__(16) uint32_t sBh[3][128 * 8], sBl[3][128 * 8];
    uint32_t bAh = smem_u32(sAh), bAl = smem_u32(sAl);
    uint32_t bBh = smem_u32(sBh), bBl = smem_u32(sBl);

    int b = blockIdx.x;
    if (b < nblk0)
        gemm_body(g0, b % gx0, b / gx0, bAh, bAl, bBh, bBl);
    else {
        b -= nblk0;
        gemm_body(g1, b % gx1, b / gx1, bAh, bAl, bBh, bBl);
    }
}

__global__ __launch_bounds__(256, 3) void gemm_one(GArg g, int gx)
{
    __shared__ __align__(16) uint32_t sAh[3][64 * 8], sAl[3][64 * 8];
    __shared__ __align__(16) uint32_t sBh[3][128 * 8], sBl[3][128 * 8];
    gemm_body(g, blockIdx.x % gx, blockIdx.x / gx,
              smem_u32(sAh), smem_u32(sAl), smem_u32(sBh), smem_u32(sBl));
}

// ---------------- conv_kv (standalone) ----------------
__global__ __launch_bounds__(256) void conv_kv_kernel(
    const float* __restrict__ csn,
    uint32_t* __restrict__ kh, uint32_t* __restrict__ kl,
    uint32_t* __restrict__ vh, uint32_t* __restrict__ vl)
{
    int b = blockIdx.x;
    if (b < T_LEN) {
        int t = b, j = threadIdx.x;
        float2 v = *(const float2*)(csn + (size_t)t * N_SN + 1024 + 2 * j);
        uint32_t h, l;
        split2(v.x, v.y, h, l);
        kh[(size_t)t * 256 + j] = h;
        kl[(size_t)t * 256 + j] = l;
    } else {
        int idx = (b - T_LEN) * 256 + threadIdx.x;
        int pp = idx & 511;
        int d = (idx >> 9) & 63;
        int h = idx >> 15;
        float v0 = csn[(size_t)(2 * pp) * N_SN + 1536 + h * DHR + d];
        float v1 = csn[(size_t)(2 * pp + 1) * N_SN + 1536 + h * DHR + d];
        uint32_t hh, ll;
        split2(v0, v1, hh, ll);
        vh[idx] = hh;
        vl[idx] = ll;
    }
}

// ---------------- s-attention + top-k sparse ----------------
__global__ __launch_bounds__(256) void s_attn_kernel(
    const float* __restrict__ csn,
    const float* __restrict__ crn,
    __nv_bfloat16* __restrict__ as_h, __nv_bfloat16* __restrict__ as_l,
    float* __restrict__ rsp)
{
    int t = blockIdx.x;
    int tid = threadIdx.x;
    int warp = tid >> 5, lane = tid & 31;

    __shared__ float qs[DS];
    __shared__ float logits[HEADS][NSLOT];
    __shared__ float wattn[HEADS][NSLOT];
    __shared__ float wsp[NSLOT];

    for (int j = tid; j < DS; j += 256) qs[j] = csn[(size_t)t * N_SN + j];
    __syncthreads();

    {
        int h = warp;
        #pragma unroll
        for (int n = 0; n < NSLOT; n++) {
            const float* krow = crn + (size_t)(t * NSLOT + n) * N_RN + h * DHS;
            const float* qrow = qs + h * DHS;
            float p = 0.f;
            #pragma unroll
            for (int d = lane; d < DHS; d += 32) p += qrow[d] * krow[d];
            #pragma unroll
            for (int off = 16; off; off >>= 1) p += __shfl_xor_sync(0xffffffffu, p, off);
            if (lane == 0) logits[h][n] = p;
        }
    }
    __syncthreads();

    if (tid < HEADS) {
        int h = tid;
        float m = -INFINITY;
        #pragma unroll
        for (int n = 0; n < NSLOT; n++) m = fmaxf(m, logits[h][n] * SCALE_S);
        float sum = 0.f;
        #pragma unroll
        for (int n = 0; n < NSLOT; n++) {
            float e = __expf(logits[h][n] * SCALE_S - m);
            wattn[h][n] = e;
            sum += e;
        }
        float inv = 1.f / sum;
        #pragma unroll
        for (int n = 0; n < NSLOT; n++) wattn[h][n] *= inv;
    }
    if (tid == 8) {
        float sp[NSLOT];
        #pragma unroll
        for (int n = 0; n < NSLOT; n++) {
            float a = 0.f;
            #pragma unroll
            for (int h = 0; h < HEADS; h++) a += logits[h][n];
            sp[n] = a * SCALE_S;
        }
        bool sel[NSLOT];
        #pragma unroll
        for (int n = 0; n < NSLOT; n++) { sel[n] = false; wsp[n] = 0.f; }
        int idxs[TOPK];
        #pragma unroll
        for (int kk = 0; kk < TOPK; kk++) {
            int best = -1; float bv = -INFINITY;
            #pragma unroll
            for (int n = 0; n < NSLOT; n++)
                if (!sel[n] && sp[n] > bv) { bv = sp[n]; best = n; }
            sel[best] = true; idxs[kk] = best;
        }
        float m = -INFINITY;
        #pragma unroll
        for (int kk = 0; kk < TOPK; kk++) m = fmaxf(m, sp[idxs[kk]]);
        float sum = 0.f, e[TOPK];
        #pragma unroll
        for (int kk = 0; kk < TOPK; kk++) { e[kk] = __expf(sp[idxs[kk]] - m); sum += e[kk]; }
        float inv = 1.f / sum;
        #pragma unroll
        for (int kk = 0; kk < TOPK; kk++) wsp[idxs[kk]] = e[kk] * inv;
    }
    __syncthreads();

    uint32_t* ph = (uint32_t*)(as_h + (size_t)t * DS);
    uint32_t* pl = (uint32_t*)(as_l + (size_t)t * DS);
    for (int j2 = tid; j2 < DS / 2; j2 += 256) {
        int j = 2 * j2;
        int h = j >> 7;
        float a0 = 0.f, a1 = 0.f, b0 = 0.f, b1 = 0.f;
        #pragma unroll
        for (int n = 0; n < NSLOT; n++) {
            float2 vv = *(const float2*)(crn + (size_t)(t * NSLOT + n) * N_RN + 1024 + j);
            a0 += wattn[h][n] * vv.x;
            a1 += wattn[h][n] * vv.y;
            b0 += wsp[n] * vv.x;
            b1 += wsp[n] * vv.y;
        }
        uint32_t hh, ll;
        split2(a0, a1, hh, ll);
        ph[j2] = hh;
        pl[j2] = ll;
        *(float2*)(rsp + (size_t)t * DS + j) = make_float2(b0, b1);
    }
}

// ---------------- causal r-attention (identical to R13 best) ----------------
__global__ __launch_bounds__(128, 3) void r_attn_mma(
    const float* __restrict__ qr, int qld,
    const uint32_t* __restrict__ kh_g, const uint32_t* __restrict__ kl_g,
    const uint32_t* __restrict__ vh_g, const uint32_t* __restrict__ vl_g,
    __nv_bfloat16* __restrict__ ar_h, __nv_bfloat16* __restrict__ ar_l)
{
    extern __shared__ __align__(16) uint32_t dsm[];
    uint32_t bkh = smem_u32(dsm);
    uint32_t bkl = bkh + 16384;
    uint32_t bvh = bkh + 32768;
    uint32_t bvl = bkh + 49152;

    int tt = (int)(gridDim.x - 1 - blockIdx.x);
    int h = blockIdx.y;
    int t0 = tt * 8;
    int hb = h * DHR;

    int tid = threadIdx.x;
    int w = tid >> 5, lane = tid & 31;
    int gid = lane >> 2, tig = lane & 3;

    int r0 = t0 * 8 + 16 * w + gid;
    int r8 = r0 + 8;
    uint32_t qh[4][4], ql[4][4];
    #pragma unroll
    for (int kc = 0; kc < 4; kc++) {
        float2 x0 = *(const float2*)(qr + (size_t)r0 * qld + hb + kc * 16 + 2 * tig);
        float2 x1 = *(const float2*)(qr + (size_t)r8 * qld + hb + kc * 16 + 2 * tig);
        float2 x2 = *(const float2*)(qr + (size_t)r0 * qld + hb + kc * 16 + 2 * tig + 8);
        float2 x3 = *(const float2*)(qr + (size_t)r8 * qld + hb + kc * 16 + 2 * tig + 8);
        split2(x0.x * SCALE_R, x0.y * SCALE_R, qh[kc][0], ql[kc][0]);
        split2(x1.x * SCALE_R, x1.y * SCALE_R, qh[kc][1], ql[kc][1]);
        split2(x2.x * SCALE_R, x2.y * SCALE_R, qh[kc][2], ql[kc][2]);
        split2(x3.x * SCALE_R, x3.y * SCALE_R, qh[kc][3], ql[kc][3]);
    }
    int tok0 = t0 + ((16 * w + gid) >> 3);
    int tok8 = t0 + ((16 * w + gid + 8) >> 3);

    uint32_t rowoff[4];
    uint32_t swr[4];
    {
        int mrow = ((lane & 16) >> 1) + (lane & 7);
        #pragma unroll
        for (int p = 0; p < 4; p++) {
            int nr = p * 16 + mrow;
            rowoff[p] = (uint32_t)(nr * 128);
            swr[p] = (uint32_t)(nr & 7);
        }
    }
    int gsel = (lane & 8) >> 3;

    float m0 = -INFINITY, m1 = -INFINITY, l0 = 0.f, l1 = 0.f;
    float acco[8][4];
    #pragma unroll
    for (int i = 0; i < 8; i++)
        #pragma unroll
        for (int j = 0; j < 4; j++) acco[i][j] = 0.f;

    int ntiles = ((t0 + 7) >> 6) + 1;

    auto issueT = [&](int st, int p0) {
        int pp0 = p0 >> 1;
        #pragma unroll
        for (int it = 0; it < 4; it++) {
            int idx = tid + it * 128;
            int p = idx >> 3, g = idx & 7;
            uint32_t doff = (uint32_t)(st * 8192) +
                            (uint32_t)(p * 32 + ((g ^ (p & 7)) << 2)) * 4;
            size_t ksrc = (size_t)(p0 + p) * 256 + h * 32 + g * 4;
            cp16(bkh + doff, kh_g + ksrc);
            cp16(bkl + doff, kl_g + ksrc);
            size_t vsrc = (size_t)h * 32768 + (size_t)p * 512 + pp0 + g * 4;
            cp16(bvh + doff, vh_g + vsrc);
            cp16(bvl + doff, vl_g + vsrc);
        }
        asm volatile("cp.async.commit_group;" ::: "memory");
    };

    issueT(0, 0);

    for (int c = 0; c < ntiles; c++) {
        int p0 = c * 64;
        if (c + 1 < ntiles) {
            issueT((c + 1) & 1, (c + 1) * 64);
            asm volatile("cp.async.wait_group 1;" ::: "memory");
        } else {
            asm volatile("cp.async.wait_group 0;" ::: "memory");
        }
        __syncthreads();

        uint32_t stB = (uint32_t)((c & 1) * 8192);

        float s[8][4];
        #pragma unroll
        for (int i = 0; i < 8; i++)
            #pragma unroll
            for (int j = 0; j < 4; j++) s[i][j] = 0.f;

        #pragma unroll
        for (int p = 0; p < 4; p++) {
            #pragma unroll
            for (int kc = 0; kc < 4; kc++) {
                uint32_t off = stB + rowoff[p] +
                               ((uint32_t)((2 * kc + gsel) ^ swr[p]) << 4);
                uint32_t bh[4], bl[4];
                ldm_x4(bh, bkh + off);
                ldm_x4(bl, bkl + off);
                #pragma unroll
                for (int q = 0; q < 2; q++) {
                    int nt = 2 * p + q;
                    mma_bf16(s[nt], qh[kc], bh[2 * q], bh[2 * q + 1]);
                    mma_bf16(s[nt], qh[kc], bl[2 * q], bl[2 * q + 1]);
                    mma_bf16(s[nt], ql[kc], bh[2 * q], bh[2 * q + 1]);
                }
            }
        }

        if (p0 + 64 > t0) {
            #pragma unroll
            for (int nt = 0; nt < 8; nt++) {
                int pg = p0 + nt * 8 + 2 * tig;
                if (pg > tok0)     s[nt][0] = -INFINITY;
                if (pg + 1 > tok0) s[nt][1] = -INFINITY;
                if (pg > tok8)     s[nt][2] = -INFINITY;
                if (pg + 1 > tok8) s[nt][3] = -INFINITY;
            }
        }

        float mx0 = -INFINITY, mx1 = -INFINITY;
        #pragma unroll
        for (int nt = 0; nt < 8; nt++) {
            mx0 = fmaxf(mx0, fmaxf(s[nt][0], s[nt][1]));
            mx1 = fmaxf(mx1, fmaxf(s[nt][2], s[nt][3]));
        }
        mx0 = fmaxf(mx0, __shfl_xor_sync(0xffffffffu, mx0, 1));
        mx0 = fmaxf(mx0, __shfl_xor_sync(0xffffffffu, mx0, 2));
        mx1 = fmaxf(mx1, __shfl_xor_sync(0xffffffffu, mx1, 1));
        mx1 = fmaxf(mx1, __shfl_xor_sync(0xffffffffu, mx1, 2));
        float nm0 = fmaxf(m0, mx0), nm1 = fmaxf(m1, mx1);
        float cr0 = __expf(m0 - nm0), cr1 = __expf(m1 - nm1);
        m0 = nm0; m1 = nm1;

        float rs0 = 0.f, rs1 = 0.f;
        #pragma unroll
        for (int nt = 0; nt < 8; nt++) {
            s[nt][0] = __expf(s[nt][0] - nm0);
            s[nt][1] = __expf(s[nt][1] - nm0);
            s[nt][2] = __expf(s[nt][2] - nm1);
            s[nt][3] = __expf(s[nt][3] - nm1);
            rs0 += s[nt][0] + s[nt][1];
            rs1 += s[nt][2] + s[nt][3];
        }
        rs0 += __shfl_xor_sync(0xffffffffu, rs0, 1);
        rs0 += __shfl_xor_sync(0xffffffffu, rs0, 2);
        rs1 += __shfl_xor_sync(0xffffffffu, rs1, 1);
        rs1 += __shfl_xor_sync(0xffffffffu, rs1, 2);
        l0 = l0 * cr0 + rs0;
        l1 = l1 * cr1 + rs1;

        #pragma unroll
        for (int ntd = 0; ntd < 8; ntd++) {
            acco[ntd][0] *= cr0; acco[ntd][1] *= cr0;
            acco[ntd][2] *= cr1; acco[ntd][3] *= cr1;
        }

        #pragma unroll
        for (int kc = 0; kc < 4; kc++) {
            uint32_t pah[4], pal[4];
            split2(s[2 * kc][0],     s[2 * kc][1],     pah[0], pal[0]);
            split2(s[2 * kc][2],     s[2 * kc][3],     pah[1], pal[1]);
            split2(s[2 * kc + 1][0], s[2 * kc + 1][1], pah[2], pal[2]);
            split2(s[2 * kc + 1][2], s[2 * kc + 1][3], pah[3], pal[3]);
            #pragma unroll
            for (int p = 0; p < 4; p++) {
                uint32_t off = stB + rowoff[p] +
                               ((uint32_t)((2 * kc + gsel) ^ swr[p]) << 4);
                uint32_t bh[4], bl[4];
                ldm_x4(bh, bvh + off);
                ldm_x4(bl, bvl + off);
                #pragma unroll
                for (int q = 0; q < 2; q++) {
                    int ntd = 2 * p + q;
                    mma_bf16(acco[ntd], pah, bh[2 * q], bh[2 * q + 1]);
                    mma_bf16(acco[ntd], pah, bl[2 * q], bl[2 * q + 1]);
                    mma_bf16(acco[ntd], pal, bh[2 * q], bh[2 * q + 1]);
                }
            }
        }

        if (c + 1 < ntiles) __syncthreads();
    }

    float i0 = 1.f / l0, i1 = 1.f / l1;
    #pragma unroll
    for (int ntd = 0; ntd < 8; ntd++) {
        int col = hb + ntd * 8 + 2 * tig;
        uint32_t hh, ll;
        split2(acco[ntd][0] * i0, acco[ntd][1] * i0, hh, ll);
        *(uint32_t*)(ar_h + (size_t)r0 * DR + col) = hh;
        *(uint32_t*)(ar_l + (size_t)r0 * DR + col) = ll;
        split2(acco[ntd][2] * i1, acco[ntd][3] * i1, hh, ll);
        *(uint32_t*)(ar_h + (size_t)r8 * DR + col) = hh;
        *(uint32_t*)(ar_l + (size_t)r8 * DR + col) = ll;
    }
}

// ---------------- host launch ----------------
extern "C" void kernel_launch(void* const* d_in, const int* in_sizes, int n_in,
                              void* d_out, int out_size)
{
    const float* s      = (const float*)d_in[0];
    const float* r      = (const float*)d_in[1];
    const float* gate_v = (const float*)d_in[2];
    const float* nsw    = (const float*)d_in[3];
    const float* nrw    = (const float*)d_in[4];
    const float* Wsq    = (const float*)d_in[5];
    const float* Wsk    = (const float*)d_in[6];
    const float* Wsv    = (const float*)d_in[7];
    const float* Wso    = (const float*)d_in[8];
    const float* Wrq    = (const float*)d_in[9];
    const float* Wrk    = (const float*)d_in[10];
    const float* Wrv    = (const float*)d_in[11];
    const float* Wro    = (const float*)d_in[12];

    float* out_s = (float*)d_out;
    float* out_r = (float*)d_out + T_LEN * DS;

    __nv_bfloat16 *snh, *snl, *rnh, *rnl, *ash, *asl, *arh, *arl;
    __nv_bfloat16 *wsnh, *wsnl, *wrnh, *wrnl, *wsoh, *wsol, *wroh, *wrol;
    float *csn, *crn, *rsp;
    uint32_t *kh, *kl, *vth, *vtl;
    cudaGetSymbolAddress((void**)&snh, g_sn_h);
    cudaGetSymbolAddress((void**)&snl, g_sn_l);
    cudaGetSymbolAddress((void**)&rnh, g_rn_h);
    cudaGetSymbolAddress((void**)&rnl, g_rn_l);
    cudaGetSymbolAddress((void**)&ash, g_as_h);
    cudaGetSymbolAddress((void**)&asl, g_as_l);
    cudaGetSymbolAddress((void**)&arh, g_ar_h);
    cudaGetSymbolAddress((void**)&arl, g_ar_l);
    cudaGetSymbolAddress((void**)&wsnh, g_wsn_h);
    cudaGetSymbolAddress((void**)&wsnl, g_wsn_l);
    cudaGetSymbolAddress((void**)&wrnh, g_wrn_h);
    cudaGetSymbolAddress((void**)&wrnl, g_wrn_l);
    cudaGetSymbolAddress((void**)&wsoh, g_wso_h);
    cudaGetSymbolAddress((void**)&wsol, g_wso_l);
    cudaGetSymbolAddress((void**)&wroh, g_wro_h);
    cudaGetSymbolAddress((void**)&wrol, g_wro_l);
    cudaGetSymbolAddress((void**)&csn, g_csn);
    cudaGetSymbolAddress((void**)&crn, g_crn);
    cudaGetSymbolAddress((void**)&rsp, g_rsp);
    cudaGetSymbolAddress((void**)&kh, g_kh);
    cudaGetSymbolAddress((void**)&kl, g_kl);
    cudaGetSymbolAddress((void**)&vth, g_vth);
    cudaGetSymbolAddress((void**)&vtl, g_vtl);

    cudaFuncSetAttribute(r_attn_mma,
                         cudaFuncAttributeMaxDynamicSharedMemorySize, 65536);

    cudaStream_t s1;
    cudaStreamCreateWithFlags(&s1, cudaStreamNonBlocking);
    cudaEvent_t e0, e1;
    cudaEventCreateWithFlags(&e0, cudaEventDisableTiming);
    cudaEventCreateWithFlags(&e1, cudaEventDisableTiming);

    // ---- stream 0: prep + projection GEMMs ----
    prep_kernel<<<4608 + T_LEN + ROWS_R, 256>>>(
        Wsq, Wsk, Wsv, Wso, Wrq, Wrk, Wrv, Wro,
        wsnh, wsnl, wrnh, wrnl, wsoh, wsol, wroh, wrol,
        s, nsw, snh, snl, r, nrw, rnh, rnl);
    {
        GArg g0 = {snh, snl, wsnh, wsnl, csn, T_LEN, N_SN, DS, N_SN,
                   nullptr, nullptr, nullptr};
        GArg g1 = {rnh, rnl, wrnh, wrnl, crn, ROWS_R, N_RN, DR, N_RN,
                   nullptr, nullptr, nullptr};
        int gx0 = N_SN / 128, gy0 = T_LEN / 64;
        int gx1 = N_RN / 128, gy1 = ROWS_R / 64;
        gemm_pair<<<gx0 * gy0 + gx1 * gy1, 256>>>(g0, g1, gx0 * gy0, gx0, gx1);
    }

    // ---- fork: chain B (r-branch) on s1 ----
    cudaEventRecord(e0, 0);
    cudaStreamWaitEvent(s1, e0, 0);

    conv_kv_kernel<<<T_LEN + 1024, 256, 0, s1>>>(csn, kh, kl, vth, vtl);
    r_attn_mma<<<dim3(T_LEN / 8, HEADS), 128, 65536, s1>>>(
        crn + 2048, N_RN, kh, kl, vth, vtl, arh, arl);
    {
        GArg gr = {arh, arl, wroh, wrol, out_r, ROWS_R, DR, DR, DR,
                   r, nullptr, nullptr};
        gemm_one<<<(DR / 128) * (ROWS_R / 64), 256, 0, s1>>>(gr, DR / 128);
    }
    cudaEventRecord(e1, s1);

    // ---- chain A (s-branch) on stream 0, concurrent with chain B ----
    s_attn_kernel<<<T_LEN, 256>>>(csn, crn, ash, asl, rsp);
    {
        GArg gs = {ash, asl, wsoh, wsol, out_s, T_LEN, DS, DS, DS,
                   s, rsp, gate_v};
        gemm_one<<<(DS / 128) * (T_LEN / 64), 256>>>(gs, DS / 128);
    }

    // ---- join ----
    cudaStreamWaitEvent(0, e1, 0);

    // destroy only when not capturing (destroy during capture invalidates it)
    cudaStreamCaptureStatus cs = cudaStreamCaptureStatusNone;
    cudaStreamIsCapturing(s1, &cs);
    if (cs == cudaStreamCaptureStatusNone) {
        cudaEventDestroy(e0);
        cudaEventDestroy(e1);
        cudaStreamDestroy(s1);
    }
}

// round 15
// speedup vs baseline: 1.0795x; 1.0230x over previous
#include <cuda_runtime.h>
#include <cuda_bf16.h>
#include <math.h>
#include <stdint.h>

// ---------------- problem constants ----------------
#define T_LEN 1024
#define NSLOT 8
#define DS 1024
#define DR 512
#define HEADS 8
#define DHS 128
#define DHR 64
#define TOPK 4
#define ROWS_R (T_LEN * NSLOT)   // 8192
#define SCALE_S 0.08838834764831845f  // 1/sqrt(128)
#define SCALE_R 0.125f                // 1/sqrt(64)
#define EPS 1e-6f

// fused layouts
#define N_SN 2048        // q(1024) | kr(512) | vr(512), K=1024
#define N_RN 2560        // k(1024) | v(1024) | qr(512), K=512

// gemm dynamic smem: [Ah 3x512][Al 3x512][Bh 3x2048][Bl 3x2048] u32 = 60KB
#define G_SMEM 61440

// ---------------- scratch (static device memory; no allocation) -------------
__device__ __nv_bfloat16 g_sn_h[T_LEN * DS], g_sn_l[T_LEN * DS];
__device__ __nv_bfloat16 g_rn_h[ROWS_R * DR], g_rn_l[ROWS_R * DR];
__device__ __nv_bfloat16 g_as_h[T_LEN * DS], g_as_l[T_LEN * DS];
__device__ __nv_bfloat16 g_ar_h[ROWS_R * DR], g_ar_l[ROWS_R * DR];
__device__ __nv_bfloat16 g_wsn_h[N_SN * DS], g_wsn_l[N_SN * DS];
__device__ __nv_bfloat16 g_wrn_h[N_RN * DR], g_wrn_l[N_RN * DR];
__device__ __nv_bfloat16 g_wso_h[DS * DS], g_wso_l[DS * DS];
__device__ __nv_bfloat16 g_wro_h[DR * DR], g_wro_l[DR * DR];
__device__ float g_csn[T_LEN * N_SN];     // q | kr | vr
__device__ float g_crn[ROWS_R * N_RN];    // k | v | qr
__device__ float g_rsp[T_LEN * DS];
__device__ uint32_t g_kh[T_LEN * 256], g_kl[T_LEN * 256];
__device__ uint32_t g_vth[HEADS * DHR * (T_LEN / 2)];
__device__ uint32_t g_vtl[HEADS * DHR * (T_LEN / 2)];

// ---------------- PTX helpers ----------------
__device__ __forceinline__ uint32_t smem_u32(const void* p) {
    uint32_t a;
    asm("{ .reg .u64 t; cvta.to.shared.u64 t, %1; cvt.u32.u64 %0, t; }"
        : "=r"(a) : "l"(p));
    return a;
}
__device__ __forceinline__ void cp16(uint32_t dst, const void* src) {
    asm volatile("cp.async.cg.shared.global [%0], [%1], 16;"
                 :: "r"(dst), "l"(src) : "memory");
}
__device__ __forceinline__ void ldm_x4(uint32_t* r, uint32_t addr) {
    asm volatile("ldmatrix.sync.aligned.m8n8.x4.shared.b16 {%0,%1,%2,%3}, [%4];"
                 : "=r"(r[0]), "=r"(r[1]), "=r"(r[2]), "=r"(r[3]) : "r"(addr));
}
__device__ __forceinline__ void mma_bf16(
    float* c, const uint32_t* a, uint32_t b0, uint32_t b1)
{
    asm volatile(
        "mma.sync.aligned.m16n8k16.row.col.f32.bf16.bf16.f32 "
        "{%0,%1,%2,%3}, {%4,%5,%6,%7}, {%8,%9}, {%0,%1,%2,%3};"
        : "+f"(c[0]), "+f"(c[1]), "+f"(c[2]), "+f"(c[3])
        : "r"(a[0]), "r"(a[1]), "r"(a[2]), "r"(a[3]), "r"(b0), "r"(b1));
}
__device__ __forceinline__ void split2(float x, float y,
                                       uint32_t& hi, uint32_t& lo)
{
    __nv_bfloat162 h = __floats2bfloat162_rn(x, y);
    float xr = x - __bfloat162float(h.x);
    float yr = y - __bfloat162float(h.y);
    __nv_bfloat162 l = __floats2bfloat162_rn(xr, yr);
    hi = *(uint32_t*)&h;
    lo = *(uint32_t*)&l;
}

// ---------------- merged prep: 8 weight transposes + 2 rmsnorms -------------
__global__ __launch_bounds__(256) void prep_kernel(
    const float* __restrict__ Wsq, const float* __restrict__ Wsk,
    const float* __restrict__ Wsv, const float* __restrict__ Wso,
    const float* __restrict__ Wrq, const float* __restrict__ Wrk,
    const float* __restrict__ Wrv, const float* __restrict__ Wro,
    __nv_bfloat16* __restrict__ wsnh, __nv_bfloat16* __restrict__ wsnl,
    __nv_bfloat16* __restrict__ wrnh, __nv_bfloat16* __restrict__ wrnl,
    __nv_bfloat16* __restrict__ wsoh, __nv_bfloat16* __restrict__ wsol,
    __nv_bfloat16* __restrict__ wroh, __nv_bfloat16* __restrict__ wrol,
    const float* __restrict__ s, const float* __restrict__ nsw,
    __nv_bfloat16* __restrict__ snh, __nv_bfloat16* __restrict__ snl,
    const float* __restrict__ r, const float* __restrict__ nrw,
    __nv_bfloat16* __restrict__ rnh, __nv_bfloat16* __restrict__ rnl)
{
    int b = blockIdx.x;
    if (b < 4608) {
        const float* W;
        __nv_bfloat16 *th, *tl;
        int K, N;
        if (b < 1024)      { W = Wsq; th = wsnh; tl = wsnl; K = 1024; N = 1024; }
        else if (b < 1536) { b -= 1024; W = Wrk; th = wsnh + 1024 * 1024;
                             tl = wsnl + 1024 * 1024; K = 1024; N = 512; }
        else if (b < 2048) { b -= 1536; W = Wrv; th = wsnh + 1536 * 1024;
                             tl = wsnl + 1536 * 1024; K = 1024; N = 512; }
        else if (b < 2560) { b -= 2048; W = Wsk; th = wrnh; tl = wrnl;
                             K = 512; N = 1024; }
        else if (b < 3072) { b -= 2560; W = Wsv; th = wrnh + 1024 * 512;
                             tl = wrnl + 1024 * 512; K = 512; N = 1024; }
        else if (b < 3328) { b -= 3072; W = Wrq; th = wrnh + 2048 * 512;
                             tl = wrnl + 2048 * 512; K = 512; N = 512; }
        else if (b < 4352) { b -= 3328; W = Wso; th = wsoh; tl = wsol;
                             K = 1024; N = 1024; }
        else               { b -= 4352; W = Wro; th = wroh; tl = wrol;
                             K = 512; N = 512; }

        int ntx = N >> 5;
        int bx = (b % ntx) * 32;
        int by = (b / ntx) * 32;

        __shared__ float t[32][33];
        int tx = threadIdx.x & 31, ty = threadIdx.x >> 5;
        #pragma unroll
        for (int i = 0; i < 4; i++)
            t[ty + i * 8][tx] = W[(size_t)(by + ty + i * 8) * N + bx + tx];
        __syncthreads();
        #pragma unroll
        for (int i = 0; i < 4; i++) {
            int n = bx + ty + i * 8;
            int k = by + tx;
            float v = t[tx][ty + i * 8];
            __nv_bfloat16 h = __float2bfloat16(v);
            th[(size_t)n * K + k] = h;
            tl[(size_t)n * K + k] = __float2bfloat16(v - __bfloat162float(h));
        }
        return;
    }
    const float *x, *w;
    __nv_bfloat16 *oh, *ol;
    int C, row;
    if (b < 4608 + T_LEN) {
        row = b - 4608; x = s; w = nsw; oh = snh; ol = snl; C = DS;
    } else {
        row = b - 4608 - T_LEN; x = r; w = nrw; oh = rnh; ol = rnl; C = DR;
    }
    const float* xr = x + (size_t)row * C;
    float acc = 0.f;
    for (int j = threadIdx.x; j < C; j += 256) {
        float v = xr[j];
        acc += v * v;
    }
    __shared__ float red[8];
    int lane = threadIdx.x & 31, warp = threadIdx.x >> 5;
    #pragma unroll
    for (int off = 16; off; off >>= 1) acc += __shfl_xor_sync(0xffffffffu, acc, off);
    if (lane == 0) red[warp] = acc;
    __syncthreads();
    __shared__ float scale;
    if (threadIdx.x == 0) {
        float tot = 0.f;
        #pragma unroll
        for (int i = 0; i < 8; i++) tot += red[i];
        scale = rsqrtf(tot / (float)C + EPS);
    }
    __syncthreads();
    float sc = scale;
    uint32_t* ph = (uint32_t*)(oh + (size_t)row * C);
    uint32_t* pl = (uint32_t*)(ol + (size_t)row * C);
    for (int j2 = threadIdx.x; j2 < C / 2; j2 += 256) {
        float v0 = xr[2 * j2] * sc * w[2 * j2];
        float v1 = xr[2 * j2 + 1] * sc * w[2 * j2 + 1];
        uint32_t h, l;
        split2(v0, v1, h, l);
        ph[j2] = h;
        pl[j2] = l;
    }
}

// ---------------- bf16-split mma GEMM body (64x256 tile, warp 32x64) --------
struct GArg {
    const __nv_bfloat16 *Ah, *Al, *Bh, *Bl;
    float* C;
    int M, N, K, ldc;
    const float *add1, *add2, *rowscale;
};

__device__ __forceinline__ void gemm_body(
    const GArg g, int bx, int by,
    uint32_t bAh, uint32_t bAl, uint32_t bBh, uint32_t bBl)
{
    int tid = threadIdx.x;
    int lane = tid & 31, wid = tid >> 5;
    int wm = wid & 1, wn = wid >> 1;          // 2 x 4 warp grid
    int bm = by * 64, bn = bx * 256;
    int gid = lane >> 2, tig = lane & 3;
    int K = g.K;

    float acc[2][8][4];
    #pragma unroll
    for (int i = 0; i < 2; i++)
        #pragma unroll
        for (int j = 0; j < 8; j++)
            #pragma unroll
            for (int l = 0; l < 4; l++) acc[i][j][l] = 0.f;

    uint32_t aoff0, aoff1, boff[4];
    {
        int lrow = lane & 7;
        int rA = wm * 32 + lrow + (lane & 8);
        int cA = (lane & 16) >> 2;
        aoff0 = (uint32_t)(rA * 8 + cA) * 4;
        aoff1 = (uint32_t)((rA + 16) * 8 + cA) * 4;
        int rB = wn * 64 + lrow + ((lane & 16) >> 1);
        int cB = (lane & 8) >> 1;
        #pragma unroll
        for (int p = 0; p < 4; p++)
            boff[p] = (uint32_t)((rB + p * 16) * 8 + cB) * 4;
    }

    const __nv_bfloat16 *Ah = g.Ah, *Al = g.Al, *Bh = g.Bh, *Bl = g.Bl;
    auto issue = [&](int st, int k0) {
        #pragma unroll
        for (int it = 0; it < 2; it++) {
            int idx = tid + it * 256;          // 0..511
            int row = idx >> 1, gg = idx & 1;
            uint32_t bdoff = (uint32_t)(st * 256 * 8 + row * 8 + gg * 4) * 4;
            size_t bsrc = (size_t)(bn + row) * K + k0 + gg * 8;
            cp16(bBh + bdoff, Bh + bsrc);
            cp16(bBl + bdoff, Bl + bsrc);
        }
        if (tid < 128) {
            int row = tid >> 1, gg = tid & 1;
            uint32_t adoff = (uint32_t)(st * 64 * 8 + row * 8 + gg * 4) * 4;
            size_t asrc = (size_t)(bm + row) * K + k0 + gg * 8;
            cp16(bAh + adoff, Ah + asrc);
            cp16(bAl + adoff, Al + asrc);
        }
        asm volatile("cp.async.commit_group;" ::: "memory");
    };

    int nch = K >> 4;
    issue(0, 0);
    if (nch > 1) issue(1, 16);

    for (int c = 0; c < nch; c++) {
        if (c + 1 < nch) {
            asm volatile("cp.async.wait_group 1;" ::: "memory");
        } else {
            asm volatile("cp.async.wait_group 0;" ::: "memory");
        }
        __syncthreads();
        if (c + 2 < nch) issue((c + 2) % 3, (c + 2) * 16);

        uint32_t aoffst = (uint32_t)((c % 3) * 64 * 8 * 4);
        uint32_t boffst = (uint32_t)((c % 3) * 256 * 8 * 4);

        uint32_t ah[2][4], al[2][4], bh[4][4], bl[4][4];
        ldm_x4(ah[0], bAh + aoffst + aoff0);
        ldm_x4(ah[1], bAh + aoffst + aoff1);
        ldm_x4(al[0], bAl + aoffst + aoff0);
        ldm_x4(al[1], bAl + aoffst + aoff1);
        #pragma unroll
        for (int p = 0; p < 4; p++) {
            ldm_x4(bh[p], bBh + boffst + boff[p]);
            ldm_x4(bl[p], bBl + boffst + boff[p]);
        }

        #pragma unroll
        for (int nt = 0; nt < 8; nt++) {
            int p = nt >> 1, q2 = (nt & 1) << 1;
            uint32_t b0h = bh[p][q2], b1h = bh[p][q2 + 1];
            uint32_t b0l = bl[p][q2], b1l = bl[p][q2 + 1];
            mma_bf16(acc[0][nt], ah[0], b0h, b1h);
            mma_bf16(acc[0][nt], ah[0], b0l, b1l);
            mma_bf16(acc[0][nt], al[0], b0h, b1h);
            mma_bf16(acc[1][nt], ah[1], b0h, b1h);
            mma_bf16(acc[1][nt], ah[1], b0l, b1l);
            mma_bf16(acc[1][nt], al[1], b0h, b1h);
        }
    }

    #pragma unroll
    for (int mt = 0; mt < 2; mt++) {
        int r0 = bm + wm * 32 + mt * 16 + gid;
        float rs0 = (g.rowscale != nullptr) ? g.rowscale[r0] : 0.f;
        float rs8 = (g.rowscale != nullptr) ? g.rowscale[r0 + 8] : 0.f;
        #pragma unroll
        for (int nt = 0; nt < 8; nt++) {
            int col = bn + wn * 64 + nt * 8 + 2 * tig;
            size_t o0 = (size_t)r0 * g.ldc + col;
            size_t o8 = (size_t)(r0 + 8) * g.ldc + col;
            float2 v0 = make_float2(acc[mt][nt][0], acc[mt][nt][1]);
            float2 v8 = make_float2(acc[mt][nt][2], acc[mt][nt][3]);
            if (g.add1) {
                float2 x = *(const float2*)(g.add1 + o0);
                v0.x += x.x; v0.y += x.y;
                x = *(const float2*)(g.add1 + o8);
                v8.x += x.x; v8.y += x.y;
            }
            if (g.add2) {
                float2 x = *(const float2*)(g.add2 + o0);
                v0.x += rs0 * x.x; v0.y += rs0 * x.y;
                x = *(const float2*)(g.add2 + o8);
                v8.x += rs8 * x.x; v8.y += rs8 * x.y;
            }
            *(float2*)(g.C + o0) = v0;
            *(float2*)(g.C + o8) = v8;
        }
    }
}

// dynamic smem layout: Ah[3*512] Al[3*512] Bh[3*2048] Bl[3*2048] (u32)
__global__ __launch_bounds__(256, 2) void gemm_pair(
    GArg g0, GArg g1, int nblk0, int gx0, int gx1)
{
    extern __shared__ __align__(16) uint32_t gsm[];
    uint32_t bAh = smem_u32(gsm);
    uint32_t bAl = bAh + 1536 * 4;
    uint32_t bBh = bAh + 3072 * 4;
    uint32_t bBl = bAh + 9216 * 4;

    int b = blockIdx.x;
    if (b < nblk0)
        gemm_body(g0, b % gx0, b / gx0, bAh, bAl, bBh, bBl);
    else {
        b -= nblk0;
        gemm_body(g1, b % gx1, b / gx1, bAh, bAl, bBh, bBl);
    }
}

__global__ __launch_bounds__(256, 2) void gemm_one(GArg g, int gx)
{
    extern __shared__ __align__(16) uint32_t gsm[];
    uint32_t bAh = smem_u32(gsm);
    uint32_t bAl = bAh + 1536 * 4;
    uint32_t bBh = bAh + 3072 * 4;
    uint32_t bBl = bAh + 9216 * 4;
    gemm_body(g, blockIdx.x % gx, blockIdx.x / gx, bAh, bAl, bBh, bBl);
}

// ---------------- conv_kv (standalone) ----------------
__global__ __launch_bounds__(256) void conv_kv_kernel(
    const float* __restrict__ csn,
    uint32_t* __restrict__ kh, uint32_t* __restrict__ kl,
    uint32_t* __restrict__ vh, uint32_t* __restrict__ vl)
{
    int b = blockIdx.x;
    if (b < T_LEN) {
        int t = b, j = threadIdx.x;
        float2 v = *(const float2*)(csn + (size_t)t * N_SN + 1024 + 2 * j);
        uint32_t h, l;
        split2(v.x, v.y, h, l);
        kh[(size_t)t * 256 + j] = h;
        kl[(size_t)t * 256 + j] = l;
    } else {
        int idx = (b - T_LEN) * 256 + threadIdx.x;
        int pp = idx & 511;
        int d = (idx >> 9) & 63;
        int h = idx >> 15;
        float v0 = csn[(size_t)(2 * pp) * N_SN + 1536 + h * DHR + d];
        float v1 = csn[(size_t)(2 * pp + 1) * N_SN + 1536 + h * DHR + d];
        uint32_t hh, ll;
        split2(v0, v1, hh, ll);
        vh[idx] = hh;
        vl[idx] = ll;
    }
}

// ---------------- s-attention + top-k sparse ----------------
__global__ __launch_bounds__(256) void s_attn_kernel(
    const float* __restrict__ csn,
    const float* __restrict__ crn,
    __nv_bfloat16* __restrict__ as_h, __nv_bfloat16* __restrict__ as_l,
    float* __restrict__ rsp)
{
    int t = blockIdx.x;
    int tid = threadIdx.x;
    int warp = tid >> 5, lane = tid & 31;

    __shared__ float qs[DS];
    __shared__ float logits[HEADS][NSLOT];
    __shared__ float wattn[HEADS][NSLOT];
    __shared__ float wsp[NSLOT];

    for (int j = tid; j < DS; j += 256) qs[j] = csn[(size_t)t * N_SN + j];
    __syncthreads();

    {
        int h = warp;
        #pragma unroll
        for (int n = 0; n < NSLOT; n++) {
            const float* krow = crn + (size_t)(t * NSLOT + n) * N_RN + h * DHS;
            const float* qrow = qs + h * DHS;
            float p = 0.f;
            #pragma unroll
            for (int d = lane; d < DHS; d += 32) p += qrow[d] * krow[d];
            #pragma unroll
            for (int off = 16; off; off >>= 1) p += __shfl_xor_sync(0xffffffffu, p, off);
            if (lane == 0) logits[h][n] = p;
        }
    }
    __syncthreads();

    if (tid < HEADS) {
        int h = tid;
        float m = -INFINITY;
        #pragma unroll
        for (int n = 0; n < NSLOT; n++) m = fmaxf(m, logits[h][n] * SCALE_S);
        float sum = 0.f;
        #pragma unroll
        for (int n = 0; n < NSLOT; n++) {
            float e = __expf(logits[h][n] * SCALE_S - m);
            wattn[h][n] = e;
            sum += e;
        }
        float inv = 1.f / sum;
        #pragma unroll
        for (int n = 0; n < NSLOT; n++) wattn[h][n] *= inv;
    }
    if (tid == 8) {
        float sp[NSLOT];
        #pragma unroll
        for (int n = 0; n < NSLOT; n++) {
            float a = 0.f;
            #pragma unroll
            for (int h = 0; h < HEADS; h++) a += logits[h][n];
            sp[n] = a * SCALE_S;
        }
        bool sel[NSLOT];
        #pragma unroll
        for (int n = 0; n < NSLOT; n++) { sel[n] = false; wsp[n] = 0.f; }
        int idxs[TOPK];
        #pragma unroll
        for (int kk = 0; kk < TOPK; kk++) {
            int best = -1; float bv = -INFINITY;
            #pragma unroll
            for (int n = 0; n < NSLOT; n++)
                if (!sel[n] && sp[n] > bv) { bv = sp[n]; best = n; }
            sel[best] = true; idxs[kk] = best;
        }
        float m = -INFINITY;
        #pragma unroll
        for (int kk = 0; kk < TOPK; kk++) m = fmaxf(m, sp[idxs[kk]]);
        float sum = 0.f, e[TOPK];
        #pragma unroll
        for (int kk = 0; kk < TOPK; kk++) { e[kk] = __expf(sp[idxs[kk]] - m); sum += e[kk]; }
        float inv = 1.f / sum;
        #pragma unroll
        for (int kk = 0; kk < TOPK; kk++) wsp[idxs[kk]] = e[kk] * inv;
    }
    __syncthreads();

    uint32_t* ph = (uint32_t*)(as_h + (size_t)t * DS);
    uint32_t* pl = (uint32_t*)(as_l + (size_t)t * DS);
    for (int j2 = tid; j2 < DS / 2; j2 += 256) {
        int j = 2 * j2;
        int h = j >> 7;
        float a0 = 0.f, a1 = 0.f, b0 = 0.f, b1 = 0.f;
        #pragma unroll
        for (int n = 0; n < NSLOT; n++) {
            float2 vv = *(const float2*)(crn + (size_t)(t * NSLOT + n) * N_RN + 1024 + j);
            a0 += wattn[h][n] * vv.x;
            a1 += wattn[h][n] * vv.y;
            b0 += wsp[n] * vv.x;
            b1 += wsp[n] * vv.y;
        }
        uint32_t hh, ll;
        split2(a0, a1, hh, ll);
        ph[j2] = hh;
        pl[j2] = ll;
        *(float2*)(rsp + (size_t)t * DS + j) = make_float2(b0, b1);
    }
}

// ---------------- causal r-attention (identical to R13/R14 best) ------------
__global__ __launch_bounds__(128, 3) void r_attn_mma(
    const float* __restrict__ qr, int qld,
    const uint32_t* __restrict__ kh_g, const uint32_t* __restrict__ kl_g,
    const uint32_t* __restrict__ vh_g, const uint32_t* __restrict__ vl_g,
    __nv_bfloat16* __restrict__ ar_h, __nv_bfloat16* __restrict__ ar_l)
{
    extern __shared__ __align__(16) uint32_t dsm[];
    uint32_t bkh = smem_u32(dsm);
    uint32_t bkl = bkh + 16384;
    uint32_t bvh = bkh + 32768;
    uint32_t bvl = bkh + 49152;

    int tt = (int)(gridDim.x - 1 - blockIdx.x);
    int h = blockIdx.y;
    int t0 = tt * 8;
    int hb = h * DHR;

    int tid = threadIdx.x;
    int w = tid >> 5, lane = tid & 31;
    int gid = lane >> 2, tig = lane & 3;

    int r0 = t0 * 8 + 16 * w + gid;
    int r8 = r0 + 8;
    uint32_t qh[4][4], ql[4][4];
    #pragma unroll
    for (int kc = 0; kc < 4; kc++) {
        float2 x0 = *(const float2*)(qr + (size_t)r0 * qld + hb + kc * 16 + 2 * tig);
        float2 x1 = *(const float2*)(qr + (size_t)r8 * qld + hb + kc * 16 + 2 * tig);
        float2 x2 = *(const float2*)(qr + (size_t)r0 * qld + hb + kc * 16 + 2 * tig + 8);
        float2 x3 = *(const float2*)(qr + (size_t)r8 * qld + hb + kc * 16 + 2 * tig + 8);
        split2(x0.x * SCALE_R, x0.y * SCALE_R, qh[kc][0], ql[kc][0]);
        split2(x1.x * SCALE_R, x1.y * SCALE_R, qh[kc][1], ql[kc][1]);
        split2(x2.x * SCALE_R, x2.y * SCALE_R, qh[kc][2], ql[kc][2]);
        split2(x3.x * SCALE_R, x3.y * SCALE_R, qh[kc][3], ql[kc][3]);
    }
    int tok0 = t0 + ((16 * w + gid) >> 3);
    int tok8 = t0 + ((16 * w + gid + 8) >> 3);

    uint32_t rowoff[4];
    uint32_t swr[4];
    {
        int mrow = ((lane & 16) >> 1) + (lane & 7);
        #pragma unroll
        for (int p = 0; p < 4; p++) {
            int nr = p * 16 + mrow;
            rowoff[p] = (uint32_t)(nr * 128);
            swr[p] = (uint32_t)(nr & 7);
        }
    }
    int gsel = (lane & 8) >> 3;

    float m0 = -INFINITY, m1 = -INFINITY, l0 = 0.f, l1 = 0.f;
    float acco[8][4];
    #pragma unroll
    for (int i = 0; i < 8; i++)
        #pragma unroll
        for (int j = 0; j < 4; j++) acco[i][j] = 0.f;

    int ntiles = ((t0 + 7) >> 6) + 1;

    auto issueT = [&](int st, int p0) {
        int pp0 = p0 >> 1;
        #pragma unroll
        for (int it = 0; it < 4; it++) {
            int idx = tid + it * 128;
            int p = idx >> 3, g = idx & 7;
            uint32_t doff = (uint32_t)(st * 8192) +
                            (uint32_t)(p * 32 + ((g ^ (p & 7)) << 2)) * 4;
            size_t ksrc = (size_t)(p0 + p) * 256 + h * 32 + g * 4;
            cp16(bkh + doff, kh_g + ksrc);
            cp16(bkl + doff, kl_g + ksrc);
            size_t vsrc = (size_t)h * 32768 + (size_t)p * 512 + pp0 + g * 4;
            cp16(bvh + doff, vh_g + vsrc);
            cp16(bvl + doff, vl_g + vsrc);
        }
        asm volatile("cp.async.commit_group;" ::: "memory");
    };

    issueT(0, 0);

    for (int c = 0; c < ntiles; c++) {
        int p0 = c * 64;
        if (c + 1 < ntiles) {
            issueT((c + 1) & 1, (c + 1) * 64);
            asm volatile("cp.async.wait_group 1;" ::: "memory");
        } else {
            asm volatile("cp.async.wait_group 0;" ::: "memory");
        }
        __syncthreads();

        uint32_t stB = (uint32_t)((c & 1) * 8192);

        float s[8][4];
        #pragma unroll
        for (int i = 0; i < 8; i++)
            #pragma unroll
            for (int j = 0; j < 4; j++) s[i][j] = 0.f;

        #pragma unroll
        for (int p = 0; p < 4; p++) {
            #pragma unroll
            for (int kc = 0; kc < 4; kc++) {
                uint32_t off = stB + rowoff[p] +
                               ((uint32_t)((2 * kc + gsel) ^ swr[p]) << 4);
                uint32_t bh[4], bl[4];
                ldm_x4(bh, bkh + off);
                ldm_x4(bl, bkl + off);
                #pragma unroll
                for (int q = 0; q < 2; q++) {
                    int nt = 2 * p + q;
                    mma_bf16(s[nt], qh[kc], bh[2 * q], bh[2 * q + 1]);
                    mma_bf16(s[nt], qh[kc], bl[2 * q], bl[2 * q + 1]);
                    mma_bf16(s[nt], ql[kc], bh[2 * q], bh[2 * q + 1]);
                }
            }
        }

        if (p0 + 64 > t0) {
            #pragma unroll
            for (int nt = 0; nt < 8; nt++) {
                int pg = p0 + nt * 8 + 2 * tig;
                if (pg > tok0)     s[nt][0] = -INFINITY;
                if (pg + 1 > tok0) s[nt][1] = -INFINITY;
                if (pg > tok8)     s[nt][2] = -INFINITY;
                if (pg + 1 > tok8) s[nt][3] = -INFINITY;
            }
        }

        float mx0 = -INFINITY, mx1 = -INFINITY;
        #pragma unroll
        for (int nt = 0; nt < 8; nt++) {
            mx0 = fmaxf(mx0, fmaxf(s[nt][0], s[nt][1]));
            mx1 = fmaxf(mx1, fmaxf(s[nt][2], s[nt][3]));
        }
        mx0 = fmaxf(mx0, __shfl_xor_sync(0xffffffffu, mx0, 1));
        mx0 = fmaxf(mx0, __shfl_xor_sync(0xffffffffu, mx0, 2));
        mx1 = fmaxf(mx1, __shfl_xor_sync(0xffffffffu, mx1, 1));
        mx1 = fmaxf(mx1, __shfl_xor_sync(0xffffffffu, mx1, 2));
        float nm0 = fmaxf(m0, mx0), nm1 = fmaxf(m1, mx1);
        float cr0 = __expf(m0 - nm0), cr1 = __expf(m1 - nm1);
        m0 = nm0; m1 = nm1;

        float rs0 = 0.f, rs1 = 0.f;
        #pragma unroll
        for (int nt = 0; nt < 8; nt++) {
            s[nt][0] = __expf(s[nt][0] - nm0);
            s[nt][1] = __expf(s[nt][1] - nm0);
            s[nt][2] = __expf(s[nt][2] - nm1);
            s[nt][3] = __expf(s[nt][3] - nm1);
            rs0 += s[nt][0] + s[nt][1];
            rs1 += s[nt][2] + s[nt][3];
        }
        rs0 += __shfl_xor_sync(0xffffffffu, rs0, 1);
        rs0 += __shfl_xor_sync(0xffffffffu, rs0, 2);
        rs1 += __shfl_xor_sync(0xffffffffu, rs1, 1);
        rs1 += __shfl_xor_sync(0xffffffffu, rs1, 2);
        l0 = l0 * cr0 + rs0;
        l1 = l1 * cr1 + rs1;

        #pragma unroll
        for (int ntd = 0; ntd < 8; ntd++) {
            acco[ntd][0] *= cr0; acco[ntd][1] *= cr0;
            acco[ntd][2] *= cr1; acco[ntd][3] *= cr1;
        }

        #pragma unroll
        for (int kc = 0; kc < 4; kc++) {
            uint32_t pah[4], pal[4];
            split2(s[2 * kc][0],     s[2 * kc][1],     pah[0], pal[0]);
            split2(s[2 * kc][2],     s[2 * kc][3],     pah[1], pal[1]);
            split2(s[2 * kc + 1][0], s[2 * kc + 1][1], pah[2], pal[2]);
            split2(s[2 * kc + 1][2], s[2 * kc + 1][3], pah[3], pal[3]);
            #pragma unroll
            for (int p = 0; p < 4; p++) {
                uint32_t off = stB + rowoff[p] +
                               ((uint32_t)((2 * kc + gsel) ^ swr[p]) << 4);
                uint32_t bh[4], bl[4];
                ldm_x4(bh, bvh + off);
                ldm_x4(bl, bvl + off);
                #pragma unroll
                for (int q = 0; q < 2; q++) {
                    int ntd = 2 * p + q;
                    mma_bf16(acco[ntd], pah, bh[2 * q], bh[2 * q + 1]);
                    mma_bf16(acco[ntd], pah, bl[2 * q], bl[2 * q + 1]);
                    mma_bf16(acco[ntd], pal, bh[2 * q], bh[2 * q + 1]);
                }
            }
        }

        if (c + 1 < ntiles) __syncthreads();
    }

    float i0 = 1.f / l0, i1 = 1.f / l1;
    #pragma unroll
    for (int ntd = 0; ntd < 8; ntd++) {
        int col = hb + ntd * 8 + 2 * tig;
        uint32_t hh, ll;
        split2(acco[ntd][0] * i0, acco[ntd][1] * i0, hh, ll);
        *(uint32_t*)(ar_h + (size_t)r0 * DR + col) = hh;
        *(uint32_t*)(ar_l + (size_t)r0 * DR + col) = ll;
        split2(acco[ntd][2] * i1, acco[ntd][3] * i1, hh, ll);
        *(uint32_t*)(ar_h + (size_t)r8 * DR + col) = hh;
        *(uint32_t*)(ar_l + (size_t)r8 * DR + col) = ll;
    }
}

// ---------------- host launch ----------------
extern "C" void kernel_launch(void* const* d_in, const int* in_sizes, int n_in,
                              void* d_out, int out_size)
{
    const float* s      = (const float*)d_in[0];
    const float* r      = (const float*)d_in[1];
    const float* gate_v = (const float*)d_in[2];
    const float* nsw    = (const float*)d_in[3];
    const float* nrw    = (const float*)d_in[4];
    const float* Wsq    = (const float*)d_in[5];
    const float* Wsk    = (const float*)d_in[6];
    const float* Wsv    = (const float*)d_in[7];
    const float* Wso    = (const float*)d_in[8];
    const float* Wrq    = (const float*)d_in[9];
    const float* Wrk    = (const float*)d_in[10];
    const float* Wrv    = (const float*)d_in[11];
    const float* Wro    = (const float*)d_in[12];

    float* out_s = (float*)d_out;
    float* out_r = (float*)d_out + T_LEN * DS;

    __nv_bfloat16 *snh, *snl, *rnh, *rnl, *ash, *asl, *arh, *arl;
    __nv_bfloat16 *wsnh, *wsnl, *wrnh, *wrnl, *wsoh, *wsol, *wroh, *wrol;
    float *csn, *crn, *rsp;
    uint32_t *kh, *kl, *vth, *vtl;
    cudaGetSymbolAddress((void**)&snh, g_sn_h);
    cudaGetSymbolAddress((void**)&snl, g_sn_l);
    cudaGetSymbolAddress((void**)&rnh, g_rn_h);
    cudaGetSymbolAddress((void**)&rnl, g_rn_l);
    cudaGetSymbolAddress((void**)&ash, g_as_h);
    cudaGetSymbolAddress((void**)&asl, g_as_l);
    cudaGetSymbolAddress((void**)&arh, g_ar_h);
    cudaGetSymbolAddress((void**)&arl, g_ar_l);
    cudaGetSymbolAddress((void**)&wsnh, g_wsn_h);
    cudaGetSymbolAddress((void**)&wsnl, g_wsn_l);
    cudaGetSymbolAddress((void**)&wrnh, g_wrn_h);
    cudaGetSymbolAddress((void**)&wrnl, g_wrn_l);
    cudaGetSymbolAddress((void**)&wsoh, g_wso_h);
    cudaGetSymbolAddress((void**)&wsol, g_wso_l);
    cudaGetSymbolAddress((void**)&wroh, g_wro_h);
    cudaGetSymbolAddress((void**)&wrol, g_wro_l);
    cudaGetSymbolAddress((void**)&csn, g_csn);
    cudaGetSymbolAddress((void**)&crn, g_crn);
    cudaGetSymbolAddress((void**)&rsp, g_rsp);
    cudaGetSymbolAddress((void**)&kh, g_kh);
    cudaGetSymbolAddress((void**)&kl, g_kl);
    cudaGetSymbolAddress((void**)&vth, g_vth);
    cudaGetSymbolAddress((void**)&vtl, g_vtl);

    cudaFuncSetAttribute(r_attn_mma,
                         cudaFuncAttributeMaxDynamicSharedMemorySize, 65536);
    cudaFuncSetAttribute(gemm_pair,
                         cudaFuncAttributeMaxDynamicSharedMemorySize, G_SMEM);
    cudaFuncSetAttribute(gemm_one,
                         cudaFuncAttributeMaxDynamicSharedMemorySize, G_SMEM);

    cudaStream_t s1;
    cudaStreamCreateWithFlags(&s1, cudaStreamNonBlocking);
    cudaEvent_t e0, e1;
    cudaEventCreateWithFlags(&e0, cudaEventDisableTiming);
    cudaEventCreateWithFlags(&e1, cudaEventDisableTiming);

    // ---- stream 0: prep + projection GEMMs ----
    prep_kernel<<<4608 + T_LEN + ROWS_R, 256>>>(
        Wsq, Wsk, Wsv, Wso, Wrq, Wrk, Wrv, Wro,
        wsnh, wsnl, wrnh, wrnl, wsoh, wsol, wroh, wrol,
        s, nsw, snh, snl, r, nrw, rnh, rnl);
    {
        GArg g0 = {snh, snl, wsnh, wsnl, csn, T_LEN, N_SN, DS, N_SN,
                   nullptr, nullptr, nullptr};
        GArg g1 = {rnh, rnl, wrnh, wrnl, crn, ROWS_R, N_RN, DR, N_RN,
                   nullptr, nullptr, nullptr};
        int gx0 = N_SN / 256, gy0 = T_LEN / 64;
        int gx1 = N_RN / 256, gy1 = ROWS_R / 64;
        gemm_pair<<<gx0 * gy0 + gx1 * gy1, 256, G_SMEM>>>(
            g0, g1, gx0 * gy0, gx0, gx1);
    }

    // ---- fork: chain B (r-branch) on s1 ----
    cudaEventRecord(e0, 0);
    cudaStreamWaitEvent(s1, e0, 0);

    conv_kv_kernel<<<T_LEN + 1024, 256, 0, s1>>>(csn, kh, kl, vth, vtl);
    r_attn_mma<<<dim3(T_LEN / 8, HEADS), 128, 65536, s1>>>(
        crn + 2048, N_RN, kh, kl, vth, vtl, arh, arl);
    {
        GArg gr = {arh, arl, wroh, wrol, out_r, ROWS_R, DR, DR, DR,
                   r, nullptr, nullptr};
        gemm_one<<<(DR / 256) * (ROWS_R / 64), 256, G_SMEM, s1>>>(gr, DR / 256);
    }
    cudaEventRecord(e1, s1);

    // ---- chain A (s-branch) on stream 0, concurrent with chain B ----
    s_attn_kernel<<<T_LEN, 256>>>(csn, crn, ash, asl, rsp);
    {
        GArg gs = {ash, asl, wsoh, wsol, out_s, T_LEN, DS, DS, DS,
                   s, rsp, gate_v};
        gemm_one<<<(DS / 256) * (T_LEN / 64), 256, G_SMEM>>>(gs, DS / 256);
    }

    // ---- join ----
    cudaStreamWaitEvent(0, e1, 0);

    // destroy only when not capturing (destroy during capture invalidates it)
    cudaStreamCaptureStatus cs = cudaStreamCaptureStatusNone;
    cudaStreamIsCapturing(s1, &cs);
    if (cs == cudaStreamCaptureStatusNone) {
        cudaEventDestroy(e0);
        cudaEventDestroy(e1);
        cudaStreamDestroy(s1);
    }
}

// round 16
// speedup vs baseline: 1.2807x; 1.1864x over previous
#include <cuda_runtime.h>
#include <cuda_bf16.h>
#include <math.h>
#include <stdint.h>

// ---------------- problem constants ----------------
#define T_LEN 1024
#define NSLOT 8
#define DS 1024
#define DR 512
#define HEADS 8
#define DHS 128
#define DHR 64
#define TOPK 4
#define ROWS_R (T_LEN * NSLOT)   // 8192
#define SCALE_S 0.08838834764831845f  // 1/sqrt(128)
#define SCALE_R 0.125f                // 1/sqrt(64)
#define EPS 1e-6f

// fused layouts
#define N_SN 2048        // q(1024) | kr(512) | vr(512), K=1024

// gemm dynamic smem: [Ah 3x512][Al 3x512][Bh 3x2048][Bl 3x2048] u32 = 60KB
#define G_SMEM 61440

// ---------------- scratch (static device memory; no allocation) -------------
__device__ __nv_bfloat16 g_sn_h[T_LEN * DS], g_sn_l[T_LEN * DS];
__device__ __nv_bfloat16 g_rn_h[ROWS_R * DR], g_rn_l[ROWS_R * DR];
__device__ __nv_bfloat16 g_as_h[T_LEN * DS], g_as_l[T_LEN * DS];
__device__ __nv_bfloat16 g_ar_h[ROWS_R * DR], g_ar_l[ROWS_R * DR];
__device__ __nv_bfloat16 g_wsn_h[N_SN * DS], g_wsn_l[N_SN * DS];
__device__ __nv_bfloat16 g_wrn_h[2560 * DR], g_wrn_l[2560 * DR]; // WskT|WsvT|WrqT
__device__ __nv_bfloat16 g_wso_h[DS * DS], g_wso_l[DS * DS];
__device__ __nv_bfloat16 g_wro_h[DR * DR], g_wro_l[DR * DR];
__device__ __nv_bfloat16 g_wu_h[HEADS * 512 * 128], g_wu_l[HEADS * 512 * 128];
__device__ __nv_bfloat16 g_qs_h[T_LEN * DS], g_qs_l[T_LEN * DS];
__device__ __nv_bfloat16 g_z2h[ROWS_R * DR], g_z2l[ROWS_R * DR];   // (h*T+t, 512)
__device__ __nv_bfloat16 g_zsph[T_LEN * DR], g_zspl[T_LEN * DR];
__device__ float g_csn[T_LEN * N_SN];     // q | kr | vr
__device__ float g_crn[ROWS_R * DR];      // qr only
__device__ float g_u[T_LEN * 4096];       // u[t][h*512+i]
__device__ float g_rsp[T_LEN * DS];
__device__ uint32_t g_kh[T_LEN * 256], g_kl[T_LEN * 256];
__device__ uint32_t g_vth[HEADS * DHR * (T_LEN / 2)];
__device__ uint32_t g_vtl[HEADS * DHR * (T_LEN / 2)];

// ---------------- PTX helpers ----------------
__device__ __forceinline__ uint32_t smem_u32(const void* p) {
    uint32_t a;
    asm("{ .reg .u64 t; cvta.to.shared.u64 t, %1; cvt.u32.u64 %0, t; }"
        : "=r"(a) : "l"(p));
    return a;
}
__device__ __forceinline__ void cp16(uint32_t dst, const void* src) {
    asm volatile("cp.async.cg.shared.global [%0], [%1], 16;"
                 :: "r"(dst), "l"(src) : "memory");
}
__device__ __forceinline__ void ldm_x4(uint32_t* r, uint32_t addr) {
    asm volatile("ldmatrix.sync.aligned.m8n8.x4.shared.b16 {%0,%1,%2,%3}, [%4];"
                 : "=r"(r[0]), "=r"(r[1]), "=r"(r[2]), "=r"(r[3]) : "r"(addr));
}
__device__ __forceinline__ void mma_bf16(
    float* c, const uint32_t* a, uint32_t b0, uint32_t b1)
{
    asm volatile(
        "mma.sync.aligned.m16n8k16.row.col.f32.bf16.bf16.f32 "
        "{%0,%1,%2,%3}, {%4,%5,%6,%7}, {%8,%9}, {%0,%1,%2,%3};"
        : "+f"(c[0]), "+f"(c[1]), "+f"(c[2]), "+f"(c[3])
        : "r"(a[0]), "r"(a[1]), "r"(a[2]), "r"(a[3]), "r"(b0), "r"(b1));
}
__device__ __forceinline__ void split2(float x, float y,
                                       uint32_t& hi, uint32_t& lo)
{
    __nv_bfloat162 h = __floats2bfloat162_rn(x, y);
    float xr = x - __bfloat162float(h.x);
    float yr = y - __bfloat162float(h.y);
    __nv_bfloat162 l = __floats2bfloat162_rn(xr, yr);
    hi = *(uint32_t*)&h;
    lo = *(uint32_t*)&l;
}

// ---------------- merged prep: transposes + wu copy + rmsnorms --------------
__global__ __launch_bounds__(256) void prep_kernel(
    const float* __restrict__ Wsq, const float* __restrict__ Wsk,
    const float* __restrict__ Wsv, const float* __restrict__ Wso,
    const float* __restrict__ Wrq, const float* __restrict__ Wrk,
    const float* __restrict__ Wrv, const float* __restrict__ Wro,
    __nv_bfloat16* __restrict__ wsnh, __nv_bfloat16* __restrict__ wsnl,
    __nv_bfloat16* __restrict__ wrnh, __nv_bfloat16* __restrict__ wrnl,
    __nv_bfloat16* __restrict__ wsoh, __nv_bfloat16* __restrict__ wsol,
    __nv_bfloat16* __restrict__ wroh, __nv_bfloat16* __restrict__ wrol,
    __nv_bfloat16* __restrict__ wuh, __nv_bfloat16* __restrict__ wul,
    const float* __restrict__ s, const float* __restrict__ nsw,
    __nv_bfloat16* __restrict__ snh, __nv_bfloat16* __restrict__ snl,
    const float* __restrict__ r, const float* __restrict__ nrw,
    __nv_bfloat16* __restrict__ rnh, __nv_bfloat16* __restrict__ rnl)
{
    int b = blockIdx.x;
    if (b < 4608) {
        const float* W;
        __nv_bfloat16 *th, *tl;
        int K, N;
        if (b < 1024)      { W = Wsq; th = wsnh; tl = wsnl; K = 1024; N = 1024; }
        else if (b < 1536) { b -= 1024; W = Wrk; th = wsnh + 1024 * 1024;
                             tl = wsnl + 1024 * 1024; K = 1024; N = 512; }
        else if (b < 2048) { b -= 1536; W = Wrv; th = wsnh + 1536 * 1024;
                             tl = wsnl + 1536 * 1024; K = 1024; N = 512; }
        else if (b < 2560) { b -= 2048; W = Wsk; th = wrnh; tl = wrnl;
                             K = 512; N = 1024; }
        else if (b < 3072) { b -= 2560; W = Wsv; th = wrnh + 1024 * 512;
                             tl = wrnl + 1024 * 512; K = 512; N = 1024; }
        else if (b < 3328) { b -= 3072; W = Wrq; th = wrnh + 2048 * 512;
                             tl = wrnl + 2048 * 512; K = 512; N = 512; }
        else if (b < 4352) { b -= 3328; W = Wso; th = wsoh; tl = wsol;
                             K = 1024; N = 1024; }
        else               { b -= 4352; W = Wro; th = wroh; tl = wrol;
                             K = 512; N = 512; }

        int ntx = N >> 5;
        int bx = (b % ntx) * 32;
        int by = (b / ntx) * 32;

        __shared__ float t[32][33];
        int tx = threadIdx.x & 31, ty = threadIdx.x >> 5;
        #pragma unroll
        for (int i = 0; i < 4; i++)
            t[ty + i * 8][tx] = W[(size_t)(by + ty + i * 8) * N + bx + tx];
        __syncthreads();
        #pragma unroll
        for (int i = 0; i < 4; i++) {
            int n = bx + ty + i * 8;
            int k = by + tx;
            float v = t[tx][ty + i * 8];
            __nv_bfloat16 h = __float2bfloat16(v);
            th[(size_t)n * K + k] = h;
            tl[(size_t)n * K + k] = __float2bfloat16(v - __bfloat162float(h));
        }
        return;
    }
    if (b < 5632) {
        // wu: wu[(h*512+i)][j] = Wsk[i][h*128+j], split bf16 (pairs)
        int idx = (b - 4608) * 256 + threadIdx.x;    // 0..262143 pairs
        int o = idx * 2;
        int h = o >> 16;
        int rem = o & 65535;
        int i = rem >> 7;
        int j = rem & 127;
        float2 v = *(const float2*)(Wsk + (size_t)i * 1024 + h * 128 + j);
        uint32_t hh, ll;
        split2(v.x, v.y, hh, ll);
        ((uint32_t*)wuh)[idx] = hh;
        ((uint32_t*)wul)[idx] = ll;
        return;
    }
    const float *x, *w;
    __nv_bfloat16 *oh, *ol;
    int C, row;
    if (b < 5632 + T_LEN) {
        row = b - 5632; x = s; w = nsw; oh = snh; ol = snl; C = DS;
    } else {
        row = b - 5632 - T_LEN; x = r; w = nrw; oh = rnh; ol = rnl; C = DR;
    }
    const float* xr = x + (size_t)row * C;
    float acc = 0.f;
    for (int j = threadIdx.x; j < C; j += 256) {
        float v = xr[j];
        acc += v * v;
    }
    __shared__ float red[8];
    int lane = threadIdx.x & 31, warp = threadIdx.x >> 5;
    #pragma unroll
    for (int off = 16; off; off >>= 1) acc += __shfl_xor_sync(0xffffffffu, acc, off);
    if (lane == 0) red[warp] = acc;
    __syncthreads();
    __shared__ float scale;
    if (threadIdx.x == 0) {
        float tot = 0.f;
        #pragma unroll
        for (int i = 0; i < 8; i++) tot += red[i];
        scale = rsqrtf(tot / (float)C + EPS);
    }
    __syncthreads();
    float sc = scale;
    uint32_t* ph = (uint32_t*)(oh + (size_t)row * C);
    uint32_t* pl = (uint32_t*)(ol + (size_t)row * C);
    for (int j2 = threadIdx.x; j2 < C / 2; j2 += 256) {
        float v0 = xr[2 * j2] * sc * w[2 * j2];
        float v1 = xr[2 * j2 + 1] * sc * w[2 * j2 + 1];
        uint32_t h, l;
        split2(v0, v1, h, l);
        ph[j2] = h;
        pl[j2] = l;
    }
}

// ---------------- bf16-split mma GEMM body (64x256 tile, warp 32x64) --------
struct GArg {
    const __nv_bfloat16 *Ah, *Al, *Bh, *Bl;
    float* C;
    int M, N, K, lda, ldc;
    const float *add1, *add2, *rowscale;
};

__device__ __forceinline__ void gemm_body(
    const GArg g, int bx, int by,
    uint32_t bAh, uint32_t bAl, uint32_t bBh, uint32_t bBl)
{
    int tid = threadIdx.x;
    int lane = tid & 31, wid = tid >> 5;
    int wm = wid & 1, wn = wid >> 1;          // 2 x 4 warp grid
    int bm = by * 64, bn = bx * 256;
    int gid = lane >> 2, tig = lane & 3;
    int K = g.K, lda = g.lda;

    float acc[2][8][4];
    #pragma unroll
    for (int i = 0; i < 2; i++)
        #pragma unroll
        for (int j = 0; j < 8; j++)
            #pragma unroll
            for (int l = 0; l < 4; l++) acc[i][j][l] = 0.f;

    uint32_t aoff0, aoff1, boff[4];
    {
        int lrow = lane & 7;
        int rA = wm * 32 + lrow + (lane & 8);
        int cA = (lane & 16) >> 2;
        aoff0 = (uint32_t)(rA * 8 + cA) * 4;
        aoff1 = (uint32_t)((rA + 16) * 8 + cA) * 4;
        int rB = wn * 64 + lrow + ((lane & 16) >> 1);
        int cB = (lane & 8) >> 1;
        #pragma unroll
        for (int p = 0; p < 4; p++)
            boff[p] = (uint32_t)((rB + p * 16) * 8 + cB) * 4;
    }

    const __nv_bfloat16 *Ah = g.Ah, *Al = g.Al, *Bh = g.Bh, *Bl = g.Bl;
    auto issue = [&](int st, int k0) {
        #pragma unroll
        for (int it = 0; it < 2; it++) {
            int idx = tid + it * 256;
            int row = idx >> 1, gg = idx & 1;
            uint32_t bdoff = (uint32_t)(st * 256 * 8 + row * 8 + gg * 4) * 4;
            size_t bsrc = (size_t)(bn + row) * K + k0 + gg * 8;
            cp16(bBh + bdoff, Bh + bsrc);
            cp16(bBl + bdoff, Bl + bsrc);
        }
        if (tid < 128) {
            int row = tid >> 1, gg = tid & 1;
            uint32_t adoff = (uint32_t)(st * 64 * 8 + row * 8 + gg * 4) * 4;
            size_t asrc = (size_t)(bm + row) * lda + k0 + gg * 8;
            cp16(bAh + adoff, Ah + asrc);
            cp16(bAl + adoff, Al + asrc);
        }
        asm volatile("cp.async.commit_group;" ::: "memory");
    };

    int nch = K >> 4;
    issue(0, 0);
    if (nch > 1) issue(1, 16);

    for (int c = 0; c < nch; c++) {
        if (c + 1 < nch) {
            asm volatile("cp.async.wait_group 1;" ::: "memory");
        } else {
            asm volatile("cp.async.wait_group 0;" ::: "memory");
        }
        __syncthreads();
        if (c + 2 < nch) issue((c + 2) % 3, (c + 2) * 16);

        uint32_t aoffst = (uint32_t)((c % 3) * 64 * 8 * 4);
        uint32_t boffst = (uint32_t)((c % 3) * 256 * 8 * 4);

        uint32_t ah[2][4], al[2][4], bh[4][4], bl[4][4];
        ldm_x4(ah[0], bAh + aoffst + aoff0);
        ldm_x4(ah[1], bAh + aoffst + aoff1);
        ldm_x4(al[0], bAl + aoffst + aoff0);
        ldm_x4(al[1], bAl + aoffst + aoff1);
        #pragma unroll
        for (int p = 0; p < 4; p++) {
            ldm_x4(bh[p], bBh + boffst + boff[p]);
            ldm_x4(bl[p], bBl + boffst + boff[p]);
        }

        #pragma unroll
        for (int nt = 0; nt < 8; nt++) {
            int p = nt >> 1, q2 = (nt & 1) << 1;
            uint32_t b0h = bh[p][q2], b1h = bh[p][q2 + 1];
            uint32_t b0l = bl[p][q2], b1l = bl[p][q2 + 1];
            mma_bf16(acc[0][nt], ah[0], b0h, b1h);
            mma_bf16(acc[0][nt], ah[0], b0l, b1l);
            mma_bf16(acc[0][nt], al[0], b0h, b1h);
            mma_bf16(acc[1][nt], ah[1], b0h, b1h);
            mma_bf16(acc[1][nt], ah[1], b0l, b1l);
            mma_bf16(acc[1][nt], al[1], b0h, b1h);
        }
    }

    #pragma unroll
    for (int mt = 0; mt < 2; mt++) {
        int r0 = bm + wm * 32 + mt * 16 + gid;
        float rs0 = (g.rowscale != nullptr) ? g.rowscale[r0] : 0.f;
        float rs8 = (g.rowscale != nullptr) ? g.rowscale[r0 + 8] : 0.f;
        #pragma unroll
        for (int nt = 0; nt < 8; nt++) {
            int col = bn + wn * 64 + nt * 8 + 2 * tig;
            size_t o0 = (size_t)r0 * g.ldc + col;
            size_t o8 = (size_t)(r0 + 8) * g.ldc + col;
            float2 v0 = make_float2(acc[mt][nt][0], acc[mt][nt][1]);
            float2 v8 = make_float2(acc[mt][nt][2], acc[mt][nt][3]);
            if (g.add1) {
                float2 x = *(const float2*)(g.add1 + o0);
                v0.x += x.x; v0.y += x.y;
                x = *(const float2*)(g.add1 + o8);
                v8.x += x.x; v8.y += x.y;
            }
            if (g.add2) {
                float2 x = *(const float2*)(g.add2 + o0);
                v0.x += rs0 * x.x; v0.y += rs0 * x.y;
                x = *(const float2*)(g.add2 + o8);
                v8.x += rs8 * x.x; v8.y += rs8 * x.y;
            }
            *(float2*)(g.C + o0) = v0;
            *(float2*)(g.C + o8) = v8;
        }
    }
}

__global__ __launch_bounds__(256, 2) void gemm_pair(
    GArg g0, GArg g1, int nblk0, int gx0, int gx1)
{
    extern __shared__ __align__(16) uint32_t gsm[];
    uint32_t bAh = smem_u32(gsm);
    uint32_t bAl = bAh + 1536 * 4;
    uint32_t bBh = bAh + 3072 * 4;
    uint32_t bBl = bAh + 9216 * 4;

    int b = blockIdx.x;
    if (b < nblk0)
        gemm_body(g0, b % gx0, b / gx0, bAh, bAl, bBh, bBl);
    else {
        b -= nblk0;
        gemm_body(g1, b % gx1, b / gx1, bAh, bAl, bBh, bBl);
    }
}

__global__ __launch_bounds__(256, 2) void gemm_one(GArg g, int gx)
{
    extern __shared__ __align__(16) uint32_t gsm[];
    uint32_t bAh = smem_u32(gsm);
    uint32_t bAl = bAh + 1536 * 4;
    uint32_t bBh = bAh + 3072 * 4;
    uint32_t bBl = bAh + 9216 * 4;
    gemm_body(g, blockIdx.x % gx, blockIdx.x / gx, bAh, bAl, bBh, bBl);
}

// batched-per-head u-GEMM: u[t][h*512+i] = q_h @ Wsk_h^T
__global__ __launch_bounds__(256, 2) void gemm_u(
    const __nv_bfloat16* __restrict__ qh_, const __nv_bfloat16* __restrict__ ql_,
    const __nv_bfloat16* __restrict__ wuh, const __nv_bfloat16* __restrict__ wul,
    float* __restrict__ u)
{
    extern __shared__ __align__(16) uint32_t gsm[];
    uint32_t bAh = smem_u32(gsm);
    uint32_t bAl = bAh + 1536 * 4;
    uint32_t bBh = bAh + 3072 * 4;
    uint32_t bBl = bAh + 9216 * 4;
    int h = blockIdx.y;
    GArg g = { qh_ + h * 128, ql_ + h * 128,
               wuh + (size_t)h * 65536, wul + (size_t)h * 65536,
               u + h * 512, 1024, 512, 128, 1024, 4096,
               nullptr, nullptr, nullptr };
    gemm_body(g, blockIdx.x % 2, blockIdx.x / 2, bAh, bAl, bBh, bBl);
}

// ---------------- z-GEMM: attn_s (64x128 tile, split-bf16 output) -----------
// Z2 ((H*T) x 512) @ WsvT_h (128 x 512) -> ash/asl (T x 1024) cols h*128..
__global__ __launch_bounds__(256, 2) void zgemm_kernel(
    const __nv_bfloat16* __restrict__ z2h, const __nv_bfloat16* __restrict__ z2l,
    const __nv_bfloat16* __restrict__ wrnh, const __nv_bfloat16* __restrict__ wrnl,
    __nv_bfloat16* __restrict__ ash, __nv_bfloat16* __restrict__ asl)
{
    __shared__ __align__(16) uint32_t sAh[3][64 * 8], sAl[3][64 * 8];
    __shared__ __align__(16) uint32_t sBh[3][128 * 8], sBl[3][128 * 8];
    uint32_t bAh = smem_u32(sAh), bAl = smem_u32(sAl);
    uint32_t bBh = smem_u32(sBh), bBl = smem_u32(sBl);

    int by = blockIdx.x;               // 0..127
    int gr0 = by * 64;
    int h = gr0 >> 10;
    int t_base = gr0 & 1023;

    int tid = threadIdx.x;
    int lane = tid & 31, wid = tid >> 5;
    int wm = wid & 1, wn = wid >> 1;
    int gid = lane >> 2, tig = lane & 3;

    float acc[2][4][4];
    #pragma unroll
    for (int i = 0; i < 2; i++)
        #pragma unroll
        for (int j = 0; j < 4; j++)
            #pragma unroll
            for (int l = 0; l < 4; l++) acc[i][j][l] = 0.f;

    uint32_t aoff0, aoff1, boff0, boff1;
    {
        int lrow = lane & 7;
        int rA = wm * 32 + lrow + (lane & 8);
        int cA = (lane & 16) >> 2;
        aoff0 = (uint32_t)(rA * 8 + cA) * 4;
        aoff1 = (uint32_t)((rA + 16) * 8 + cA) * 4;
        int rB = wn * 32 + lrow + ((lane & 16) >> 1);
        int cB = (lane & 8) >> 1;
        boff0 = (uint32_t)(rB * 8 + cB) * 4;
        boff1 = (uint32_t)((rB + 16) * 8 + cB) * 4;
    }

    const __nv_bfloat16* Bh = wrnh + (size_t)(1024 + h * 128) * 512;
    const __nv_bfloat16* Bl = wrnl + (size_t)(1024 + h * 128) * 512;
    auto issue = [&](int st, int k0) {
        uint32_t bdoff = (uint32_t)(st * 128 * 8 + (tid >> 1) * 8 + (tid & 1) * 4) * 4;
        size_t bsrc = (size_t)(tid >> 1) * 512 + k0 + (tid & 1) * 8;
        cp16(bBh + bdoff, Bh + bsrc);
        cp16(bBl + bdoff, Bl + bsrc);
        if (tid < 128) {
            uint32_t adoff = (uint32_t)(st * 64 * 8 + (tid >> 1) * 8 + (tid & 1) * 4) * 4;
            size_t asrc = (size_t)(gr0 + (tid >> 1)) * 512 + k0 + (tid & 1) * 8;
            cp16(bAh + adoff, z2h + asrc);
            cp16(bAl + adoff, z2l + asrc);
        }
        asm volatile("cp.async.commit_group;" ::: "memory");
    };

    int nch = 512 >> 4;   // 32
    issue(0, 0);
    issue(1, 16);

    for (int c = 0; c < nch; c++) {
        if (c + 1 < nch) {
            asm volatile("cp.async.wait_group 1;" ::: "memory");
        } else {
            asm volatile("cp.async.wait_group 0;" ::: "memory");
        }
        __syncthreads();
        if (c + 2 < nch) issue((c + 2) % 3, (c + 2) * 16);

        uint32_t aoffst = (uint32_t)((c % 3) * 64 * 8 * 4);
        uint32_t boffst = (uint32_t)((c % 3) * 128 * 8 * 4);

        uint32_t ah[2][4], al[2][4];
        ldm_x4(ah[0], bAh + aoffst + aoff0);
        ldm_x4(ah[1], bAh + aoffst + aoff1);
        ldm_x4(al[0], bAl + aoffst + aoff0);
        ldm_x4(al[1], bAl + aoffst + aoff1);

        #pragma unroll
        for (int p = 0; p < 2; p++) {
            uint32_t bh[4], bl[4];
            ldm_x4(bh, bBh + boffst + (p ? boff1 : boff0));
            ldm_x4(bl, bBl + boffst + (p ? boff1 : boff0));
            #pragma unroll
            for (int q = 0; q < 2; q++) {
                int nt = p * 2 + q;
                uint32_t b0h = bh[2 * q], b1h = bh[2 * q + 1];
                uint32_t b0l = bl[2 * q], b1l = bl[2 * q + 1];
                mma_bf16(acc[0][nt], ah[0], b0h, b1h);
                mma_bf16(acc[0][nt], ah[0], b0l, b1l);
                mma_bf16(acc[0][nt], al[0], b0h, b1h);
                mma_bf16(acc[1][nt], ah[1], b0h, b1h);
                mma_bf16(acc[1][nt], ah[1], b0l, b1l);
                mma_bf16(acc[1][nt], al[1], b0h, b1h);
            }
        }
    }

    #pragma unroll
    for (int mt = 0; mt < 2; mt++) {
        int t0 = t_base + wm * 32 + mt * 16 + gid;
        #pragma unroll
        for (int nt = 0; nt < 4; nt++) {
            int col = h * 128 + wn * 32 + nt * 8 + 2 * tig;
            uint32_t hh, ll;
            split2(acc[mt][nt][0], acc[mt][nt][1], hh, ll);
            ((uint32_t*)ash)[(size_t)t0 * 512 + col / 2] = hh;
            ((uint32_t*)asl)[(size_t)t0 * 512 + col / 2] = ll;
            split2(acc[mt][nt][2], acc[mt][nt][3], hh, ll);
            ((uint32_t*)ash)[(size_t)(t0 + 8) * 512 + col / 2] = hh;
            ((uint32_t*)asl)[(size_t)(t0 + 8) * 512 + col / 2] = ll;
        }
    }
}

// ---------------- conv: k/v pre-split + q split ----------------
__global__ __launch_bounds__(256) void conv_kv_kernel(
    const float* __restrict__ csn,
    uint32_t* __restrict__ kh, uint32_t* __restrict__ kl,
    uint32_t* __restrict__ vh, uint32_t* __restrict__ vl,
    uint32_t* __restrict__ qsh, uint32_t* __restrict__ qsl)
{
    int b = blockIdx.x;
    if (b < T_LEN) {
        int t = b, j = threadIdx.x;
        float2 v = *(const float2*)(csn + (size_t)t * N_SN + 1024 + 2 * j);
        uint32_t h, l;
        split2(v.x, v.y, h, l);
        kh[(size_t)t * 256 + j] = h;
        kl[(size_t)t * 256 + j] = l;
        return;
    }
    if (b < 2 * T_LEN) {
        int idx = (b - T_LEN) * 256 + threadIdx.x;
        int pp = idx & 511;
        int d = (idx >> 9) & 63;
        int h = idx >> 15;
        float v0 = csn[(size_t)(2 * pp) * N_SN + 1536 + h * DHR + d];
        float v1 = csn[(size_t)(2 * pp + 1) * N_SN + 1536 + h * DHR + d];
        uint32_t hh, ll;
        split2(v0, v1, hh, ll);
        vh[idx] = hh;
        vl[idx] = ll;
        return;
    }
    int t = b - 2 * T_LEN;
    #pragma unroll
    for (int it = 0; it < 2; it++) {
        int j2 = threadIdx.x + it * 256;    // 0..511
        float2 v = *(const float2*)(csn + (size_t)t * N_SN + 2 * j2);
        uint32_t h, l;
        split2(v.x, v.y, h, l);
        qsh[(size_t)t * 512 + j2] = h;
        qsl[(size_t)t * 512 + j2] = l;
    }
}

// ---------------- s-attention lite: logits from u, emit z/zsp ---------------
__global__ __launch_bounds__(256) void s_attn_lite(
    const float* __restrict__ u,            // (T, 4096)
    const __nv_bfloat16* __restrict__ rnh,
    const __nv_bfloat16* __restrict__ rnl,
    __nv_bfloat16* __restrict__ z2h, __nv_bfloat16* __restrict__ z2l,
    __nv_bfloat16* __restrict__ zsph, __nv_bfloat16* __restrict__ zspl)
{
    int t = blockIdx.x;
    int tid = threadIdx.x;
    int warp = tid >> 5, lane = tid & 31;

    __shared__ float us[4096];
    __shared__ float rn8[NSLOT][512];
    __shared__ float logits[HEADS][NSLOT];
    __shared__ float wattn[HEADS][NSLOT];
    __shared__ float wsp[NSLOT];

    for (int j = tid; j < 4096; j += 256)
        us[j] = u[(size_t)t * 4096 + j];
    const uint32_t* rh = (const uint32_t*)rnh + (size_t)t * 8 * 256;
    const uint32_t* rl = (const uint32_t*)rnl + (size_t)t * 8 * 256;
    for (int idx = tid; idx < 8 * 256; idx += 256) {
        uint32_t hh = rh[idx], ll = rl[idx];
        __nv_bfloat162 h2 = *(__nv_bfloat162*)&hh;
        __nv_bfloat162 l2 = *(__nv_bfloat162*)&ll;
        int n = idx >> 8, j2 = idx & 255;
        rn8[n][2 * j2] = __bfloat162float(h2.x) + __bfloat162float(l2.x);
        rn8[n][2 * j2 + 1] = __bfloat162float(h2.y) + __bfloat162float(l2.y);
    }
    __syncthreads();

    {
        int h = warp;
        #pragma unroll
        for (int n = 0; n < NSLOT; n++) {
            float p = 0.f;
            #pragma unroll
            for (int d = lane; d < 512; d += 32)
                p += rn8[n][d] * us[h * 512 + d];
            #pragma unroll
            for (int off = 16; off; off >>= 1)
                p += __shfl_xor_sync(0xffffffffu, p, off);
            if (lane == 0) logits[h][n] = p;
        }
    }
    __syncthreads();

    if (tid < HEADS) {
        int h = tid;
        float m = -INFINITY;
        #pragma unroll
        for (int n = 0; n < NSLOT; n++) m = fmaxf(m, logits[h][n] * SCALE_S);
        float sum = 0.f;
        #pragma unroll
        for (int n = 0; n < NSLOT; n++) {
            float e = __expf(logits[h][n] * SCALE_S - m);
            wattn[h][n] = e;
            sum += e;
        }
        float inv = 1.f / sum;
        #pragma unroll
        for (int n = 0; n < NSLOT; n++) wattn[h][n] *= inv;
    }
    if (tid == 8) {
        float sp[NSLOT];
        #pragma unroll
        for (int n = 0; n < NSLOT; n++) {
            float a = 0.f;
            #pragma unroll
            for (int h = 0; h < HEADS; h++) a += logits[h][n];
            sp[n] = a * SCALE_S;
        }
        bool sel[NSLOT];
        #pragma unroll
        for (int n = 0; n < NSLOT; n++) { sel[n] = false; wsp[n] = 0.f; }
        int idxs[TOPK];
        #pragma unroll
        for (int kk = 0; kk < TOPK; kk++) {
            int best = -1; float bv = -INFINITY;
            #pragma unroll
            for (int n = 0; n < NSLOT; n++)
                if (!sel[n] && sp[n] > bv) { bv = sp[n]; best = n; }
            sel[best] = true; idxs[kk] = best;
        }
        float m = -INFINITY;
        #pragma unroll
        for (int kk = 0; kk < TOPK; kk++) m = fmaxf(m, sp[idxs[kk]]);
        float sum = 0.f, e[TOPK];
        #pragma unroll
        for (int kk = 0; kk < TOPK; kk++) { e[kk] = __expf(sp[idxs[kk]] - m); sum += e[kk]; }
        float inv = 1.f / sum;
        #pragma unroll
        for (int kk = 0; kk < TOPK; kk++) wsp[idxs[kk]] = e[kk] * inv;
    }
    __syncthreads();

    // z[t,h] = sum_n wattn[h][n] * rn8[n]; row h*T+t in z2
    {
        int h = warp;
        uint32_t* zh = (uint32_t*)z2h + ((size_t)h * T_LEN + t) * 256;
        uint32_t* zl = (uint32_t*)z2l + ((size_t)h * T_LEN + t) * 256;
        for (int j2 = lane; j2 < 256; j2 += 32) {
            float z0 = 0.f, z1 = 0.f;
            #pragma unroll
            for (int n = 0; n < NSLOT; n++) {
                z0 += wattn[h][n] * rn8[n][2 * j2];
                z1 += wattn[h][n] * rn8[n][2 * j2 + 1];
            }
            uint32_t hh, ll;
            split2(z0, z1, hh, ll);
            zh[j2] = hh;
            zl[j2] = ll;
        }
    }
    // zsp[t] = sum_n wsp[n] * rn8[n]
    {
        int j2 = tid;   // 0..255
        float z0 = 0.f, z1 = 0.f;
        #pragma unroll
        for (int n = 0; n < NSLOT; n++) {
            z0 += wsp[n] * rn8[n][2 * j2];
            z1 += wsp[n] * rn8[n][2 * j2 + 1];
        }
        uint32_t hh, ll;
        split2(z0, z1, hh, ll);
        ((uint32_t*)zsph)[(size_t)t * 256 + j2] = hh;
        ((uint32_t*)zspl)[(size_t)t * 256 + j2] = ll;
    }
}

// ---------------- causal r-attention (identical to R13-R15 best) ------------
__global__ __launch_bounds__(128, 3) void r_attn_mma(
    const float* __restrict__ qr, int qld,
    const uint32_t* __restrict__ kh_g, const uint32_t* __restrict__ kl_g,
    const uint32_t* __restrict__ vh_g, const uint32_t* __restrict__ vl_g,
    __nv_bfloat16* __restrict__ ar_h, __nv_bfloat16* __restrict__ ar_l)
{
    extern __shared__ __align__(16) uint32_t dsm[];
    uint32_t bkh = smem_u32(dsm);
    uint32_t bkl = bkh + 16384;
    uint32_t bvh = bkh + 32768;
    uint32_t bvl = bkh + 49152;

    int tt = (int)(gridDim.x - 1 - blockIdx.x);
    int h = blockIdx.y;
    int t0 = tt * 8;
    int hb = h * DHR;

    int tid = threadIdx.x;
    int w = tid >> 5, lane = tid & 31;
    int gid = lane >> 2, tig = lane & 3;

    int r0 = t0 * 8 + 16 * w + gid;
    int r8 = r0 + 8;
    uint32_t qh[4][4], ql[4][4];
    #pragma unroll
    for (int kc = 0; kc < 4; kc++) {
        float2 x0 = *(const float2*)(qr + (size_t)r0 * qld + hb + kc * 16 + 2 * tig);
        float2 x1 = *(const float2*)(qr + (size_t)r8 * qld + hb + kc * 16 + 2 * tig);
        float2 x2 = *(const float2*)(qr + (size_t)r0 * qld + hb + kc * 16 + 2 * tig + 8);
        float2 x3 = *(const float2*)(qr + (size_t)r8 * qld + hb + kc * 16 + 2 * tig + 8);
        split2(x0.x * SCALE_R, x0.y * SCALE_R, qh[kc][0], ql[kc][0]);
        split2(x1.x * SCALE_R, x1.y * SCALE_R, qh[kc][1], ql[kc][1]);
        split2(x2.x * SCALE_R, x2.y * SCALE_R, qh[kc][2], ql[kc][2]);
        split2(x3.x * SCALE_R, x3.y * SCALE_R, qh[kc][3], ql[kc][3]);
    }
    int tok0 = t0 + ((16 * w + gid) >> 3);
    int tok8 = t0 + ((16 * w + gid + 8) >> 3);

    uint32_t rowoff[4];
    uint32_t swr[4];
    {
        int mrow = ((lane & 16) >> 1) + (lane & 7);
        #pragma unroll
        for (int p = 0; p < 4; p++) {
            int nr = p * 16 + mrow;
            rowoff[p] = (uint32_t)(nr * 128);
            swr[p] = (uint32_t)(nr & 7);
        }
    }
    int gsel = (lane & 8) >> 3;

    float m0 = -INFINITY, m1 = -INFINITY, l0 = 0.f, l1 = 0.f;
    float acco[8][4];
    #pragma unroll
    for (int i = 0; i < 8; i++)
        #pragma unroll
        for (int j = 0; j < 4; j++) acco[i][j] = 0.f;

    int ntiles = ((t0 + 7) >> 6) + 1;

    auto issueT = [&](int st, int p0) {
        int pp0 = p0 >> 1;
        #pragma unroll
        for (int it = 0; it < 4; it++) {
            int idx = tid + it * 128;
            int p = idx >> 3, g = idx & 7;
            uint32_t doff = (uint32_t)(st * 8192) +
                            (uint32_t)(p * 32 + ((g ^ (p & 7)) << 2)) * 4;
            size_t ksrc = (size_t)(p0 + p) * 256 + h * 32 + g * 4;
            cp16(bkh + doff, kh_g + ksrc);
            cp16(bkl + doff, kl_g + ksrc);
            size_t vsrc = (size_t)h * 32768 + (size_t)p * 512 + pp0 + g * 4;
            cp16(bvh + doff, vh_g + vsrc);
            cp16(bvl + doff, vl_g + vsrc);
        }
        asm volatile("cp.async.commit_group;" ::: "memory");
    };

    issueT(0, 0);

    for (int c = 0; c < ntiles; c++) {
        int p0 = c * 64;
        if (c + 1 < ntiles) {
            issueT((c + 1) & 1, (c + 1) * 64);
            asm volatile("cp.async.wait_group 1;" ::: "memory");
        } else {
            asm volatile("cp.async.wait_group 0;" ::: "memory");
        }
        __syncthreads();

        uint32_t stB = (uint32_t)((c & 1) * 8192);

        float s[8][4];
        #pragma unroll
        for (int i = 0; i < 8; i++)
            #pragma unroll
            for (int j = 0; j < 4; j++) s[i][j] = 0.f;

        #pragma unroll
        for (int p = 0; p < 4; p++) {
            #pragma unroll
            for (int kc = 0; kc < 4; kc++) {
                uint32_t off = stB + rowoff[p] +
                               ((uint32_t)((2 * kc + gsel) ^ swr[p]) << 4);
                uint32_t bh[4], bl[4];
                ldm_x4(bh, bkh + off);
                ldm_x4(bl, bkl + off);
                #pragma unroll
                for (int q = 0; q < 2; q++) {
                    int nt = 2 * p + q;
                    mma_bf16(s[nt], qh[kc], bh[2 * q], bh[2 * q + 1]);
                    mma_bf16(s[nt], qh[kc], bl[2 * q], bl[2 * q + 1]);
                    mma_bf16(s[nt], ql[kc], bh[2 * q], bh[2 * q + 1]);
                }
            }
        }

        if (p0 + 64 > t0) {
            #pragma unroll
            for (int nt = 0; nt < 8; nt++) {
                int pg = p0 + nt * 8 + 2 * tig;
                if (pg > tok0)     s[nt][0] = -INFINITY;
                if (pg + 1 > tok0) s[nt][1] = -INFINITY;
                if (pg > tok8)     s[nt][2] = -INFINITY;
                if (pg + 1 > tok8) s[nt][3] = -INFINITY;
            }
        }

        float mx0 = -INFINITY, mx1 = -INFINITY;
        #pragma unroll
        for (int nt = 0; nt < 8; nt++) {
            mx0 = fmaxf(mx0, fmaxf(s[nt][0], s[nt][1]));
            mx1 = fmaxf(mx1, fmaxf(s[nt][2], s[nt][3]));
        }
        mx0 = fmaxf(mx0, __shfl_xor_sync(0xffffffffu, mx0, 1));
        mx0 = fmaxf(mx0, __shfl_xor_sync(0xffffffffu, mx0, 2));
        mx1 = fmaxf(mx1, __shfl_xor_sync(0xffffffffu, mx1, 1));
        mx1 = fmaxf(mx1, __shfl_xor_sync(0xffffffffu, mx1, 2));
        float nm0 = fmaxf(m0, mx0), nm1 = fmaxf(m1, mx1);
        float cr0 = __expf(m0 - nm0), cr1 = __expf(m1 - nm1);
        m0 = nm0; m1 = nm1;

        float rs0 = 0.f, rs1 = 0.f;
        #pragma unroll
        for (int nt = 0; nt < 8; nt++) {
            s[nt][0] = __expf(s[nt][0] - nm0);
            s[nt][1] = __expf(s[nt][1] - nm0);
            s[nt][2] = __expf(s[nt][2] - nm1);
            s[nt][3] = __expf(s[nt][3] - nm1);
            rs0 += s[nt][0] + s[nt][1];
            rs1 += s[nt][2] + s[nt][3];
        }
        rs0 += __shfl_xor_sync(0xffffffffu, rs0, 1);
        rs0 += __shfl_xor_sync(0xffffffffu, rs0, 2);
        rs1 += __shfl_xor_sync(0xffffffffu, rs1, 1);
        rs1 += __shfl_xor_sync(0xffffffffu, rs1, 2);
        l0 = l0 * cr0 + rs0;
        l1 = l1 * cr1 + rs1;

        #pragma unroll
        for (int ntd = 0; ntd < 8; ntd++) {
            acco[ntd][0] *= cr0; acco[ntd][1] *= cr0;
            acco[ntd][2] *= cr1; acco[ntd][3] *= cr1;
        }

        #pragma unroll
        for (int kc = 0; kc < 4; kc++) {
            uint32_t pah[4], pal[4];
            split2(s[2 * kc][0],     s[2 * kc][1],     pah[0], pal[0]);
            split2(s[2 * kc][2],     s[2 * kc][3],     pah[1], pal[1]);
            split2(s[2 * kc + 1][0], s[2 * kc + 1][1], pah[2], pal[2]);
            split2(s[2 * kc + 1][2], s[2 * kc + 1][3], pah[3], pal[3]);
            #pragma unroll
            for (int p = 0; p < 4; p++) {
                uint32_t off = stB + rowoff[p] +
                               ((uint32_t)((2 * kc + gsel) ^ swr[p]) << 4);
                uint32_t bh[4], bl[4];
                ldm_x4(bh, bvh + off);
                ldm_x4(bl, bvl + off);
                #pragma unroll
                for (int q = 0; q < 2; q++) {
                    int ntd = 2 * p + q;
                    mma_bf16(acco[ntd], pah, bh[2 * q], bh[2 * q + 1]);
                    mma_bf16(acco[ntd], pah, bl[2 * q], bl[2 * q + 1]);
                    mma_bf16(acco[ntd], pal, bh[2 * q], bh[2 * q + 1]);
                }
            }
        }

        if (c + 1 < ntiles) __syncthreads();
    }

    float i0 = 1.f / l0, i1 = 1.f / l1;
    #pragma unroll
    for (int ntd = 0; ntd < 8; ntd++) {
        int col = hb + ntd * 8 + 2 * tig;
        uint32_t hh, ll;
        split2(acco[ntd][0] * i0, acco[ntd][1] * i0, hh, ll);
        *(uint32_t*)(ar_h + (size_t)r0 * DR + col) = hh;
        *(uint32_t*)(ar_l + (size_t)r0 * DR + col) = ll;
        split2(acco[ntd][2] * i1, acco[ntd][3] * i1, hh, ll);
        *(uint32_t*)(ar_h + (size_t)r8 * DR + col) = hh;
        *(uint32_t*)(ar_l + (size_t)r8 * DR + col) = ll;
    }
}

// ---------------- host launch ----------------
extern "C" void kernel_launch(void* const* d_in, const int* in_sizes, int n_in,
                              void* d_out, int out_size)
{
    const float* s      = (const float*)d_in[0];
    const float* r      = (const float*)d_in[1];
    const float* gate_v = (const float*)d_in[2];
    const float* nsw    = (const float*)d_in[3];
    const float* nrw    = (const float*)d_in[4];
    const float* Wsq    = (const float*)d_in[5];
    const float* Wsk    = (const float*)d_in[6];
    const float* Wsv    = (const float*)d_in[7];
    const float* Wso    = (const float*)d_in[8];
    const float* Wrq    = (const float*)d_in[9];
    const float* Wrk    = (const float*)d_in[10];
    const float* Wrv    = (const float*)d_in[11];
    const float* Wro    = (const float*)d_in[12];

    float* out_s = (float*)d_out;
    float* out_r = (float*)d_out + T_LEN * DS;

    __nv_bfloat16 *snh, *snl, *rnh, *rnl, *ash, *asl, *arh, *arl;
    __nv_bfloat16 *wsnh, *wsnl, *wrnh, *wrnl, *wsoh, *wsol, *wroh, *wrol;
    __nv_bfloat16 *wuh, *wul, *qsh, *qsl, *z2h, *z2l, *zsph, *zspl;
    float *csn, *crn, *rsp, *uu;
    uint32_t *kh, *kl, *vth, *vtl;
    cudaGetSymbolAddress((void**)&snh, g_sn_h);
    cudaGetSymbolAddress((void**)&snl, g_sn_l);
    cudaGetSymbolAddress((void**)&rnh, g_rn_h);
    cudaGetSymbolAddress((void**)&rnl, g_rn_l);
    cudaGetSymbolAddress((void**)&ash, g_as_h);
    cudaGetSymbolAddress((void**)&asl, g_as_l);
    cudaGetSymbolAddress((void**)&arh, g_ar_h);
    cudaGetSymbolAddress((void**)&arl, g_ar_l);
    cudaGetSymbolAddress((void**)&wsnh, g_wsn_h);
    cudaGetSymbolAddress((void**)&wsnl, g_wsn_l);
    cudaGetSymbolAddress((void**)&wrnh, g_wrn_h);
    cudaGetSymbolAddress((void**)&wrnl, g_wrn_l);
    cudaGetSymbolAddress((void**)&wsoh, g_wso_h);
    cudaGetSymbolAddress((void**)&wsol, g_wso_l);
    cudaGetSymbolAddress((void**)&wroh, g_wro_h);
    cudaGetSymbolAddress((void**)&wrol, g_wro_l);
    cudaGetSymbolAddress((void**)&wuh, g_wu_h);
    cudaGetSymbolAddress((void**)&wul, g_wu_l);
    cudaGetSymbolAddress((void**)&qsh, g_qs_h);
    cudaGetSymbolAddress((void**)&qsl, g_qs_l);
    cudaGetSymbolAddress((void**)&z2h, g_z2h);
    cudaGetSymbolAddress((void**)&z2l, g_z2l);
    cudaGetSymbolAddress((void**)&zsph, g_zsph);
    cudaGetSymbolAddress((void**)&zspl, g_zspl);
    cudaGetSymbolAddress((void**)&csn, g_csn);
    cudaGetSymbolAddress((void**)&crn, g_crn);
    cudaGetSymbolAddress((void**)&rsp, g_rsp);
    cudaGetSymbolAddress((void**)&uu, g_u);
    cudaGetSymbolAddress((void**)&kh, g_kh);
    cudaGetSymbolAddress((void**)&kl, g_kl);
    cudaGetSymbolAddress((void**)&vth, g_vth);
    cudaGetSymbolAddress((void**)&vtl, g_vtl);

    cudaFuncSetAttribute(r_attn_mma,
                         cudaFuncAttributeMaxDynamicSharedMemorySize, 65536);
    cudaFuncSetAttribute(gemm_pair,
                         cudaFuncAttributeMaxDynamicSharedMemorySize, G_SMEM);
    cudaFuncSetAttribute(gemm_one,
                         cudaFuncAttributeMaxDynamicSharedMemorySize, G_SMEM);
    cudaFuncSetAttribute(gemm_u,
                         cudaFuncAttributeMaxDynamicSharedMemorySize, G_SMEM);

    cudaStream_t s1;
    cudaStreamCreateWithFlags(&s1, cudaStreamNonBlocking);
    cudaEvent_t e0, e1;
    cudaEventCreateWithFlags(&e0, cudaEventDisableTiming);
    cudaEventCreateWithFlags(&e1, cudaEventDisableTiming);

    // ---- 1. prep ----
    prep_kernel<<<5632 + T_LEN + ROWS_R, 256>>>(
        Wsq, Wsk, Wsv, Wso, Wrq, Wrk, Wrv, Wro,
        wsnh, wsnl, wrnh, wrnl, wsoh, wsol, wroh, wrol, wuh, wul,
        s, nsw, snh, snl, r, nrw, rnh, rnl);

    // ---- 2. projection GEMMs: csn = sn@[Wsq|Wrk|Wrv]; crn = rn@WrqT ----
    {
        GArg g0 = {snh, snl, wsnh, wsnl, csn, T_LEN, N_SN, DS, DS, N_SN,
                   nullptr, nullptr, nullptr};
        GArg g1 = {rnh, rnl, wrnh + 2048 * 512, wrnl + 2048 * 512, crn,
                   ROWS_R, DR, DR, DR, DR, nullptr, nullptr, nullptr};
        int gx0 = N_SN / 256, gy0 = T_LEN / 64;    // 8 x 16 = 128
        int gx1 = DR / 256, gy1 = ROWS_R / 64;     // 2 x 128 = 256
        gemm_pair<<<gx0 * gy0 + gx1 * gy1, 256, G_SMEM>>>(
            g0, g1, gx0 * gy0, gx0, gx1);
    }

    // ---- 3. conv: kr/vr pre-split + q split ----
    conv_kv_kernel<<<3 * T_LEN, 256>>>(csn, kh, kl, vth, vtl,
                                       (uint32_t*)qsh, (uint32_t*)qsl);

    // ---- fork: chain B (r-branch) on s1 ----
    cudaEventRecord(e0, 0);
    cudaStreamWaitEvent(s1, e0, 0);

    r_attn_mma<<<dim3(T_LEN / 8, HEADS), 128, 65536, s1>>>(
        crn, DR, kh, kl, vth, vtl, arh, arl);
    {
        GArg gr = {arh, arl, wroh, wrol, out_r, ROWS_R, DR, DR, DR, DR,
                   r, nullptr, nullptr};
        gemm_one<<<(DR / 256) * (ROWS_R / 64), 256, G_SMEM, s1>>>(gr, DR / 256);
    }
    cudaEventRecord(e1, s1);

    // ---- chain A (s-branch) on stream 0 ----
    gemm_u<<<dim3(32, 8), 256, G_SMEM>>>(qsh, qsl, wuh, wul, uu);
    s_attn_lite<<<T_LEN, 256>>>(uu, rnh, rnl, z2h, z2l, zsph, zspl);
    zgemm_kernel<<<128, 256>>>(z2h, z2l, wrnh, wrnl, ash, asl);
    {
        GArg gp = {zsph, zspl, wrnh + 1024 * 512, wrnl + 1024 * 512, rsp,
                   T_LEN, DS, DR, DR, DS, nullptr, nullptr, nullptr};
        gemm_one<<<(DS / 256) * (T_LEN / 64), 256, G_SMEM>>>(gp, DS / 256);
    }
    {
        GArg gs = {ash, asl, wsoh, wsol, out_s, T_LEN, DS, DS, DS, DS,
                   s, rsp, gate_v};
        gemm_one<<<(DS / 256) * (T_LEN / 64), 256, G_SMEM>>>(gs, DS / 256);
    }

    // ---- join ----
    cudaStreamWaitEvent(0, e1, 0);

    cudaStreamCaptureStatus cs = cudaStreamCaptureStatusNone;
    cudaStreamIsCapturing(s1, &cs);
    if (cs == cudaStreamCaptureStatusNone) {
        cudaEventDestroy(e0);
        cudaEventDestroy(e1);
        cudaStreamDestroy(s1);
    }
}

// round 17
// speedup vs baseline: 1.2929x; 1.0096x over previous
#include <cuda_runtime.h>
#include <cuda_bf16.h>
#include <math.h>
#include <stdint.h>

// ---------------- problem constants ----------------
#define T_LEN 1024
#define NSLOT 8
#define DS 1024
#define DR 512
#define HEADS 8
#define DHS 128
#define DHR 64
#define TOPK 4
#define ROWS_R (T_LEN * NSLOT)   // 8192
#define SCALE_S 0.08838834764831845f  // 1/sqrt(128)
#define SCALE_R 0.125f                // 1/sqrt(64)
#define EPS 1e-6f

// fused layouts
#define N_SN 2048        // q(1024) | kr(512) | vr(512), K=1024

// gemm dynamic smem: [Ah 3x512][Al 3x512][Bh 3x2048][Bl 3x2048] u32 = 60KB
#define G_SMEM 61440

// ---------------- scratch (static device memory; no allocation) -------------
__device__ __nv_bfloat16 g_sn_h[T_LEN * DS], g_sn_l[T_LEN * DS];
__device__ __nv_bfloat16 g_rn_h[ROWS_R * DR], g_rn_l[ROWS_R * DR];
__device__ __nv_bfloat16 g_as_h[T_LEN * DS], g_as_l[T_LEN * DS];
__device__ __nv_bfloat16 g_ar_h[ROWS_R * DR], g_ar_l[ROWS_R * DR];
__device__ __nv_bfloat16 g_wsn_h[N_SN * DS], g_wsn_l[N_SN * DS];
__device__ __nv_bfloat16 g_wrn_h[2560 * DR], g_wrn_l[2560 * DR]; // WskT|WsvT|WrqT
__device__ __nv_bfloat16 g_wso_h[DS * DS], g_wso_l[DS * DS];
__device__ __nv_bfloat16 g_wro_h[DR * DR], g_wro_l[DR * DR];
__device__ __nv_bfloat16 g_wu_h[HEADS * 512 * 128], g_wu_l[HEADS * 512 * 128];
__device__ __nv_bfloat16 g_qs_h[T_LEN * DS], g_qs_l[T_LEN * DS];
__device__ __nv_bfloat16 g_z2h[ROWS_R * DR], g_z2l[ROWS_R * DR];   // (h*T+t, 512)
__device__ __nv_bfloat16 g_zsph[T_LEN * DR], g_zspl[T_LEN * DR];   // gate-scaled
__device__ float g_csn[T_LEN * N_SN];     // q | kr | vr
__device__ float g_crn[ROWS_R * DR];      // qr only
__device__ float g_u[T_LEN * 4096];       // u[t][h*512+i]
__device__ uint32_t g_kh[T_LEN * 256], g_kl[T_LEN * 256];
__device__ uint32_t g_vth[HEADS * DHR * (T_LEN / 2)];
__device__ uint32_t g_vtl[HEADS * DHR * (T_LEN / 2)];

// ---------------- PTX helpers ----------------
__device__ __forceinline__ uint32_t smem_u32(const void* p) {
    uint32_t a;
    asm("{ .reg .u64 t; cvta.to.shared.u64 t, %1; cvt.u32.u64 %0, t; }"
        : "=r"(a) : "l"(p));
    return a;
}
__device__ __forceinline__ void cp16(uint32_t dst, const void* src) {
    asm volatile("cp.async.cg.shared.global [%0], [%1], 16;"
                 :: "r"(dst), "l"(src) : "memory");
}
__device__ __forceinline__ void ldm_x4(uint32_t* r, uint32_t addr) {
    asm volatile("ldmatrix.sync.aligned.m8n8.x4.shared.b16 {%0,%1,%2,%3}, [%4];"
                 : "=r"(r[0]), "=r"(r[1]), "=r"(r[2]), "=r"(r[3]) : "r"(addr));
}
__device__ __forceinline__ void mma_bf16(
    float* c, const uint32_t* a, uint32_t b0, uint32_t b1)
{
    asm volatile(
        "mma.sync.aligned.m16n8k16.row.col.f32.bf16.bf16.f32 "
        "{%0,%1,%2,%3}, {%4,%5,%6,%7}, {%8,%9}, {%0,%1,%2,%3};"
        : "+f"(c[0]), "+f"(c[1]), "+f"(c[2]), "+f"(c[3])
        : "r"(a[0]), "r"(a[1]), "r"(a[2]), "r"(a[3]), "r"(b0), "r"(b1));
}
__device__ __forceinline__ void split2(float x, float y,
                                       uint32_t& hi, uint32_t& lo)
{
    __nv_bfloat162 h = __floats2bfloat162_rn(x, y);
    float xr = x - __bfloat162float(h.x);
    float yr = y - __bfloat162float(h.y);
    __nv_bfloat162 l = __floats2bfloat162_rn(xr, yr);
    hi = *(uint32_t*)&h;
    lo = *(uint32_t*)&l;
}

// ---------------- merged prep: transposes + wu copy + rmsnorms --------------
__global__ __launch_bounds__(256) void prep_kernel(
    const float* __restrict__ Wsq, const float* __restrict__ Wsk,
    const float* __restrict__ Wsv, const float* __restrict__ Wso,
    const float* __restrict__ Wrq, const float* __restrict__ Wrk,
    const float* __restrict__ Wrv, const float* __restrict__ Wro,
    __nv_bfloat16* __restrict__ wsnh, __nv_bfloat16* __restrict__ wsnl,
    __nv_bfloat16* __restrict__ wrnh, __nv_bfloat16* __restrict__ wrnl,
    __nv_bfloat16* __restrict__ wsoh, __nv_bfloat16* __restrict__ wsol,
    __nv_bfloat16* __restrict__ wroh, __nv_bfloat16* __restrict__ wrol,
    __nv_bfloat16* __restrict__ wuh, __nv_bfloat16* __restrict__ wul,
    const float* __restrict__ s, const float* __restrict__ nsw,
    __nv_bfloat16* __restrict__ snh, __nv_bfloat16* __restrict__ snl,
    const float* __restrict__ r, const float* __restrict__ nrw,
    __nv_bfloat16* __restrict__ rnh, __nv_bfloat16* __restrict__ rnl)
{
    int b = blockIdx.x;
    if (b < 4608) {
        const float* W;
        __nv_bfloat16 *th, *tl;
        int K, N;
        if (b < 1024)      { W = Wsq; th = wsnh; tl = wsnl; K = 1024; N = 1024; }
        else if (b < 1536) { b -= 1024; W = Wrk; th = wsnh + 1024 * 1024;
                             tl = wsnl + 1024 * 1024; K = 1024; N = 512; }
        else if (b < 2048) { b -= 1536; W = Wrv; th = wsnh + 1536 * 1024;
                             tl = wsnl + 1536 * 1024; K = 1024; N = 512; }
        else if (b < 2560) { b -= 2048; W = Wsk; th = wrnh; tl = wrnl;
                             K = 512; N = 1024; }
        else if (b < 3072) { b -= 2560; W = Wsv; th = wrnh + 1024 * 512;
                             tl = wrnl + 1024 * 512; K = 512; N = 1024; }
        else if (b < 3328) { b -= 3072; W = Wrq; th = wrnh + 2048 * 512;
                             tl = wrnl + 2048 * 512; K = 512; N = 512; }
        else if (b < 4352) { b -= 3328; W = Wso; th = wsoh; tl = wsol;
                             K = 1024; N = 1024; }
        else               { b -= 4352; W = Wro; th = wroh; tl = wrol;
                             K = 512; N = 512; }

        int ntx = N >> 5;
        int bx = (b % ntx) * 32;
        int by = (b / ntx) * 32;

        __shared__ float t[32][33];
        int tx = threadIdx.x & 31, ty = threadIdx.x >> 5;
        #pragma unroll
        for (int i = 0; i < 4; i++)
            t[ty + i * 8][tx] = W[(size_t)(by + ty + i * 8) * N + bx + tx];
        __syncthreads();
        #pragma unroll
        for (int i = 0; i < 4; i++) {
            int n = bx + ty + i * 8;
            int k = by + tx;
            float v = t[tx][ty + i * 8];
            __nv_bfloat16 h = __float2bfloat16(v);
            th[(size_t)n * K + k] = h;
            tl[(size_t)n * K + k] = __float2bfloat16(v - __bfloat162float(h));
        }
        return;
    }
    if (b < 5632) {
        int idx = (b - 4608) * 256 + threadIdx.x;
        int o = idx * 2;
        int h = o >> 16;
        int rem = o & 65535;
        int i = rem >> 7;
        int j = rem & 127;
        float2 v = *(const float2*)(Wsk + (size_t)i * 1024 + h * 128 + j);
        uint32_t hh, ll;
        split2(v.x, v.y, hh, ll);
        ((uint32_t*)wuh)[idx] = hh;
        ((uint32_t*)wul)[idx] = ll;
        return;
    }
    const float *x, *w;
    __nv_bfloat16 *oh, *ol;
    int C, row;
    if (b < 5632 + T_LEN) {
        row = b - 5632; x = s; w = nsw; oh = snh; ol = snl; C = DS;
    } else {
        row = b - 5632 - T_LEN; x = r; w = nrw; oh = rnh; ol = rnl; C = DR;
    }
    const float* xr = x + (size_t)row * C;
    float acc = 0.f;
    for (int j = threadIdx.x; j < C; j += 256) {
        float v = xr[j];
        acc += v * v;
    }
    __shared__ float red[8];
    int lane = threadIdx.x & 31, warp = threadIdx.x >> 5;
    #pragma unroll
    for (int off = 16; off; off >>= 1) acc += __shfl_xor_sync(0xffffffffu, acc, off);
    if (lane == 0) red[warp] = acc;
    __syncthreads();
    __shared__ float scale;
    if (threadIdx.x == 0) {
        float tot = 0.f;
        #pragma unroll
        for (int i = 0; i < 8; i++) tot += red[i];
        scale = rsqrtf(tot / (float)C + EPS);
    }
    __syncthreads();
    float sc = scale;
    uint32_t* ph = (uint32_t*)(oh + (size_t)row * C);
    uint32_t* pl = (uint32_t*)(ol + (size_t)row * C);
    for (int j2 = threadIdx.x; j2 < C / 2; j2 += 256) {
        float v0 = xr[2 * j2] * sc * w[2 * j2];
        float v1 = xr[2 * j2 + 1] * sc * w[2 * j2 + 1];
        uint32_t h, l;
        split2(v0, v1, h, l);
        ph[j2] = h;
        pl[j2] = l;
    }
}

// ---------------- bf16-split mma GEMM body (64x256 tile, warp 32x64) --------
struct GArg {
    const __nv_bfloat16 *Ah, *Al, *Bh, *Bl;
    float* C;
    int M, N, K, lda, ldc;
    const float *add1, *add2, *rowscale;
};

__device__ __forceinline__ void gemm_body(
    const GArg g, int bx, int by,
    uint32_t bAh, uint32_t bAl, uint32_t bBh, uint32_t bBl)
{
    int tid = threadIdx.x;
    int lane = tid & 31, wid = tid >> 5;
    int wm = wid & 1, wn = wid >> 1;
    int bm = by * 64, bn = bx * 256;
    int gid = lane >> 2, tig = lane & 3;
    int K = g.K, lda = g.lda;

    float acc[2][8][4];
    #pragma unroll
    for (int i = 0; i < 2; i++)
        #pragma unroll
        for (int j = 0; j < 8; j++)
            #pragma unroll
            for (int l = 0; l < 4; l++) acc[i][j][l] = 0.f;

    uint32_t aoff0, aoff1, boff[4];
    {
        int lrow = lane & 7;
        int rA = wm * 32 + lrow + (lane & 8);
        int cA = (lane & 16) >> 2;
        aoff0 = (uint32_t)(rA * 8 + cA) * 4;
        aoff1 = (uint32_t)((rA + 16) * 8 + cA) * 4;
        int rB = wn * 64 + lrow + ((lane & 16) >> 1);
        int cB = (lane & 8) >> 1;
        #pragma unroll
        for (int p = 0; p < 4; p++)
            boff[p] = (uint32_t)((rB + p * 16) * 8 + cB) * 4;
    }

    const __nv_bfloat16 *Ah = g.Ah, *Al = g.Al, *Bh = g.Bh, *Bl = g.Bl;
    auto issue = [&](int st, int k0) {
        #pragma unroll
        for (int it = 0; it < 2; it++) {
            int idx = tid + it * 256;
            int row = idx >> 1, gg = idx & 1;
            uint32_t bdoff = (uint32_t)(st * 256 * 8 + row * 8 + gg * 4) * 4;
            size_t bsrc = (size_t)(bn + row) * K + k0 + gg * 8;
            cp16(bBh + bdoff, Bh + bsrc);
            cp16(bBl + bdoff, Bl + bsrc);
        }
        if (tid < 128) {
            int row = tid >> 1, gg = tid & 1;
            uint32_t adoff = (uint32_t)(st * 64 * 8 + row * 8 + gg * 4) * 4;
            size_t asrc = (size_t)(bm + row) * lda + k0 + gg * 8;
            cp16(bAh + adoff, Ah + asrc);
            cp16(bAl + adoff, Al + asrc);
        }
        asm volatile("cp.async.commit_group;" ::: "memory");
    };

    int nch = K >> 4;
    issue(0, 0);
    if (nch > 1) issue(1, 16);

    for (int c = 0; c < nch; c++) {
        if (c + 1 < nch) {
            asm volatile("cp.async.wait_group 1;" ::: "memory");
        } else {
            asm volatile("cp.async.wait_group 0;" ::: "memory");
        }
        __syncthreads();
        if (c + 2 < nch) issue((c + 2) % 3, (c + 2) * 16);

        uint32_t aoffst = (uint32_t)((c % 3) * 64 * 8 * 4);
        uint32_t boffst = (uint32_t)((c % 3) * 256 * 8 * 4);

        uint32_t ah[2][4], al[2][4], bh[4][4], bl[4][4];
        ldm_x4(ah[0], bAh + aoffst + aoff0);
        ldm_x4(ah[1], bAh + aoffst + aoff1);
        ldm_x4(al[0], bAl + aoffst + aoff0);
        ldm_x4(al[1], bAl + aoffst + aoff1);
        #pragma unroll
        for (int p = 0; p < 4; p++) {
            ldm_x4(bh[p], bBh + boffst + boff[p]);
            ldm_x4(bl[p], bBl + boffst + boff[p]);
        }

        #pragma unroll
        for (int nt = 0; nt < 8; nt++) {
            int p = nt >> 1, q2 = (nt & 1) << 1;
            uint32_t b0h = bh[p][q2], b1h = bh[p][q2 + 1];
            uint32_t b0l = bl[p][q2], b1l = bl[p][q2 + 1];
            mma_bf16(acc[0][nt], ah[0], b0h, b1h);
            mma_bf16(acc[0][nt], ah[0], b0l, b1l);
            mma_bf16(acc[0][nt], al[0], b0h, b1h);
            mma_bf16(acc[1][nt], ah[1], b0h, b1h);
            mma_bf16(acc[1][nt], ah[1], b0l, b1l);
            mma_bf16(acc[1][nt], al[1], b0h, b1h);
        }
    }

    #pragma unroll
    for (int mt = 0; mt < 2; mt++) {
        int r0 = bm + wm * 32 + mt * 16 + gid;
        float rs0 = (g.rowscale != nullptr) ? g.rowscale[r0] : 0.f;
        float rs8 = (g.rowscale != nullptr) ? g.rowscale[r0 + 8] : 0.f;
        #pragma unroll
        for (int nt = 0; nt < 8; nt++) {
            int col = bn + wn * 64 + nt * 8 + 2 * tig;
            size_t o0 = (size_t)r0 * g.ldc + col;
            size_t o8 = (size_t)(r0 + 8) * g.ldc + col;
            float2 v0 = make_float2(acc[mt][nt][0], acc[mt][nt][1]);
            float2 v8 = make_float2(acc[mt][nt][2], acc[mt][nt][3]);
            if (g.add1) {
                float2 x = *(const float2*)(g.add1 + o0);
                v0.x += x.x; v0.y += x.y;
                x = *(const float2*)(g.add1 + o8);
                v8.x += x.x; v8.y += x.y;
            }
            if (g.add2) {
                float2 x = *(const float2*)(g.add2 + o0);
                v0.x += rs0 * x.x; v0.y += rs0 * x.y;
                x = *(const float2*)(g.add2 + o8);
                v8.x += rs8 * x.x; v8.y += rs8 * x.y;
            }
            *(float2*)(g.C + o0) = v0;
            *(float2*)(g.C + o8) = v8;
        }
    }
}

__global__ __launch_bounds__(256, 2) void gemm_pair(
    GArg g0, GArg g1, int nblk0, int gx0, int gx1)
{
    extern __shared__ __align__(16) uint32_t gsm[];
    uint32_t bAh = smem_u32(gsm);
    uint32_t bAl = bAh + 1536 * 4;
    uint32_t bBh = bAh + 3072 * 4;
    uint32_t bBl = bAh + 9216 * 4;

    int b = blockIdx.x;
    if (b < nblk0)
        gemm_body(g0, b % gx0, b / gx0, bAh, bAl, bBh, bBl);
    else {
        b -= nblk0;
        gemm_body(g1, b % gx1, b / gx1, bAh, bAl, bBh, bBl);
    }
}

__global__ __launch_bounds__(256, 2) void gemm_one(GArg g, int gx)
{
    extern __shared__ __align__(16) uint32_t gsm[];
    uint32_t bAh = smem_u32(gsm);
    uint32_t bAl = bAh + 1536 * 4;
    uint32_t bBh = bAh + 3072 * 4;
    uint32_t bBl = bAh + 9216 * 4;
    gemm_body(g, blockIdx.x % gx, blockIdx.x / gx, bAh, bAl, bBh, bBl);
}

// batched-per-head u-GEMM: u[t][h*512+i] = q_h @ Wsk_h^T
__global__ __launch_bounds__(256, 2) void gemm_u(
    const __nv_bfloat16* __restrict__ qh_, const __nv_bfloat16* __restrict__ ql_,
    const __nv_bfloat16* __restrict__ wuh, const __nv_bfloat16* __restrict__ wul,
    float* __restrict__ u)
{
    extern __shared__ __align__(16) uint32_t gsm[];
    uint32_t bAh = smem_u32(gsm);
    uint32_t bAl = bAh + 1536 * 4;
    uint32_t bBh = bAh + 3072 * 4;
    uint32_t bBl = bAh + 9216 * 4;
    int h = blockIdx.y;
    GArg g = { qh_ + h * 128, ql_ + h * 128,
               wuh + (size_t)h * 65536, wul + (size_t)h * 65536,
               u + h * 512, 1024, 512, 128, 1024, 4096,
               nullptr, nullptr, nullptr };
    gemm_body(g, blockIdx.x % 2, blockIdx.x / 2, bAh, bAl, bBh, bBl);
}

// ---------------- dual-segment output GEMM ----------------
// out_s = ash@Wso^T (K=1024) + zspg@Wsv^T (K=512) + s
__global__ __launch_bounds__(256, 2) void gemm_dual(
    const __nv_bfloat16* __restrict__ A1h, const __nv_bfloat16* __restrict__ A1l,
    const __nv_bfloat16* __restrict__ B1h, const __nv_bfloat16* __restrict__ B1l,
    const __nv_bfloat16* __restrict__ A2h, const __nv_bfloat16* __restrict__ A2l,
    const __nv_bfloat16* __restrict__ B2h, const __nv_bfloat16* __restrict__ B2l,
    float* __restrict__ C, const float* __restrict__ add1)
{
    extern __shared__ __align__(16) uint32_t gsm[];
    uint32_t bAh = smem_u32(gsm);
    uint32_t bAl = bAh + 1536 * 4;
    uint32_t bBh = bAh + 3072 * 4;
    uint32_t bBl = bAh + 9216 * 4;

    int bx = blockIdx.x & 3, by = blockIdx.x >> 2;   // gx=4 (N=1024/256)
    int tid = threadIdx.x;
    int lane = tid & 31, wid = tid >> 5;
    int wm = wid & 1, wn = wid >> 1;
    int bm = by * 64, bn = bx * 256;
    int gid = lane >> 2, tig = lane & 3;

    float acc[2][8][4];
    #pragma unroll
    for (int i = 0; i < 2; i++)
        #pragma unroll
        for (int j = 0; j < 8; j++)
            #pragma unroll
            for (int l = 0; l < 4; l++) acc[i][j][l] = 0.f;

    uint32_t aoff0, aoff1, boff[4];
    {
        int lrow = lane & 7;
        int rA = wm * 32 + lrow + (lane & 8);
        int cA = (lane & 16) >> 2;
        aoff0 = (uint32_t)(rA * 8 + cA) * 4;
        aoff1 = (uint32_t)((rA + 16) * 8 + cA) * 4;
        int rB = wn * 64 + lrow + ((lane & 16) >> 1);
        int cB = (lane & 8) >> 1;
        #pragma unroll
        for (int p = 0; p < 4; p++)
            boff[p] = (uint32_t)((rB + p * 16) * 8 + cB) * 4;
    }

    const int NCH1 = 64;   // K1=1024
    const int NCH = 96;    // + K2=512
    auto issue = [&](int st, int c) {
        const __nv_bfloat16 *Ah, *Al, *Bh, *Bl;
        int k0, kst;
        if (c < NCH1) { k0 = c * 16; Ah = A1h; Al = A1l; Bh = B1h; Bl = B1l; kst = 1024; }
        else { k0 = (c - NCH1) * 16; Ah = A2h; Al = A2l; Bh = B2h; Bl = B2l; kst = 512; }
        #pragma unroll
        for (int it = 0; it < 2; it++) {
            int idx = tid + it * 256;
            int row = idx >> 1, gg = idx & 1;
            uint32_t bdoff = (uint32_t)(st * 256 * 8 + row * 8 + gg * 4) * 4;
            size_t bsrc = (size_t)(bn + row) * kst + k0 + gg * 8;
            cp16(bBh + bdoff, Bh + bsrc);
            cp16(bBl + bdoff, Bl + bsrc);
        }
        if (tid < 128) {
            int row = tid >> 1, gg = tid & 1;
            uint32_t adoff = (uint32_t)(st * 64 * 8 + row * 8 + gg * 4) * 4;
            size_t asrc = (size_t)(bm + row) * kst + k0 + gg * 8;
            cp16(bAh + adoff, Ah + asrc);
            cp16(bAl + adoff, Al + asrc);
        }
        asm volatile("cp.async.commit_group;" ::: "memory");
    };

    issue(0, 0);
    issue(1, 1);

    for (int c = 0; c < NCH; c++) {
        if (c + 1 < NCH) {
            asm volatile("cp.async.wait_group 1;" ::: "memory");
        } else {
            asm volatile("cp.async.wait_group 0;" ::: "memory");
        }
        __syncthreads();
        if (c + 2 < NCH) issue((c + 2) % 3, c + 2);

        uint32_t aoffst = (uint32_t)((c % 3) * 64 * 8 * 4);
        uint32_t boffst = (uint32_t)((c % 3) * 256 * 8 * 4);

        uint32_t ah[2][4], al[2][4], bh[4][4], bl[4][4];
        ldm_x4(ah[0], bAh + aoffst + aoff0);
        ldm_x4(ah[1], bAh + aoffst + aoff1);
        ldm_x4(al[0], bAl + aoffst + aoff0);
        ldm_x4(al[1], bAl + aoffst + aoff1);
        #pragma unroll
        for (int p = 0; p < 4; p++) {
            ldm_x4(bh[p], bBh + boffst + boff[p]);
            ldm_x4(bl[p], bBl + boffst + boff[p]);
        }

        #pragma unroll
        for (int nt = 0; nt < 8; nt++) {
            int p = nt >> 1, q2 = (nt & 1) << 1;
            uint32_t b0h = bh[p][q2], b1h = bh[p][q2 + 1];
            uint32_t b0l = bl[p][q2], b1l = bl[p][q2 + 1];
            mma_bf16(acc[0][nt], ah[0], b0h, b1h);
            mma_bf16(acc[0][nt], ah[0], b0l, b1l);
            mma_bf16(acc[0][nt], al[0], b0h, b1h);
            mma_bf16(acc[1][nt], ah[1], b0h, b1h);
            mma_bf16(acc[1][nt], ah[1], b0l, b1l);
            mma_bf16(acc[1][nt], al[1], b0h, b1h);
        }
    }

    #pragma unroll
    for (int mt = 0; mt < 2; mt++) {
        int r0 = bm + wm * 32 + mt * 16 + gid;
        #pragma unroll
        for (int nt = 0; nt < 8; nt++) {
            int col = bn + wn * 64 + nt * 8 + 2 * tig;
            size_t o0 = (size_t)r0 * DS + col;
            size_t o8 = (size_t)(r0 + 8) * DS + col;
            float2 v0 = make_float2(acc[mt][nt][0], acc[mt][nt][1]);
            float2 v8 = make_float2(acc[mt][nt][2], acc[mt][nt][3]);
            float2 x = *(const float2*)(add1 + o0);
            v0.x += x.x; v0.y += x.y;
            x = *(const float2*)(add1 + o8);
            v8.x += x.x; v8.y += x.y;
            *(float2*)(C + o0) = v0;
            *(float2*)(C + o8) = v8;
        }
    }
}

// ---------------- z-GEMM: attn_s (64x128 tile, split-bf16 output) -----------
__global__ __launch_bounds__(256, 2) void zgemm_kernel(
    const __nv_bfloat16* __restrict__ z2h, const __nv_bfloat16* __restrict__ z2l,
    const __nv_bfloat16* __restrict__ wrnh, const __nv_bfloat16* __restrict__ wrnl,
    __nv_bfloat16* __restrict__ ash, __nv_bfloat16* __restrict__ asl)
{
    __shared__ __align__(16) uint32_t sAh[3][64 * 8], sAl[3][64 * 8];
    __shared__ __align__(16) uint32_t sBh[3][128 * 8], sBl[3][128 * 8];
    uint32_t bAh = smem_u32(sAh), bAl = smem_u32(sAl);
    uint32_t bBh = smem_u32(sBh), bBl = smem_u32(sBl);

    int by = blockIdx.x;
    int gr0 = by * 64;
    int h = gr0 >> 10;
    int t_base = gr0 & 1023;

    int tid = threadIdx.x;
    int lane = tid & 31, wid = tid >> 5;
    int wm = wid & 1, wn = wid >> 1;
    int gid = lane >> 2, tig = lane & 3;

    float acc[2][4][4];
    #pragma unroll
    for (int i = 0; i < 2; i++)
        #pragma unroll
        for (int j = 0; j < 4; j++)
            #pragma unroll
            for (int l = 0; l < 4; l++) acc[i][j][l] = 0.f;

    uint32_t aoff0, aoff1, boff0, boff1;
    {
        int lrow = lane & 7;
        int rA = wm * 32 + lrow + (lane & 8);
        int cA = (lane & 16) >> 2;
        aoff0 = (uint32_t)(rA * 8 + cA) * 4;
        aoff1 = (uint32_t)((rA + 16) * 8 + cA) * 4;
        int rB = wn * 32 + lrow + ((lane & 16) >> 1);
        int cB = (lane & 8) >> 1;
        boff0 = (uint32_t)(rB * 8 + cB) * 4;
        boff1 = (uint32_t)((rB + 16) * 8 + cB) * 4;
    }

    const __nv_bfloat16* Bh = wrnh + (size_t)(1024 + h * 128) * 512;
    const __nv_bfloat16* Bl = wrnl + (size_t)(1024 + h * 128) * 512;
    auto issue = [&](int st, int k0) {
        uint32_t bdoff = (uint32_t)(st * 128 * 8 + (tid >> 1) * 8 + (tid & 1) * 4) * 4;
        size_t bsrc = (size_t)(tid >> 1) * 512 + k0 + (tid & 1) * 8;
        cp16(bBh + bdoff, Bh + bsrc);
        cp16(bBl + bdoff, Bl + bsrc);
        if (tid < 128) {
            uint32_t adoff = (uint32_t)(st * 64 * 8 + (tid >> 1) * 8 + (tid & 1) * 4) * 4;
            size_t asrc = (size_t)(gr0 + (tid >> 1)) * 512 + k0 + (tid & 1) * 8;
            cp16(bAh + adoff, z2h + asrc);
            cp16(bAl + adoff, z2l + asrc);
        }
        asm volatile("cp.async.commit_group;" ::: "memory");
    };

    int nch = 512 >> 4;
    issue(0, 0);
    issue(1, 16);

    for (int c = 0; c < nch; c++) {
        if (c + 1 < nch) {
            asm volatile("cp.async.wait_group 1;" ::: "memory");
        } else {
            asm volatile("cp.async.wait_group 0;" ::: "memory");
        }
        __syncthreads();
        if (c + 2 < nch) issue((c + 2) % 3, (c + 2) * 16);

        uint32_t aoffst = (uint32_t)((c % 3) * 64 * 8 * 4);
        uint32_t boffst = (uint32_t)((c % 3) * 128 * 8 * 4);

        uint32_t ah[2][4], al[2][4];
        ldm_x4(ah[0], bAh + aoffst + aoff0);
        ldm_x4(ah[1], bAh + aoffst + aoff1);
        ldm_x4(al[0], bAl + aoffst + aoff0);
        ldm_x4(al[1], bAl + aoffst + aoff1);

        #pragma unroll
        for (int p = 0; p < 2; p++) {
            uint32_t bh[4], bl[4];
            ldm_x4(bh, bBh + boffst + (p ? boff1 : boff0));
            ldm_x4(bl, bBl + boffst + (p ? boff1 : boff0));
            #pragma unroll
            for (int q = 0; q < 2; q++) {
                int nt = p * 2 + q;
                uint32_t b0h = bh[2 * q], b1h = bh[2 * q + 1];
                uint32_t b0l = bl[2 * q], b1l = bl[2 * q + 1];
                mma_bf16(acc[0][nt], ah[0], b0h, b1h);
                mma_bf16(acc[0][nt], ah[0], b0l, b1l);
                mma_bf16(acc[0][nt], al[0], b0h, b1h);
                mma_bf16(acc[1][nt], ah[1], b0h, b1h);
                mma_bf16(acc[1][nt], ah[1], b0l, b1l);
                mma_bf16(acc[1][nt], al[1], b0h, b1h);
            }
        }
    }

    #pragma unroll
    for (int mt = 0; mt < 2; mt++) {
        int t0 = t_base + wm * 32 + mt * 16 + gid;
        #pragma unroll
        for (int nt = 0; nt < 4; nt++) {
            int col = h * 128 + wn * 32 + nt * 8 + 2 * tig;
            uint32_t hh, ll;
            split2(acc[mt][nt][0], acc[mt][nt][1], hh, ll);
            ((uint32_t*)ash)[(size_t)t0 * 512 + col / 2] = hh;
            ((uint32_t*)asl)[(size_t)t0 * 512 + col / 2] = ll;
            split2(acc[mt][nt][2], acc[mt][nt][3], hh, ll);
            ((uint32_t*)ash)[(size_t)(t0 + 8) * 512 + col / 2] = hh;
            ((uint32_t*)asl)[(size_t)(t0 + 8) * 512 + col / 2] = ll;
        }
    }
}

// ---------------- conv: k/v pre-split + q split ----------------
__global__ __launch_bounds__(256) void conv_kv_kernel(
    const float* __restrict__ csn,
    uint32_t* __restrict__ kh, uint32_t* __restrict__ kl,
    uint32_t* __restrict__ vh, uint32_t* __restrict__ vl,
    uint32_t* __restrict__ qsh, uint32_t* __restrict__ qsl)
{
    int b = blockIdx.x;
    if (b < T_LEN) {
        int t = b, j = threadIdx.x;
        float2 v = *(const float2*)(csn + (size_t)t * N_SN + 1024 + 2 * j);
        uint32_t h, l;
        split2(v.x, v.y, h, l);
        kh[(size_t)t * 256 + j] = h;
        kl[(size_t)t * 256 + j] = l;
        return;
    }
    if (b < 2 * T_LEN) {
        int idx = (b - T_LEN) * 256 + threadIdx.x;
        int pp = idx & 511;
        int d = (idx >> 9) & 63;
        int h = idx >> 15;
        float v0 = csn[(size_t)(2 * pp) * N_SN + 1536 + h * DHR + d];
        float v1 = csn[(size_t)(2 * pp + 1) * N_SN + 1536 + h * DHR + d];
        uint32_t hh, ll;
        split2(v0, v1, hh, ll);
        vh[idx] = hh;
        vl[idx] = ll;
        return;
    }
    int t = b - 2 * T_LEN;
    #pragma unroll
    for (int it = 0; it < 2; it++) {
        int j2 = threadIdx.x + it * 256;
        float2 v = *(const float2*)(csn + (size_t)t * N_SN + 2 * j2);
        uint32_t h, l;
        split2(v.x, v.y, h, l);
        qsh[(size_t)t * 512 + j2] = h;
        qsl[(size_t)t * 512 + j2] = l;
    }
}

// ---------------- s-attention lite: logits from u, emit z / gate*zsp --------
__global__ __launch_bounds__(256) void s_attn_lite(
    const float* __restrict__ u,
    const __nv_bfloat16* __restrict__ rnh,
    const __nv_bfloat16* __restrict__ rnl,
    const float* __restrict__ gate,
    __nv_bfloat16* __restrict__ z2h, __nv_bfloat16* __restrict__ z2l,
    __nv_bfloat16* __restrict__ zsph, __nv_bfloat16* __restrict__ zspl)
{
    int t = blockIdx.x;
    int tid = threadIdx.x;
    int warp = tid >> 5, lane = tid & 31;

    __shared__ float us[4096];
    __shared__ float rn8[NSLOT][512];
    __shared__ float logits[HEADS][NSLOT];
    __shared__ float wattn[HEADS][NSLOT];
    __shared__ float wsp[NSLOT];

    for (int j = tid; j < 4096; j += 256)
        us[j] = u[(size_t)t * 4096 + j];
    const uint32_t* rh = (const uint32_t*)rnh + (size_t)t * 8 * 256;
    const uint32_t* rl = (const uint32_t*)rnl + (size_t)t * 8 * 256;
    for (int idx = tid; idx < 8 * 256; idx += 256) {
        uint32_t hh = rh[idx], ll = rl[idx];
        __nv_bfloat162 h2 = *(__nv_bfloat162*)&hh;
        __nv_bfloat162 l2 = *(__nv_bfloat162*)&ll;
        int n = idx >> 8, j2 = idx & 255;
        rn8[n][2 * j2] = __bfloat162float(h2.x) + __bfloat162float(l2.x);
        rn8[n][2 * j2 + 1] = __bfloat162float(h2.y) + __bfloat162float(l2.y);
    }
    __syncthreads();

    {
        int h = warp;
        #pragma unroll
        for (int n = 0; n < NSLOT; n++) {
            float p = 0.f;
            #pragma unroll
            for (int d = lane; d < 512; d += 32)
                p += rn8[n][d] * us[h * 512 + d];
            #pragma unroll
            for (int off = 16; off; off >>= 1)
                p += __shfl_xor_sync(0xffffffffu, p, off);
            if (lane == 0) logits[h][n] = p;
        }
    }
    __syncthreads();

    if (tid < HEADS) {
        int h = tid;
        float m = -INFINITY;
        #pragma unroll
        for (int n = 0; n < NSLOT; n++) m = fmaxf(m, logits[h][n] * SCALE_S);
        float sum = 0.f;
        #pragma unroll
        for (int n = 0; n < NSLOT; n++) {
            float e = __expf(logits[h][n] * SCALE_S - m);
            wattn[h][n] = e;
            sum += e;
        }
        float inv = 1.f / sum;
        #pragma unroll
        for (int n = 0; n < NSLOT; n++) wattn[h][n] *= inv;
    }
    if (tid == 8) {
        float sp[NSLOT];
        #pragma unroll
        for (int n = 0; n < NSLOT; n++) {
            float a = 0.f;
            #pragma unroll
            for (int h = 0; h < HEADS; h++) a += logits[h][n];
            sp[n] = a * SCALE_S;
        }
        bool sel[NSLOT];
        #pragma unroll
        for (int n = 0; n < NSLOT; n++) { sel[n] = false; wsp[n] = 0.f; }
        int idxs[TOPK];
        #pragma unroll
        for (int kk = 0; kk < TOPK; kk++) {
            int best = -1; float bv = -INFINITY;
            #pragma unroll
            for (int n = 0; n < NSLOT; n++)
                if (!sel[n] && sp[n] > bv) { bv = sp[n]; best = n; }
            sel[best] = true; idxs[kk] = best;
        }
        float m = -INFINITY;
        #pragma unroll
        for (int kk = 0; kk < TOPK; kk++) m = fmaxf(m, sp[idxs[kk]]);
        float sum = 0.f, e[TOPK];
        #pragma unroll
        for (int kk = 0; kk < TOPK; kk++) { e[kk] = __expf(sp[idxs[kk]] - m); sum += e[kk]; }
        float inv = 1.f / sum;
        #pragma unroll
        for (int kk = 0; kk < TOPK; kk++) wsp[idxs[kk]] = e[kk] * inv;
    }
    __syncthreads();

    {
        int h = warp;
        uint32_t* zh = (uint32_t*)z2h + ((size_t)h * T_LEN + t) * 256;
        uint32_t* zl = (uint32_t*)z2l + ((size_t)h * T_LEN + t) * 256;
        for (int j2 = lane; j2 < 256; j2 += 32) {
            float z0 = 0.f, z1 = 0.f;
            #pragma unroll
            for (int n = 0; n < NSLOT; n++) {
                z0 += wattn[h][n] * rn8[n][2 * j2];
                z1 += wattn[h][n] * rn8[n][2 * j2 + 1];
            }
            uint32_t hh, ll;
            split2(z0, z1, hh, ll);
            zh[j2] = hh;
            zl[j2] = ll;
        }
    }
    {
        float gv = gate[t];
        int j2 = tid;
        float z0 = 0.f, z1 = 0.f;
        #pragma unroll
        for (int n = 0; n < NSLOT; n++) {
            z0 += wsp[n] * rn8[n][2 * j2];
            z1 += wsp[n] * rn8[n][2 * j2 + 1];
        }
        uint32_t hh, ll;
        split2(gv * z0, gv * z1, hh, ll);
        ((uint32_t*)zsph)[(size_t)t * 256 + j2] = hh;
        ((uint32_t*)zspl)[(size_t)t * 256 + j2] = ll;
    }
}

// ---------------- causal r-attention (identical to R13-R16 best) ------------
__global__ __launch_bounds__(128, 3) void r_attn_mma(
    const float* __restrict__ qr, int qld,
    const uint32_t* __restrict__ kh_g, const uint32_t* __restrict__ kl_g,
    const uint32_t* __restrict__ vh_g, const uint32_t* __restrict__ vl_g,
    __nv_bfloat16* __restrict__ ar_h, __nv_bfloat16* __restrict__ ar_l)
{
    extern __shared__ __align__(16) uint32_t dsm[];
    uint32_t bkh = smem_u32(dsm);
    uint32_t bkl = bkh + 16384;
    uint32_t bvh = bkh + 32768;
    uint32_t bvl = bkh + 49152;

    int tt = (int)(gridDim.x - 1 - blockIdx.x);
    int h = blockIdx.y;
    int t0 = tt * 8;
    int hb = h * DHR;

    int tid = threadIdx.x;
    int w = tid >> 5, lane = tid & 31;
    int gid = lane >> 2, tig = lane & 3;

    int r0 = t0 * 8 + 16 * w + gid;
    int r8 = r0 + 8;
    uint32_t qh[4][4], ql[4][4];
    #pragma unroll
    for (int kc = 0; kc < 4; kc++) {
        float2 x0 = *(const float2*)(qr + (size_t)r0 * qld + hb + kc * 16 + 2 * tig);
        float2 x1 = *(const float2*)(qr + (size_t)r8 * qld + hb + kc * 16 + 2 * tig);
        float2 x2 = *(const float2*)(qr + (size_t)r0 * qld + hb + kc * 16 + 2 * tig + 8);
        float2 x3 = *(const float2*)(qr + (size_t)r8 * qld + hb + kc * 16 + 2 * tig + 8);
        split2(x0.x * SCALE_R, x0.y * SCALE_R, qh[kc][0], ql[kc][0]);
        split2(x1.x * SCALE_R, x1.y * SCALE_R, qh[kc][1], ql[kc][1]);
        split2(x2.x * SCALE_R, x2.y * SCALE_R, qh[kc][2], ql[kc][2]);
        split2(x3.x * SCALE_R, x3.y * SCALE_R, qh[kc][3], ql[kc][3]);
    }
    int tok0 = t0 + ((16 * w + gid) >> 3);
    int tok8 = t0 + ((16 * w + gid + 8) >> 3);

    uint32_t rowoff[4];
    uint32_t swr[4];
    {
        int mrow = ((lane & 16) >> 1) + (lane & 7);
        #pragma unroll
        for (int p = 0; p < 4; p++) {
            int nr = p * 16 + mrow;
            rowoff[p] = (uint32_t)(nr * 128);
            swr[p] = (uint32_t)(nr & 7);
        }
    }
    int gsel = (lane & 8) >> 3;

    float m0 = -INFINITY, m1 = -INFINITY, l0 = 0.f, l1 = 0.f;
    float acco[8][4];
    #pragma unroll
    for (int i = 0; i < 8; i++)
        #pragma unroll
        for (int j = 0; j < 4; j++) acco[i][j] = 0.f;

    int ntiles = ((t0 + 7) >> 6) + 1;

    auto issueT = [&](int st, int p0) {
        int pp0 = p0 >> 1;
        #pragma unroll
        for (int it = 0; it < 4; it++) {
            int idx = tid + it * 128;
            int p = idx >> 3, g = idx & 7;
            uint32_t doff = (uint32_t)(st * 8192) +
                            (uint32_t)(p * 32 + ((g ^ (p & 7)) << 2)) * 4;
            size_t ksrc = (size_t)(p0 + p) * 256 + h * 32 + g * 4;
            cp16(bkh + doff, kh_g + ksrc);
            cp16(bkl + doff, kl_g + ksrc);
            size_t vsrc = (size_t)h * 32768 + (size_t)p * 512 + pp0 + g * 4;
            cp16(bvh + doff, vh_g + vsrc);
            cp16(bvl + doff, vl_g + vsrc);
        }
        asm volatile("cp.async.commit_group;" ::: "memory");
    };

    issueT(0, 0);

    for (int c = 0; c < ntiles; c++) {
        int p0 = c * 64;
        if (c + 1 < ntiles) {
            issueT((c + 1) & 1, (c + 1) * 64);
            asm volatile("cp.async.wait_group 1;" ::: "memory");
        } else {
            asm volatile("cp.async.wait_group 0;" ::: "memory");
        }
        __syncthreads();

        uint32_t stB = (uint32_t)((c & 1) * 8192);

        float s[8][4];
        #pragma unroll
        for (int i = 0; i < 8; i++)
            #pragma unroll
            for (int j = 0; j < 4; j++) s[i][j] = 0.f;

        #pragma unroll
        for (int p = 0; p < 4; p++) {
            #pragma unroll
            for (int kc = 0; kc < 4; kc++) {
                uint32_t off = stB + rowoff[p] +
                               ((uint32_t)((2 * kc + gsel) ^ swr[p]) << 4);
                uint32_t bh[4], bl[4];
                ldm_x4(bh, bkh + off);
                ldm_x4(bl, bkl + off);
                #pragma unroll
                for (int q = 0; q < 2; q++) {
                    int nt = 2 * p + q;
                    mma_bf16(s[nt], qh[kc], bh[2 * q], bh[2 * q + 1]);
                    mma_bf16(s[nt], qh[kc], bl[2 * q], bl[2 * q + 1]);
                    mma_bf16(s[nt], ql[kc], bh[2 * q], bh[2 * q + 1]);
                }
            }
        }

        if (p0 + 64 > t0) {
            #pragma unroll
            for (int nt = 0; nt < 8; nt++) {
                int pg = p0 + nt * 8 + 2 * tig;
                if (pg > tok0)     s[nt][0] = -INFINITY;
                if (pg + 1 > tok0) s[nt][1] = -INFINITY;
                if (pg > tok8)     s[nt][2] = -INFINITY;
                if (pg + 1 > tok8) s[nt][3] = -INFINITY;
            }
        }

        float mx0 = -INFINITY, mx1 = -INFINITY;
        #pragma unroll
        for (int nt = 0; nt < 8; nt++) {
            mx0 = fmaxf(mx0, fmaxf(s[nt][0], s[nt][1]));
            mx1 = fmaxf(mx1, fmaxf(s[nt][2], s[nt][3]));
        }
        mx0 = fmaxf(mx0, __shfl_xor_sync(0xffffffffu, mx0, 1));
        mx0 = fmaxf(mx0, __shfl_xor_sync(0xffffffffu, mx0, 2));
        mx1 = fmaxf(mx1, __shfl_xor_sync(0xffffffffu, mx1, 1));
        mx1 = fmaxf(mx1, __shfl_xor_sync(0xffffffffu, mx1, 2));
        float nm0 = fmaxf(m0, mx0), nm1 = fmaxf(m1, mx1);
        float cr0 = __expf(m0 - nm0), cr1 = __expf(m1 - nm1);
        m0 = nm0; m1 = nm1;

        float rs0 = 0.f, rs1 = 0.f;
        #pragma unroll
        for (int nt = 0; nt < 8; nt++) {
            s[nt][0] = __expf(s[nt][0] - nm0);
            s[nt][1] = __expf(s[nt][1] - nm0);
            s[nt][2] = __expf(s[nt][2] - nm1);
            s[nt][3] = __expf(s[nt][3] - nm1);
            rs0 += s[nt][0] + s[nt][1];
            rs1 += s[nt][2] + s[nt][3];
        }
        rs0 += __shfl_xor_sync(0xffffffffu, rs0, 1);
        rs0 += __shfl_xor_sync(0xffffffffu, rs0, 2);
        rs1 += __shfl_xor_sync(0xffffffffu, rs1, 1);
        rs1 += __shfl_xor_sync(0xffffffffu, rs1, 2);
        l0 = l0 * cr0 + rs0;
        l1 = l1 * cr1 + rs1;

        #pragma unroll
        for (int ntd = 0; ntd < 8; ntd++) {
            acco[ntd][0] *= cr0; acco[ntd][1] *= cr0;
            acco[ntd][2] *= cr1; acco[ntd][3] *= cr1;
        }

        #pragma unroll
        for (int kc = 0; kc < 4; kc++) {
            uint32_t pah[4], pal[4];
            split2(s[2 * kc][0],     s[2 * kc][1],     pah[0], pal[0]);
            split2(s[2 * kc][2],     s[2 * kc][3],     pah[1], pal[1]);
            split2(s[2 * kc + 1][0], s[2 * kc + 1][1], pah[2], pal[2]);
            split2(s[2 * kc + 1][2], s[2 * kc + 1][3], pah[3], pal[3]);
            #pragma unroll
            for (int p = 0; p < 4; p++) {
                uint32_t off = stB + rowoff[p] +
                               ((uint32_t)((2 * kc + gsel) ^ swr[p]) << 4);
                uint32_t bh[4], bl[4];
                ldm_x4(bh, bvh + off);
                ldm_x4(bl, bvl + off);
                #pragma unroll
                for (int q = 0; q < 2; q++) {
                    int ntd = 2 * p + q;
                    mma_bf16(acco[ntd], pah, bh[2 * q], bh[2 * q + 1]);
                    mma_bf16(acco[ntd], pah, bl[2 * q], bl[2 * q + 1]);
                    mma_bf16(acco[ntd], pal, bh[2 * q], bh[2 * q + 1]);
                }
            }
        }

        if (c + 1 < ntiles) __syncthreads();
    }

    float i0 = 1.f / l0, i1 = 1.f / l1;
    #pragma unroll
    for (int ntd = 0; ntd < 8; ntd++) {
        int col = hb + ntd * 8 + 2 * tig;
        uint32_t hh, ll;
        split2(acco[ntd][0] * i0, acco[ntd][1] * i0, hh, ll);
        *(uint32_t*)(ar_h + (size_t)r0 * DR + col) = hh;
        *(uint32_t*)(ar_l + (size_t)r0 * DR + col) = ll;
        split2(acco[ntd][2] * i1, acco[ntd][3] * i1, hh, ll);
        *(uint32_t*)(ar_h + (size_t)r8 * DR + col) = hh;
        *(uint32_t*)(ar_l + (size_t)r8 * DR + col) = ll;
    }
}

// ---------------- host launch ----------------
extern "C" void kernel_launch(void* const* d_in, const int* in_sizes, int n_in,
                              void* d_out, int out_size)
{
    const float* s      = (const float*)d_in[0];
    const float* r      = (const float*)d_in[1];
    const float* gate_v = (const float*)d_in[2];
    const float* nsw    = (const float*)d_in[3];
    const float* nrw    = (const float*)d_in[4];
    const float* Wsq    = (const float*)d_in[5];
    const float* Wsk    = (const float*)d_in[6];
    const float* Wsv    = (const float*)d_in[7];
    const float* Wso    = (const float*)d_in[8];
    const float* Wrq    = (const float*)d_in[9];
    const float* Wrk    = (const float*)d_in[10];
    const float* Wrv    = (const float*)d_in[11];
    const float* Wro    = (const float*)d_in[12];

    float* out_s = (float*)d_out;
    float* out_r = (float*)d_out + T_LEN * DS;

    __nv_bfloat16 *snh, *snl, *rnh, *rnl, *ash, *asl, *arh, *arl;
    __nv_bfloat16 *wsnh, *wsnl, *wrnh, *wrnl, *wsoh, *wsol, *wroh, *wrol;
    __nv_bfloat16 *wuh, *wul, *qsh, *qsl, *z2h, *z2l, *zsph, *zspl;
    float *csn, *crn, *uu;
    uint32_t *kh, *kl, *vth, *vtl;
    cudaGetSymbolAddress((void**)&snh, g_sn_h);
    cudaGetSymbolAddress((void**)&snl, g_sn_l);
    cudaGetSymbolAddress((void**)&rnh, g_rn_h);
    cudaGetSymbolAddress((void**)&rnl, g_rn_l);
    cudaGetSymbolAddress((void**)&ash, g_as_h);
    cudaGetSymbolAddress((void**)&asl, g_as_l);
    cudaGetSymbolAddress((void**)&arh, g_ar_h);
    cudaGetSymbolAddress((void**)&arl, g_ar_l);
    cudaGetSymbolAddress((void**)&wsnh, g_wsn_h);
    cudaGetSymbolAddress((void**)&wsnl, g_wsn_l);
    cudaGetSymbolAddress((void**)&wrnh, g_wrn_h);
    cudaGetSymbolAddress((void**)&wrnl, g_wrn_l);
    cudaGetSymbolAddress((void**)&wsoh, g_wso_h);
    cudaGetSymbolAddress((void**)&wsol, g_wso_l);
    cudaGetSymbolAddress((void**)&wroh, g_wro_h);
    cudaGetSymbolAddress((void**)&wrol, g_wro_l);
    cudaGetSymbolAddress((void**)&wuh, g_wu_h);
    cudaGetSymbolAddress((void**)&wul, g_wu_l);
    cudaGetSymbolAddress((void**)&qsh, g_qs_h);
    cudaGetSymbolAddress((void**)&qsl, g_qs_l);
    cudaGetSymbolAddress((void**)&z2h, g_z2h);
    cudaGetSymbolAddress((void**)&z2l, g_z2l);
    cudaGetSymbolAddress((void**)&zsph, g_zsph);
    cudaGetSymbolAddress((void**)&zspl, g_zspl);
    cudaGetSymbolAddress((void**)&csn, g_csn);
    cudaGetSymbolAddress((void**)&crn, g_crn);
    cudaGetSymbolAddress((void**)&uu, g_u);
    cudaGetSymbolAddress((void**)&kh, g_kh);
    cudaGetSymbolAddress((void**)&kl, g_kl);
    cudaGetSymbolAddress((void**)&vth, g_vth);
    cudaGetSymbolAddress((void**)&vtl, g_vtl);

    cudaFuncSetAttribute(r_attn_mma,
                         cudaFuncAttributeMaxDynamicSharedMemorySize, 65536);
    cudaFuncSetAttribute(gemm_pair,
                         cudaFuncAttributeMaxDynamicSharedMemorySize, G_SMEM);
    cudaFuncSetAttribute(gemm_one,
                         cudaFuncAttributeMaxDynamicSharedMemorySize, G_SMEM);
    cudaFuncSetAttribute(gemm_u,
                         cudaFuncAttributeMaxDynamicSharedMemorySize, G_SMEM);
    cudaFuncSetAttribute(gemm_dual,
                         cudaFuncAttributeMaxDynamicSharedMemorySize, G_SMEM);

    cudaStream_t s1;
    cudaStreamCreateWithFlags(&s1, cudaStreamNonBlocking);
    cudaEvent_t e0, e1;
    cudaEventCreateWithFlags(&e0, cudaEventDisableTiming);
    cudaEventCreateWithFlags(&e1, cudaEventDisableTiming);

    // ---- 1. prep ----
    prep_kernel<<<5632 + T_LEN + ROWS_R, 256>>>(
        Wsq, Wsk, Wsv, Wso, Wrq, Wrk, Wrv, Wro,
        wsnh, wsnl, wrnh, wrnl, wsoh, wsol, wroh, wrol, wuh, wul,
        s, nsw, snh, snl, r, nrw, rnh, rnl);

    // ---- 2. projection GEMMs ----
    {
        GArg g0 = {snh, snl, wsnh, wsnl, csn, T_LEN, N_SN, DS, DS, N_SN,
                   nullptr, nullptr, nullptr};
        GArg g1 = {rnh, rnl, wrnh + 2048 * 512, wrnl + 2048 * 512, crn,
                   ROWS_R, DR, DR, DR, DR, nullptr, nullptr, nullptr};
        int gx0 = N_SN / 256, gy0 = T_LEN / 64;
        int gx1 = DR / 256, gy1 = ROWS_R / 64;
        gemm_pair<<<gx0 * gy0 + gx1 * gy1, 256, G_SMEM>>>(
            g0, g1, gx0 * gy0, gx0, gx1);
    }

    // ---- 3. conv: kr/vr pre-split + q split ----
    conv_kv_kernel<<<3 * T_LEN, 256>>>(csn, kh, kl, vth, vtl,
                                       (uint32_t*)qsh, (uint32_t*)qsl);

    // ---- fork: chain B (r-branch) on s1 ----
    cudaEventRecord(e0, 0);
    cudaStreamWaitEvent(s1, e0, 0);

    r_attn_mma<<<dim3(T_LEN / 8, HEADS), 128, 65536, s1>>>(
        crn, DR, kh, kl, vth, vtl, arh, arl);
    {
        GArg gr = {arh, arl, wroh, wrol, out_r, ROWS_R, DR, DR, DR, DR,
                   r, nullptr, nullptr};
        gemm_one<<<(DR / 256) * (ROWS_R / 64), 256, G_SMEM, s1>>>(gr, DR / 256);
    }
    cudaEventRecord(e1, s1);

    // ---- chain A (s-branch) on stream 0 ----
    gemm_u<<<dim3(32, 8), 256, G_SMEM>>>(qsh, qsl, wuh, wul, uu);
    s_attn_lite<<<T_LEN, 256>>>(uu, rnh, rnl, gate_v, z2h, z2l, zsph, zspl);
    zgemm_kernel<<<128, 256>>>(z2h, z2l, wrnh, wrnl, ash, asl);
    gemm_dual<<<64, 256, G_SMEM>>>(ash, asl, wsoh, wsol,
                                   zsph, zspl, wrnh + 1024 * 512,
                                   wrnl + 1024 * 512, out_s, s);

    // ---- join ----
    cudaStreamWaitEvent(0, e1, 0);

    cudaStreamCaptureStatus cs = cudaStreamCaptureStatusNone;
    cudaStreamIsCapturing(s1, &cs);
    if (cs == cudaStreamCaptureStatusNone) {
        cudaEventDestroy(e0);
        cudaEventDestroy(e1);
        cudaStreamDestroy(s1);
    }
}